// round 1
// baseline (speedup 1.0000x reference)
#include <cuda_runtime.h>
#include <cuda_bf16.h>
#include <math.h>

// ---------------- problem constants ----------------
#define NN 32            // batch
#define CC 3
#define NP 14
#define PS 16
#define DD 768
#define HH 12
#define DH 64
#define SS 197           // NP*NP+1
#define LL 8
#define FF 3072          // 4*D
#define OUTC 1000
#define NPATCH (NP*NP)   // 196
#define ROWS (NN*SS)     // 6304
#define PROWS (NN*NPATCH) // 6272

#define FLAG_BIAS 1
#define FLAG_GELU 2
#define FLAG_RES  4

// ---------------- scratch (device globals; no runtime allocation) ----------------
__device__ float g_patch[PROWS * DD];
__device__ float g_x[ROWS * DD];
__device__ float g_h[ROWS * DD];
__device__ float g_q[ROWS * DD];
__device__ float g_k[ROWS * DD];
__device__ float g_v[ROWS * DD];
__device__ float g_u[ROWS * FF];
__device__ float g_logits[NN * OUTC];

__device__ __forceinline__ float gelu_exact(float x) {
    return 0.5f * x * (1.0f + erff(x * 0.70710678118654752f));
}

// ---------------- patch extraction ----------------
__global__ void extract_patches(const float* __restrict__ images, float* __restrict__ P) {
    int idx = blockIdx.x * blockDim.x + threadIdx.x;
    if (idx >= PROWS * DD) return;
    int row = idx / DD;      // n*196 + p
    int col = idx - row * DD;
    int n = row / NPATCH;
    int p = row - n * NPATCH;
    int py = p / NP, px = p - py * NP;
    int c = col / (PS * PS);
    int r = col - c * PS * PS;
    int i = r / PS, j = r - i * PS;
    int H = NP * PS;
    P[idx] = images[(((size_t)n * CC + c) * H + (py * PS + i)) * H + (px * PS + j)];
}

// ---------------- assemble tokens + cls + pos ----------------
__global__ void assemble(const float* __restrict__ tok, const float* __restrict__ cls,
                         const float* __restrict__ pos, float* __restrict__ x) {
    int idx = blockIdx.x * blockDim.x + threadIdx.x;
    if (idx >= ROWS * DD) return;
    int row = idx / DD;
    int d = idx - row * DD;
    int n = row / SS;
    int s = row - n * SS;
    float v;
    if (s == 0) v = cls[d];
    else        v = tok[((size_t)n * NPATCH + (s - 1)) * DD + d];
    x[idx] = v + pos[(size_t)s * DD + d];
}

// ---------------- layernorm (block per row) ----------------
__global__ __launch_bounds__(256) void ln_kernel(const float* __restrict__ x,
                                                 const float* __restrict__ w,
                                                 const float* __restrict__ b,
                                                 float* __restrict__ out) {
    int row = blockIdx.x;
    int tid = threadIdx.x;
    const float* xr = x + (size_t)row * DD;
    float v0 = xr[tid], v1 = xr[tid + 256], v2 = xr[tid + 512];
    __shared__ float sh[8];
    int lane = tid & 31, wp = tid >> 5;

    float s = v0 + v1 + v2;
    #pragma unroll
    for (int o = 16; o; o >>= 1) s += __shfl_xor_sync(0xffffffffu, s, o);
    if (lane == 0) sh[wp] = s;
    __syncthreads();
    float total = 0.f;
    #pragma unroll
    for (int i = 0; i < 8; i++) total += sh[i];
    float mean = total * (1.0f / DD);
    __syncthreads();

    float d0 = v0 - mean, d1 = v1 - mean, d2 = v2 - mean;
    float sq = d0 * d0 + d1 * d1 + d2 * d2;
    #pragma unroll
    for (int o = 16; o; o >>= 1) sq += __shfl_xor_sync(0xffffffffu, sq, o);
    if (lane == 0) sh[wp] = sq;
    __syncthreads();
    float tot2 = 0.f;
    #pragma unroll
    for (int i = 0; i < 8; i++) tot2 += sh[i];
    float rstd = rsqrtf(tot2 * (1.0f / DD) + 1e-5f);

    float* orow = out + (size_t)row * DD;
    orow[tid]       = d0 * rstd * w[tid]       + b[tid];
    orow[tid + 256] = d1 * rstd * w[tid + 256] + b[tid + 256];
    orow[tid + 512] = d2 * rstd * w[tid + 512] + b[tid + 512];
}

// ---------------- big GEMM: 128x128 tile, BK=8, 8x8 per thread ----------------
__global__ __launch_bounds__(256) void gemm128(const float* __restrict__ A, int lda,
                                               const float* __restrict__ B, int ldb,
                                               float* __restrict__ C, int ldc,
                                               const float* __restrict__ bias,
                                               int M, int N, int K, int flags) {
    __shared__ float As[8][128];
    __shared__ float Bs[8][128];
    int tid = threadIdx.x;
    int m0 = blockIdx.y * 128, n0 = blockIdx.x * 128;
    int arow = tid >> 1, akcol = (tid & 1) * 4;
    int brow = tid >> 5, bcol = (tid & 31) * 4;
    int tx = tid & 15, ty = tid >> 4;

    float acc[8][8];
    #pragma unroll
    for (int i = 0; i < 8; i++)
        #pragma unroll
        for (int j = 0; j < 8; j++) acc[i][j] = 0.f;

    for (int k0 = 0; k0 < K; k0 += 8) {
        float4 a4 = make_float4(0.f, 0.f, 0.f, 0.f);
        int gm = m0 + arow;
        if (gm < M) a4 = *(const float4*)&A[(size_t)gm * lda + k0 + akcol];
        As[akcol + 0][arow] = a4.x;
        As[akcol + 1][arow] = a4.y;
        As[akcol + 2][arow] = a4.z;
        As[akcol + 3][arow] = a4.w;

        float4 b4;
        int gn = n0 + bcol;
        const float* Brow = &B[(size_t)(k0 + brow) * ldb];
        if (gn + 3 < N) {
            b4 = *(const float4*)&Brow[gn];
        } else {
            b4.x = (gn + 0 < N) ? Brow[gn + 0] : 0.f;
            b4.y = (gn + 1 < N) ? Brow[gn + 1] : 0.f;
            b4.z = (gn + 2 < N) ? Brow[gn + 2] : 0.f;
            b4.w = (gn + 3 < N) ? Brow[gn + 3] : 0.f;
        }
        *(float4*)&Bs[brow][bcol] = b4;
        __syncthreads();

        #pragma unroll
        for (int kk = 0; kk < 8; kk++) {
            float4 a0 = *(float4*)&As[kk][ty * 4];
            float4 a1 = *(float4*)&As[kk][ty * 4 + 64];
            float4 b0 = *(float4*)&Bs[kk][tx * 4];
            float4 b1 = *(float4*)&Bs[kk][tx * 4 + 64];
            float ar[8] = {a0.x, a0.y, a0.z, a0.w, a1.x, a1.y, a1.z, a1.w};
            float br[8] = {b0.x, b0.y, b0.z, b0.w, b1.x, b1.y, b1.z, b1.w};
            #pragma unroll
            for (int i = 0; i < 8; i++)
                #pragma unroll
                for (int j = 0; j < 8; j++) acc[i][j] += ar[i] * br[j];
        }
        __syncthreads();
    }

    #pragma unroll
    for (int i = 0; i < 8; i++) {
        int r = m0 + ty * 4 + (i & 3) + ((i >> 2) * 64);
        if (r >= M) continue;
        #pragma unroll
        for (int j = 0; j < 8; j++) {
            int c = n0 + tx * 4 + (j & 3) + ((j >> 2) * 64);
            if (c >= N) continue;
            float val = acc[i][j];
            if (flags & FLAG_BIAS) val += bias[c];
            if (flags & FLAG_GELU) val = gelu_exact(val);
            float* p = &C[(size_t)r * ldc + c];
            if (flags & FLAG_RES) *p += val; else *p = val;
        }
    }
}

// ---------------- small batched GEMM: 64x64 tile, BK=16, 4x4 per thread ----------------
__global__ __launch_bounds__(256) void gemm64(const float* __restrict__ A, long long lda, long long strideA,
                                              const float* __restrict__ B, int ldb, long long strideB,
                                              float* __restrict__ C, int ldc, long long strideC,
                                              const float* __restrict__ bias, long long strideBias,
                                              int M, int N, int K, int flags) {
    int bz = blockIdx.z;
    A += (size_t)bz * strideA;
    B += (size_t)bz * strideB;
    C += (size_t)bz * strideC;
    if (bias) bias += (size_t)bz * strideBias;

    __shared__ float As[16][64];
    __shared__ float Bs[16][68];
    int tid = threadIdx.x;
    int m0 = blockIdx.y * 64, n0 = blockIdx.x * 64;
    int arow = tid >> 2, akcol = (tid & 3) * 4;
    int brow = tid >> 4, bcol = (tid & 15) * 4;
    int tx = tid & 15, ty = tid >> 4;

    float acc[4][4];
    #pragma unroll
    for (int i = 0; i < 4; i++)
        #pragma unroll
        for (int j = 0; j < 4; j++) acc[i][j] = 0.f;

    for (int k0 = 0; k0 < K; k0 += 16) {
        float4 a4 = make_float4(0.f, 0.f, 0.f, 0.f);
        int gm = m0 + arow;
        if (gm < M) a4 = *(const float4*)&A[(size_t)gm * lda + k0 + akcol];
        As[akcol + 0][arow] = a4.x;
        As[akcol + 1][arow] = a4.y;
        As[akcol + 2][arow] = a4.z;
        As[akcol + 3][arow] = a4.w;

        float4 b4;
        int gn = n0 + bcol;
        const float* Brow = &B[(size_t)(k0 + brow) * ldb];
        if (gn + 3 < N) {
            b4 = *(const float4*)&Brow[gn];
        } else {
            b4.x = (gn + 0 < N) ? Brow[gn + 0] : 0.f;
            b4.y = (gn + 1 < N) ? Brow[gn + 1] : 0.f;
            b4.z = (gn + 2 < N) ? Brow[gn + 2] : 0.f;
            b4.w = (gn + 3 < N) ? Brow[gn + 3] : 0.f;
        }
        *(float4*)&Bs[brow][bcol] = b4;
        __syncthreads();

        #pragma unroll
        for (int kk = 0; kk < 16; kk++) {
            float4 a0 = *(float4*)&As[kk][ty * 4];
            float4 b0 = *(float4*)&Bs[kk][tx * 4];
            float ar[4] = {a0.x, a0.y, a0.z, a0.w};
            float br[4] = {b0.x, b0.y, b0.z, b0.w};
            #pragma unroll
            for (int i = 0; i < 4; i++)
                #pragma unroll
                for (int j = 0; j < 4; j++) acc[i][j] += ar[i] * br[j];
        }
        __syncthreads();
    }

    #pragma unroll
    for (int i = 0; i < 4; i++) {
        int r = m0 + ty * 4 + i;
        if (r >= M) continue;
        #pragma unroll
        for (int j = 0; j < 4; j++) {
            int c = n0 + tx * 4 + j;
            if (c >= N) continue;
            float val = acc[i][j];
            if (flags & FLAG_BIAS) val += bias[c];
            if (flags & FLAG_GELU) val = gelu_exact(val);
            float* p = &C[(size_t)r * ldc + c];
            if (flags & FLAG_RES) *p += val; else *p = val;
        }
    }
}

// ---------------- fused attention: block per (n, head) ----------------
// smem: ks[197*65] + vs[197*65] + sc[8*200] + qs[8*64]
#define ATT_SMEM_FLOATS (SS*65*2 + 8*200 + 8*64)

__global__ __launch_bounds__(256) void attn_kernel(const float* __restrict__ q,
                                                   const float* __restrict__ k,
                                                   const float* __restrict__ v,
                                                   float* __restrict__ x) {
    extern __shared__ float sm[];
    float* ks = sm;
    float* vs = sm + SS * 65;
    float* sc = vs + SS * 65;       // 8 * 200 per-warp prob buffers
    float* qs = sc + 8 * 200;       // 8 * 64 per-warp q staging

    int nh = blockIdx.x;
    int n = nh / HH, h = nh - n * HH;
    int tid = threadIdx.x;
    int wp = tid >> 5, lane = tid & 31;

    const float* kb = k + ((size_t)n * SS) * DD + h * DH;
    const float* vb = v + ((size_t)n * SS) * DD + h * DH;

    for (int idx = tid; idx < SS * 16; idx += 256) {
        int t = idx >> 4;
        int e4 = (idx & 15) * 4;
        float4 kk4 = *(const float4*)&kb[(size_t)t * DD + e4];
        float4 vv4 = *(const float4*)&vb[(size_t)t * DD + e4];
        int base = t * 65 + e4;
        ks[base + 0] = kk4.x; ks[base + 1] = kk4.y; ks[base + 2] = kk4.z; ks[base + 3] = kk4.w;
        vs[base + 0] = vv4.x; vs[base + 1] = vv4.y; vs[base + 2] = vv4.z; vs[base + 3] = vv4.w;
    }
    __syncthreads();

    const float scale = 0.125f; // 1/sqrt(64)
    float* myqs = qs + wp * 64;
    float* mysc = sc + wp * 200;

    for (int s = wp; s < SS; s += 8) {
        const float* qrow = q + ((size_t)(n * SS + s)) * DD + h * DH;
        myqs[lane]      = qrow[lane];
        myqs[lane + 32] = qrow[lane + 32];
        __syncwarp();

        float qreg[DH];
        #pragma unroll
        for (int e = 0; e < DH; e++) qreg[e] = myqs[e];

        float sreg[7];
        float mx = -1e30f;
        int cnt = 0;
        for (int t = lane; t < SS; t += 32) {
            float a = 0.f;
            #pragma unroll
            for (int e = 0; e < DH; e++) a += qreg[e] * ks[t * 65 + e];
            a *= scale;
            sreg[cnt++] = a;
            mx = fmaxf(mx, a);
        }
        #pragma unroll
        for (int o = 16; o; o >>= 1) mx = fmaxf(mx, __shfl_xor_sync(0xffffffffu, mx, o));
        float sum = 0.f;
        for (int i = 0; i < cnt; i++) {
            sreg[i] = __expf(sreg[i] - mx);
            sum += sreg[i];
        }
        #pragma unroll
        for (int o = 16; o; o >>= 1) sum += __shfl_xor_sync(0xffffffffu, sum, o);
        float inv = 1.0f / sum;
        {
            int i = 0;
            for (int t = lane; t < SS; t += 32) mysc[t] = sreg[i++] * inv;
        }
        __syncwarp();

        float o0 = 0.f, o1 = 0.f;
        for (int t = 0; t < SS; t++) {
            float p = mysc[t];
            o0 += p * vs[t * 65 + lane];
            o1 += p * vs[t * 65 + lane + 32];
        }
        float* xr = x + ((size_t)(n * SS + s)) * DD + h * DH;
        xr[lane]      += o0;
        xr[lane + 32] += o1;
        __syncwarp();
    }
}

// ---------------- final softmax over 1000 classes ----------------
__global__ __launch_bounds__(256) void softmax_out(const float* __restrict__ logits,
                                                   float* __restrict__ out) {
    int n = blockIdx.x;
    int tid = threadIdx.x;
    const float* l = logits + (size_t)n * OUTC;
    __shared__ float sh[8];
    int lane = tid & 31, wp = tid >> 5;

    float mx = -1e30f;
    for (int c = tid; c < OUTC; c += 256) mx = fmaxf(mx, l[c]);
    #pragma unroll
    for (int o = 16; o; o >>= 1) mx = fmaxf(mx, __shfl_xor_sync(0xffffffffu, mx, o));
    if (lane == 0) sh[wp] = mx;
    __syncthreads();
    float gmx = sh[0];
    #pragma unroll
    for (int i = 1; i < 8; i++) gmx = fmaxf(gmx, sh[i]);
    __syncthreads();

    float sum = 0.f;
    for (int c = tid; c < OUTC; c += 256) sum += __expf(l[c] - gmx);
    #pragma unroll
    for (int o = 16; o; o >>= 1) sum += __shfl_xor_sync(0xffffffffu, sum, o);
    if (lane == 0) sh[wp] = sum;
    __syncthreads();
    float tot = 0.f;
    #pragma unroll
    for (int i = 0; i < 8; i++) tot += sh[i];
    float inv = 1.0f / tot;

    for (int c = tid; c < OUTC; c += 256) out[(size_t)n * OUTC + c] = __expf(l[c] - gmx) * inv;
}

// ---------------- launch ----------------
extern "C" void kernel_launch(void* const* d_in, const int* in_sizes, int n_in,
                              void* d_out, int out_size) {
    const float* images = (const float*)d_in[0];
    const float* Wm     = (const float*)d_in[1];
    const float* bm     = (const float*)d_in[2];
    const float* cls    = (const float*)d_in[3];
    const float* pos    = (const float*)d_in[4];
    const float* ln1w   = (const float*)d_in[5];
    const float* ln1b   = (const float*)d_in[6];
    const float* Wq     = (const float*)d_in[7];
    const float* bq     = (const float*)d_in[8];
    const float* Wk     = (const float*)d_in[9];
    const float* bk     = (const float*)d_in[10];
    const float* Wv     = (const float*)d_in[11];
    const float* bv     = (const float*)d_in[12];
    const float* ln2w   = (const float*)d_in[13];
    const float* ln2b   = (const float*)d_in[14];
    const float* W1     = (const float*)d_in[15];
    const float* b1     = (const float*)d_in[16];
    const float* W2     = (const float*)d_in[17];
    const float* b2     = (const float*)d_in[18];
    const float* Wout   = (const float*)d_in[19];
    const float* bout   = (const float*)d_in[20];
    float* out = (float*)d_out;

    float *p_patch, *p_x, *p_h, *p_q, *p_k, *p_v, *p_u, *p_logits;
    cudaGetSymbolAddress((void**)&p_patch, g_patch);
    cudaGetSymbolAddress((void**)&p_x, g_x);
    cudaGetSymbolAddress((void**)&p_h, g_h);
    cudaGetSymbolAddress((void**)&p_q, g_q);
    cudaGetSymbolAddress((void**)&p_k, g_k);
    cudaGetSymbolAddress((void**)&p_v, g_v);
    cudaGetSymbolAddress((void**)&p_u, g_u);
    cudaGetSymbolAddress((void**)&p_logits, g_logits);

    const int att_smem = ATT_SMEM_FLOATS * sizeof(float);
    cudaFuncSetAttribute(attn_kernel, cudaFuncAttributeMaxDynamicSharedMemorySize, att_smem);

    // patch extraction + embed GEMM
    extract_patches<<<(PROWS * DD + 255) / 256, 256>>>(images, p_patch);
    gemm128<<<dim3(DD / 128, (PROWS + 127) / 128), 256>>>(
        p_patch, DD, Wm, DD, p_h, DD, bm, PROWS, DD, DD, FLAG_BIAS);
    assemble<<<(ROWS * DD + 255) / 256, 256>>>(p_h, cls, pos, p_x);

    for (int l = 0; l < LL; l++) {
        ln_kernel<<<ROWS, 256>>>(p_x, ln1w + l * DD, ln1b + l * DD, p_h);

        // per-head QKV: M=6304, N=64, K=64, batch=12 heads
        dim3 qkv_grid(1, (ROWS + 63) / 64, HH);
        gemm64<<<qkv_grid, 256>>>(p_h, DD, DH,
                                  Wq + (size_t)l * HH * DH * DH, DH, DH * DH,
                                  p_q, DD, DH,
                                  bq + (size_t)l * DD, DH,
                                  ROWS, DH, DH, FLAG_BIAS);
        gemm64<<<qkv_grid, 256>>>(p_h, DD, DH,
                                  Wk + (size_t)l * HH * DH * DH, DH, DH * DH,
                                  p_k, DD, DH,
                                  bk + (size_t)l * DD, DH,
                                  ROWS, DH, DH, FLAG_BIAS);
        gemm64<<<qkv_grid, 256>>>(p_h, DD, DH,
                                  Wv + (size_t)l * HH * DH * DH, DH, DH * DH,
                                  p_v, DD, DH,
                                  bv + (size_t)l * DD, DH,
                                  ROWS, DH, DH, FLAG_BIAS);

        attn_kernel<<<NN * HH, 256, att_smem>>>(p_q, p_k, p_v, p_x);

        ln_kernel<<<ROWS, 256>>>(p_x, ln2w + l * DD, ln2b + l * DD, p_h);

        gemm128<<<dim3(FF / 128, (ROWS + 127) / 128), 256>>>(
            p_h, DD, W1 + (size_t)l * DD * FF, FF, p_u, FF,
            b1 + (size_t)l * FF, ROWS, FF, DD, FLAG_BIAS | FLAG_GELU);
        gemm128<<<dim3(DD / 128, (ROWS + 127) / 128), 256>>>(
            p_u, FF, W2 + (size_t)l * FF * DD, DD, p_x, DD,
            b2 + (size_t)l * DD, ROWS, DD, FF, FLAG_BIAS | FLAG_RES);
    }

    // classification head: cls rows have stride SS*DD
    gemm64<<<dim3((OUTC + 63) / 64, 1, 1), 256>>>(
        p_x, (long long)SS * DD, 0,
        Wout, OUTC, 0,
        p_logits, OUTC, 0,
        bout, 0,
        NN, OUTC, DD, FLAG_BIAS);

    softmax_out<<<NN, 256>>>(p_logits, out);
}

// round 3
// speedup vs baseline: 1.6200x; 1.6200x over previous
#include <cuda_runtime.h>
#include <cuda_bf16.h>
#include <math.h>
#include <stdint.h>

// ---------------- problem constants ----------------
#define NN 32            // batch
#define CC 3
#define NP 14
#define PS 16
#define DD 768
#define HH 12
#define DH 64
#define SS 197           // NP*NP+1
#define LL 8
#define FF 3072          // 4*D
#define OUTC 1000
#define NPATCH (NP*NP)   // 196
#define ROWS (NN*SS)     // 6304
#define PROWS (NN*NPATCH) // 6272

#define FLAG_BIAS 1
#define FLAG_GELU 2
#define FLAG_RES  4

// ---------------- scratch (device globals; no runtime allocation) ----------------
__device__ float g_patch[PROWS * DD];
__device__ float g_x[ROWS * DD];
__device__ float g_h[ROWS * DD];
__device__ float g_q[ROWS * DD];
__device__ float g_k[ROWS * DD];
__device__ float g_v[ROWS * DD];
__device__ float g_u[ROWS * FF];
__device__ float g_logits[NN * OUTC];

__device__ __forceinline__ float gelu_exact(float x) {
    return 0.5f * x * (1.0f + erff(x * 0.70710678118654752f));
}

// ---------------- patch extraction ----------------
__global__ void extract_patches(const float* __restrict__ images, float* __restrict__ P) {
    int idx = blockIdx.x * blockDim.x + threadIdx.x;
    if (idx >= PROWS * DD) return;
    int row = idx / DD;      // n*196 + p
    int col = idx - row * DD;
    int n = row / NPATCH;
    int p = row - n * NPATCH;
    int py = p / NP, px = p - py * NP;
    int c = col / (PS * PS);
    int r = col - c * PS * PS;
    int i = r / PS, j = r - i * PS;
    int H = NP * PS;
    P[idx] = images[(((size_t)n * CC + c) * H + (py * PS + i)) * H + (px * PS + j)];
}

// ---------------- assemble tokens + cls + pos ----------------
__global__ void assemble(const float* __restrict__ tok, const float* __restrict__ cls,
                         const float* __restrict__ pos, float* __restrict__ x) {
    int idx = blockIdx.x * blockDim.x + threadIdx.x;
    if (idx >= ROWS * DD) return;
    int row = idx / DD;
    int d = idx - row * DD;
    int n = row / SS;
    int s = row - n * SS;
    float v;
    if (s == 0) v = cls[d];
    else        v = tok[((size_t)n * NPATCH + (s - 1)) * DD + d];
    x[idx] = v + pos[(size_t)s * DD + d];
}

// ---------------- layernorm (block per row) ----------------
__global__ __launch_bounds__(256) void ln_kernel(const float* __restrict__ x,
                                                 const float* __restrict__ w,
                                                 const float* __restrict__ b,
                                                 float* __restrict__ out) {
    int row = blockIdx.x;
    int tid = threadIdx.x;
    const float* xr = x + (size_t)row * DD;
    float v0 = xr[tid], v1 = xr[tid + 256], v2 = xr[tid + 512];
    __shared__ float sh[8];
    int lane = tid & 31, wp = tid >> 5;

    float s = v0 + v1 + v2;
    #pragma unroll
    for (int o = 16; o; o >>= 1) s += __shfl_xor_sync(0xffffffffu, s, o);
    if (lane == 0) sh[wp] = s;
    __syncthreads();
    float total = 0.f;
    #pragma unroll
    for (int i = 0; i < 8; i++) total += sh[i];
    float mean = total * (1.0f / DD);
    __syncthreads();

    float d0 = v0 - mean, d1 = v1 - mean, d2 = v2 - mean;
    float sq = d0 * d0 + d1 * d1 + d2 * d2;
    #pragma unroll
    for (int o = 16; o; o >>= 1) sq += __shfl_xor_sync(0xffffffffu, sq, o);
    if (lane == 0) sh[wp] = sq;
    __syncthreads();
    float tot2 = 0.f;
    #pragma unroll
    for (int i = 0; i < 8; i++) tot2 += sh[i];
    float rstd = rsqrtf(tot2 * (1.0f / DD) + 1e-5f);

    float* orow = out + (size_t)row * DD;
    orow[tid]       = d0 * rstd * w[tid]       + b[tid];
    orow[tid + 256] = d1 * rstd * w[tid + 256] + b[tid + 256];
    orow[tid + 512] = d2 * rstd * w[tid + 512] + b[tid + 512];
}

// ================= bf16x3 tensor-core GEMM =================
// C[M,N] = A[M,K] @ B[K,N] (+bias)(+gelu)(+residual), fp32 in/out.
// Split each fp32 into bf16 hi+lo; accumulate hi*hi + hi*lo + lo*hi in fp32.
// Tile 128x128x32, 8 warps, warp tile 64x32 via mma.m16n8k16.

#define BM 128
#define BN 128
#define BKK 32
#define ASTR 40    // bf16 row stride, A tile [BM][ASTR]
#define BSTR 136   // bf16 row stride, B tile [BKK][BSTR]
#define ASZ (BM*ASTR)
#define BSZ (BKK*BSTR)
#define STAGE_ELEMS (2*ASZ + 2*BSZ)           // Ahi,Alo,Bhi,Blo
#define GEMM_SMEM_BYTES (2 * STAGE_ELEMS * 2) // double-buffered, bf16

__device__ __forceinline__ void ldsm_x4(uint32_t addr, uint32_t* r) {
    asm volatile("ldmatrix.sync.aligned.m8n8.x4.shared.b16 {%0,%1,%2,%3}, [%4];\n"
                 : "=r"(r[0]), "=r"(r[1]), "=r"(r[2]), "=r"(r[3]) : "r"(addr));
}
__device__ __forceinline__ void ldsm_x4_t(uint32_t addr, uint32_t* r) {
    asm volatile("ldmatrix.sync.aligned.m8n8.x4.trans.shared.b16 {%0,%1,%2,%3}, [%4];\n"
                 : "=r"(r[0]), "=r"(r[1]), "=r"(r[2]), "=r"(r[3]) : "r"(addr));
}
__device__ __forceinline__ void mma_bf16(float* c, const uint32_t* a, const uint32_t* b) {
    asm volatile("mma.sync.aligned.m16n8k16.row.col.f32.bf16.bf16.f32 "
                 "{%0,%1,%2,%3},{%4,%5,%6,%7},{%8,%9},{%0,%1,%2,%3};\n"
                 : "+f"(c[0]), "+f"(c[1]), "+f"(c[2]), "+f"(c[3])
                 : "r"(a[0]), "r"(a[1]), "r"(a[2]), "r"(a[3]), "r"(b[0]), "r"(b[1]));
}

// split two floats into (hi, lo) bf16 pairs
__device__ __forceinline__ void split_pair(float x, float y,
                                           __nv_bfloat162* hi, __nv_bfloat162* lo) {
    __nv_bfloat16 hx = __float2bfloat16(x);
    __nv_bfloat16 hy = __float2bfloat16(y);
    __nv_bfloat16 lx = __float2bfloat16(x - __bfloat162float(hx));
    __nv_bfloat16 ly = __float2bfloat16(y - __bfloat162float(hy));
    *hi = __halves2bfloat162(hx, hy);
    *lo = __halves2bfloat162(lx, ly);
}

__device__ __forceinline__ void gemm_load_g(const float* __restrict__ A, int lda,
                                            const float* __restrict__ B, int ldb,
                                            int M, int m0, int n0, int kb, int tid,
                                            float4* pa, float4* pb) {
    #pragma unroll
    for (int i = 0; i < 4; i++) {
        int idx = tid + 256 * i;
        int r = idx >> 3;
        int c = (idx & 7) * 4;
        int gr = m0 + r;
        if (gr < M) pa[i] = *(const float4*)&A[(size_t)gr * lda + kb + c];
        else        pa[i] = make_float4(0.f, 0.f, 0.f, 0.f);
    }
    #pragma unroll
    for (int i = 0; i < 4; i++) {
        int idx = tid + 256 * i;
        int r = idx >> 5;
        int c = (idx & 31) * 4;
        pb[i] = *(const float4*)&B[(size_t)(kb + r) * ldb + n0 + c];
    }
}

__device__ __forceinline__ void gemm_store_s(__nv_bfloat16* stage, int tid,
                                             const float4* pa, const float4* pb) {
    __nv_bfloat16* Ahi = stage;
    __nv_bfloat16* Alo = Ahi + ASZ;
    __nv_bfloat16* Bhi = Alo + ASZ;
    __nv_bfloat16* Blo = Bhi + BSZ;
    #pragma unroll
    for (int i = 0; i < 4; i++) {
        int idx = tid + 256 * i;
        int r = idx >> 3;
        int c = (idx & 7) * 4;
        float4 v = pa[i];
        __nv_bfloat162 h01, l01, h23, l23;
        split_pair(v.x, v.y, &h01, &l01);
        split_pair(v.z, v.w, &h23, &l23);
        __nv_bfloat162* ph = (__nv_bfloat162*)&Ahi[r * ASTR + c];
        __nv_bfloat162* pl = (__nv_bfloat162*)&Alo[r * ASTR + c];
        ph[0] = h01; ph[1] = h23;
        pl[0] = l01; pl[1] = l23;
    }
    #pragma unroll
    for (int i = 0; i < 4; i++) {
        int idx = tid + 256 * i;
        int r = idx >> 5;
        int c = (idx & 31) * 4;
        float4 v = pb[i];
        __nv_bfloat162 h01, l01, h23, l23;
        split_pair(v.x, v.y, &h01, &l01);
        split_pair(v.z, v.w, &h23, &l23);
        __nv_bfloat162* ph = (__nv_bfloat162*)&Bhi[r * BSTR + c];
        __nv_bfloat162* pl = (__nv_bfloat162*)&Blo[r * BSTR + c];
        ph[0] = h01; ph[1] = h23;
        pl[0] = l01; pl[1] = l23;
    }
}

__global__ __launch_bounds__(256, 1) void gemm_bf16x3(
    const float* __restrict__ A, int lda,
    const float* __restrict__ B, int ldb,
    float* __restrict__ C, int ldc,
    const float* __restrict__ bias,
    int M, int N, int K, int flags)
{
    extern __shared__ __nv_bfloat16 smbuf[];
    int tid = threadIdx.x;
    int m0 = blockIdx.y * BM;
    int n0 = blockIdx.x * BN;
    int warp = tid >> 5;
    int lane = tid & 31;
    int wm = (warp >> 2) * 64;
    int wn = (warp & 3) * 32;

    float acc[4][4][4];
    #pragma unroll
    for (int i = 0; i < 4; i++)
        #pragma unroll
        for (int j = 0; j < 4; j++)
            #pragma unroll
            for (int c = 0; c < 4; c++) acc[i][j][c] = 0.f;

    float4 pa[4];
    float4 pb[4];
    const int nk = K / BKK;

    gemm_load_g(A, lda, B, ldb, M, m0, n0, 0, tid, pa, pb);
    gemm_store_s(smbuf, tid, pa, pb);
    __syncthreads();

    for (int kt = 0; kt < nk; kt++) {
        int cur = kt & 1;
        if (kt + 1 < nk) {
            gemm_load_g(A, lda, B, ldb, M, m0, n0, (kt + 1) * BKK, tid, pa, pb);
        }

        const __nv_bfloat16* Ahi = smbuf + cur * STAGE_ELEMS;
        const __nv_bfloat16* Alo = Ahi + ASZ;
        const __nv_bfloat16* Bhi = Alo + ASZ;
        const __nv_bfloat16* Blo = Bhi + BSZ;
        uint32_t ahi_base = (uint32_t)__cvta_generic_to_shared(Ahi);
        uint32_t alo_base = (uint32_t)__cvta_generic_to_shared(Alo);
        uint32_t bhi_base = (uint32_t)__cvta_generic_to_shared(Bhi);
        uint32_t blo_base = (uint32_t)__cvta_generic_to_shared(Blo);

        #pragma unroll
        for (int ks = 0; ks < 2; ks++) {
            int kc = ks * 16;
            uint32_t afh[4][4];
            uint32_t afl[4][4];
            uint32_t bfh[4][2];
            uint32_t bfl[4][2];
            int arow = lane & 15;
            int acol = kc + (lane >> 4) * 8;
            #pragma unroll
            for (int mi = 0; mi < 4; mi++) {
                uint32_t off = (uint32_t)(((wm + mi * 16 + arow) * ASTR + acol) * 2);
                ldsm_x4(ahi_base + off, afh[mi]);
                ldsm_x4(alo_base + off, afl[mi]);
            }
            int brow = kc + ((lane >> 3) & 1) * 8 + (lane & 7);
            #pragma unroll
            for (int j = 0; j < 2; j++) {
                int bcol = wn + j * 16 + (lane >> 4) * 8;
                uint32_t off = (uint32_t)((brow * BSTR + bcol) * 2);
                uint32_t th[4];
                uint32_t tl[4];
                ldsm_x4_t(bhi_base + off, th);
                ldsm_x4_t(blo_base + off, tl);
                bfh[2 * j][0] = th[0];
                bfh[2 * j][1] = th[1];
                bfh[2 * j + 1][0] = th[2];
                bfh[2 * j + 1][1] = th[3];
                bfl[2 * j][0] = tl[0];
                bfl[2 * j][1] = tl[1];
                bfl[2 * j + 1][0] = tl[2];
                bfl[2 * j + 1][1] = tl[3];
            }
            #pragma unroll
            for (int mi = 0; mi < 4; mi++) {
                #pragma unroll
                for (int ni = 0; ni < 4; ni++) {
                    mma_bf16(acc[mi][ni], afh[mi], bfh[ni]);
                    mma_bf16(acc[mi][ni], afh[mi], bfl[ni]);
                    mma_bf16(acc[mi][ni], afl[mi], bfh[ni]);
                }
            }
        }

        if (kt + 1 < nk) {
            gemm_store_s(smbuf + ((kt + 1) & 1) * STAGE_ELEMS, tid, pa, pb);
        }
        __syncthreads();
    }

    // ---- epilogue ----
    #pragma unroll
    for (int mi = 0; mi < 4; mi++) {
        int r0 = m0 + wm + mi * 16 + (lane >> 2);
        #pragma unroll
        for (int ni = 0; ni < 4; ni++) {
            int c0 = n0 + wn + ni * 8 + (lane & 3) * 2;
            #pragma unroll
            for (int half = 0; half < 2; half++) {
                int r = r0 + half * 8;
                if (r >= M) continue;
                #pragma unroll
                for (int e = 0; e < 2; e++) {
                    int c = c0 + e;
                    float val = acc[mi][ni][half * 2 + e];
                    if (flags & FLAG_BIAS) val += bias[c];
                    if (flags & FLAG_GELU) val = gelu_exact(val);
                    float* p = &C[(size_t)r * ldc + c];
                    if (flags & FLAG_RES) *p += val; else *p = val;
                }
            }
        }
    }
}

// ---------------- small batched GEMM: 64x64 tile, BK=16, 4x4 per thread ----------------
__global__ __launch_bounds__(256) void gemm64(const float* __restrict__ A, long long lda, long long strideA,
                                              const float* __restrict__ B, int ldb, long long strideB,
                                              float* __restrict__ C, int ldc, long long strideC,
                                              const float* __restrict__ bias, long long strideBias,
                                              int M, int N, int K, int flags) {
    int bz = blockIdx.z;
    A += (size_t)bz * strideA;
    B += (size_t)bz * strideB;
    C += (size_t)bz * strideC;
    if (bias) bias += (size_t)bz * strideBias;

    __shared__ float As[16][64];
    __shared__ float Bs[16][68];
    int tid = threadIdx.x;
    int m0 = blockIdx.y * 64, n0 = blockIdx.x * 64;
    int arow = tid >> 2, akcol = (tid & 3) * 4;
    int brow = tid >> 4, bcol = (tid & 15) * 4;
    int tx = tid & 15, ty = tid >> 4;

    float acc[4][4];
    #pragma unroll
    for (int i = 0; i < 4; i++)
        #pragma unroll
        for (int j = 0; j < 4; j++) acc[i][j] = 0.f;

    for (int k0 = 0; k0 < K; k0 += 16) {
        float4 a4 = make_float4(0.f, 0.f, 0.f, 0.f);
        int gm = m0 + arow;
        if (gm < M) a4 = *(const float4*)&A[(size_t)gm * lda + k0 + akcol];
        As[akcol + 0][arow] = a4.x;
        As[akcol + 1][arow] = a4.y;
        As[akcol + 2][arow] = a4.z;
        As[akcol + 3][arow] = a4.w;

        float4 b4;
        int gn = n0 + bcol;
        const float* Brow = &B[(size_t)(k0 + brow) * ldb];
        if (gn + 3 < N) {
            b4 = *(const float4*)&Brow[gn];
        } else {
            b4.x = (gn + 0 < N) ? Brow[gn + 0] : 0.f;
            b4.y = (gn + 1 < N) ? Brow[gn + 1] : 0.f;
            b4.z = (gn + 2 < N) ? Brow[gn + 2] : 0.f;
            b4.w = (gn + 3 < N) ? Brow[gn + 3] : 0.f;
        }
        *(float4*)&Bs[brow][bcol] = b4;
        __syncthreads();

        #pragma unroll
        for (int kk = 0; kk < 16; kk++) {
            float4 a0 = *(float4*)&As[kk][ty * 4];
            float4 b0 = *(float4*)&Bs[kk][tx * 4];
            float ar[4] = {a0.x, a0.y, a0.z, a0.w};
            float br[4] = {b0.x, b0.y, b0.z, b0.w};
            #pragma unroll
            for (int i = 0; i < 4; i++)
                #pragma unroll
                for (int j = 0; j < 4; j++) acc[i][j] += ar[i] * br[j];
        }
        __syncthreads();
    }

    #pragma unroll
    for (int i = 0; i < 4; i++) {
        int r = m0 + ty * 4 + i;
        if (r >= M) continue;
        #pragma unroll
        for (int j = 0; j < 4; j++) {
            int c = n0 + tx * 4 + j;
            if (c >= N) continue;
            float val = acc[i][j];
            if (flags & FLAG_BIAS) val += bias[c];
            if (flags & FLAG_GELU) val = gelu_exact(val);
            float* p = &C[(size_t)r * ldc + c];
            if (flags & FLAG_RES) *p += val; else *p = val;
        }
    }
}

// ---------------- fused attention: block per (n, head) ----------------
#define ATT_SMEM_FLOATS (SS*65*2 + 8*200 + 8*64)

__global__ __launch_bounds__(256) void attn_kernel(const float* __restrict__ q,
                                                   const float* __restrict__ k,
                                                   const float* __restrict__ v,
                                                   float* __restrict__ x) {
    extern __shared__ float smf[];
    float* ks = smf;
    float* vs = smf + SS * 65;
    float* sc = vs + SS * 65;
    float* qs = sc + 8 * 200;

    int nh = blockIdx.x;
    int n = nh / HH, h = nh - n * HH;
    int tid = threadIdx.x;
    int wp = tid >> 5, lane = tid & 31;

    const float* kb = k + ((size_t)n * SS) * DD + h * DH;
    const float* vb = v + ((size_t)n * SS) * DD + h * DH;

    for (int idx = tid; idx < SS * 16; idx += 256) {
        int t = idx >> 4;
        int e4 = (idx & 15) * 4;
        float4 kk4 = *(const float4*)&kb[(size_t)t * DD + e4];
        float4 vv4 = *(const float4*)&vb[(size_t)t * DD + e4];
        int base = t * 65 + e4;
        ks[base + 0] = kk4.x; ks[base + 1] = kk4.y; ks[base + 2] = kk4.z; ks[base + 3] = kk4.w;
        vs[base + 0] = vv4.x; vs[base + 1] = vv4.y; vs[base + 2] = vv4.z; vs[base + 3] = vv4.w;
    }
    __syncthreads();

    const float scale = 0.125f;
    float* myqs = qs + wp * 64;
    float* mysc = sc + wp * 200;

    for (int s = wp; s < SS; s += 8) {
        const float* qrow = q + ((size_t)(n * SS + s)) * DD + h * DH;
        myqs[lane]      = qrow[lane];
        myqs[lane + 32] = qrow[lane + 32];
        __syncwarp();

        float qreg[DH];
        #pragma unroll
        for (int e = 0; e < DH; e++) qreg[e] = myqs[e];

        float sreg[7];
        float mx = -1e30f;
        int cnt = 0;
        for (int t = lane; t < SS; t += 32) {
            float a = 0.f;
            #pragma unroll
            for (int e = 0; e < DH; e++) a += qreg[e] * ks[t * 65 + e];
            a *= scale;
            sreg[cnt++] = a;
            mx = fmaxf(mx, a);
        }
        #pragma unroll
        for (int o = 16; o; o >>= 1) mx = fmaxf(mx, __shfl_xor_sync(0xffffffffu, mx, o));
        float sum = 0.f;
        for (int i = 0; i < cnt; i++) {
            sreg[i] = __expf(sreg[i] - mx);
            sum += sreg[i];
        }
        #pragma unroll
        for (int o = 16; o; o >>= 1) sum += __shfl_xor_sync(0xffffffffu, sum, o);
        float inv = 1.0f / sum;
        {
            int i = 0;
            for (int t = lane; t < SS; t += 32) mysc[t] = sreg[i++] * inv;
        }
        __syncwarp();

        float o0 = 0.f, o1 = 0.f;
        for (int t = 0; t < SS; t++) {
            float p = mysc[t];
            o0 += p * vs[t * 65 + lane];
            o1 += p * vs[t * 65 + lane + 32];
        }
        float* xr = x + ((size_t)(n * SS + s)) * DD + h * DH;
        xr[lane]      += o0;
        xr[lane + 32] += o1;
        __syncwarp();
    }
}

// ---------------- final softmax over 1000 classes ----------------
__global__ __launch_bounds__(256) void softmax_out(const float* __restrict__ logits,
                                                   float* __restrict__ out) {
    int n = blockIdx.x;
    int tid = threadIdx.x;
    const float* l = logits + (size_t)n * OUTC;
    __shared__ float sh[8];
    int lane = tid & 31, wp = tid >> 5;

    float mx = -1e30f;
    for (int c = tid; c < OUTC; c += 256) mx = fmaxf(mx, l[c]);
    #pragma unroll
    for (int o = 16; o; o >>= 1) mx = fmaxf(mx, __shfl_xor_sync(0xffffffffu, mx, o));
    if (lane == 0) sh[wp] = mx;
    __syncthreads();
    float gmx = sh[0];
    #pragma unroll
    for (int i = 1; i < 8; i++) gmx = fmaxf(gmx, sh[i]);
    __syncthreads();

    float sum = 0.f;
    for (int c = tid; c < OUTC; c += 256) sum += __expf(l[c] - gmx);
    #pragma unroll
    for (int o = 16; o; o >>= 1) sum += __shfl_xor_sync(0xffffffffu, sum, o);
    if (lane == 0) sh[wp] = sum;
    __syncthreads();
    float tot = 0.f;
    #pragma unroll
    for (int i = 0; i < 8; i++) tot += sh[i];
    float inv = 1.0f / tot;

    for (int c = tid; c < OUTC; c += 256) out[(size_t)n * OUTC + c] = __expf(l[c] - gmx) * inv;
}

// ---------------- launch ----------------
extern "C" void kernel_launch(void* const* d_in, const int* in_sizes, int n_in,
                              void* d_out, int out_size) {
    const float* images = (const float*)d_in[0];
    const float* Wm     = (const float*)d_in[1];
    const float* bm     = (const float*)d_in[2];
    const float* cls    = (const float*)d_in[3];
    const float* pos    = (const float*)d_in[4];
    const float* ln1w   = (const float*)d_in[5];
    const float* ln1b   = (const float*)d_in[6];
    const float* Wq     = (const float*)d_in[7];
    const float* bq     = (const float*)d_in[8];
    const float* Wk     = (const float*)d_in[9];
    const float* bk     = (const float*)d_in[10];
    const float* Wv     = (const float*)d_in[11];
    const float* bv     = (const float*)d_in[12];
    const float* ln2w   = (const float*)d_in[13];
    const float* ln2b   = (const float*)d_in[14];
    const float* W1     = (const float*)d_in[15];
    const float* b1     = (const float*)d_in[16];
    const float* W2     = (const float*)d_in[17];
    const float* b2     = (const float*)d_in[18];
    const float* Wout   = (const float*)d_in[19];
    const float* bout   = (const float*)d_in[20];
    float* out = (float*)d_out;

    float *p_patch, *p_x, *p_h, *p_q, *p_k, *p_v, *p_u, *p_logits;
    cudaGetSymbolAddress((void**)&p_patch, g_patch);
    cudaGetSymbolAddress((void**)&p_x, g_x);
    cudaGetSymbolAddress((void**)&p_h, g_h);
    cudaGetSymbolAddress((void**)&p_q, g_q);
    cudaGetSymbolAddress((void**)&p_k, g_k);
    cudaGetSymbolAddress((void**)&p_v, g_v);
    cudaGetSymbolAddress((void**)&p_u, g_u);
    cudaGetSymbolAddress((void**)&p_logits, g_logits);

    const int att_smem = ATT_SMEM_FLOATS * sizeof(float);
    cudaFuncSetAttribute(attn_kernel, cudaFuncAttributeMaxDynamicSharedMemorySize, att_smem);
    cudaFuncSetAttribute(gemm_bf16x3, cudaFuncAttributeMaxDynamicSharedMemorySize, GEMM_SMEM_BYTES);

    // patch extraction + embed GEMM
    extract_patches<<<(PROWS * DD + 255) / 256, 256>>>(images, p_patch);
    gemm_bf16x3<<<dim3(DD / 128, (PROWS + 127) / 128), 256, GEMM_SMEM_BYTES>>>(
        p_patch, DD, Wm, DD, p_h, DD, bm, PROWS, DD, DD, FLAG_BIAS);
    assemble<<<(ROWS * DD + 255) / 256, 256>>>(p_h, cls, pos, p_x);

    for (int l = 0; l < LL; l++) {
        ln_kernel<<<ROWS, 256>>>(p_x, ln1w + l * DD, ln1b + l * DD, p_h);

        // per-head QKV: M=6304, N=64, K=64, batch=12 heads
        dim3 qkv_grid(1, (ROWS + 63) / 64, HH);
        gemm64<<<qkv_grid, 256>>>(p_h, DD, DH,
                                  Wq + (size_t)l * HH * DH * DH, DH, DH * DH,
                                  p_q, DD, DH,
                                  bq + (size_t)l * DD, DH,
                                  ROWS, DH, DH, FLAG_BIAS);
        gemm64<<<qkv_grid, 256>>>(p_h, DD, DH,
                                  Wk + (size_t)l * HH * DH * DH, DH, DH * DH,
                                  p_k, DD, DH,
                                  bk + (size_t)l * DD, DH,
                                  ROWS, DH, DH, FLAG_BIAS);
        gemm64<<<qkv_grid, 256>>>(p_h, DD, DH,
                                  Wv + (size_t)l * HH * DH * DH, DH, DH * DH,
                                  p_v, DD, DH,
                                  bv + (size_t)l * DD, DH,
                                  ROWS, DH, DH, FLAG_BIAS);

        attn_kernel<<<NN * HH, 256, att_smem>>>(p_q, p_k, p_v, p_x);

        ln_kernel<<<ROWS, 256>>>(p_x, ln2w + l * DD, ln2b + l * DD, p_h);

        gemm_bf16x3<<<dim3(FF / 128, (ROWS + 127) / 128), 256, GEMM_SMEM_BYTES>>>(
            p_h, DD, W1 + (size_t)l * DD * FF, FF, p_u, FF,
            b1 + (size_t)l * FF, ROWS, FF, DD, FLAG_BIAS | FLAG_GELU);
        gemm_bf16x3<<<dim3(DD / 128, (ROWS + 127) / 128), 256, GEMM_SMEM_BYTES>>>(
            p_u, FF, W2 + (size_t)l * FF * DD, DD, p_x, DD,
            b2 + (size_t)l * DD, ROWS, DD, FF, FLAG_BIAS | FLAG_RES);
    }

    // classification head: cls rows have stride SS*DD
    gemm64<<<dim3((OUTC + 63) / 64, 1, 1), 256>>>(
        p_x, (long long)SS * DD, 0,
        Wout, OUTC, 0,
        p_logits, OUTC, 0,
        bout, 0,
        NN, OUTC, DD, FLAG_BIAS);

    softmax_out<<<NN, 256>>>(p_logits, out);
}

// round 4
// speedup vs baseline: 1.7122x; 1.0569x over previous
#include <cuda_runtime.h>
#include <cuda_bf16.h>
#include <math.h>
#include <stdint.h>

// ---------------- problem constants ----------------
#define NN 32
#define CC 3
#define NP 14
#define PS 16
#define DD 768
#define HH 12
#define DH 64
#define SS 197
#define LL 8
#define FF 3072
#define OUTC 1000
#define NPATCH (NP*NP)    // 196
#define ROWS (NN*SS)      // 6304
#define PROWS (NN*NPATCH) // 6272

#define FLAG_BIAS 1
#define FLAG_GELU 2
#define FLAG_RES  4
#define FLAG_SPLIT 8

// ---------------- scratch (device globals; no runtime allocation) ----------------
__device__ float g_x[ROWS * DD];
__device__ float g_h[ROWS * DD];
__device__ float g_q[ROWS * DD];
__device__ float g_k[ROWS * DD];
__device__ float g_v[ROWS * DD];
__device__ float g_logits[NN * OUTC];

__device__ __nv_bfloat16 g_patch_hi[PROWS * DD];
__device__ __nv_bfloat16 g_patch_lo[PROWS * DD];
__device__ __nv_bfloat16 g_h_hi[ROWS * DD];
__device__ __nv_bfloat16 g_h_lo[ROWS * DD];
__device__ __nv_bfloat16 g_u_hi[ROWS * FF];
__device__ __nv_bfloat16 g_u_lo[ROWS * FF];
__device__ __nv_bfloat16 g_Wm_hi[DD * DD];
__device__ __nv_bfloat16 g_Wm_lo[DD * DD];
__device__ __nv_bfloat16 g_W1_hi[LL * DD * FF];
__device__ __nv_bfloat16 g_W1_lo[LL * DD * FF];
__device__ __nv_bfloat16 g_W2_hi[LL * FF * DD];
__device__ __nv_bfloat16 g_W2_lo[LL * FF * DD];

__device__ __forceinline__ float gelu_exact(float x) {
    return 0.5f * x * (1.0f + erff(x * 0.70710678118654752f));
}

__device__ __forceinline__ void split1(float x, __nv_bfloat16* hi, __nv_bfloat16* lo) {
    __nv_bfloat16 h = __float2bfloat16(x);
    *hi = h;
    *lo = __float2bfloat16(x - __bfloat162float(h));
}

// ---------------- generic fp32 -> bf16 hi/lo split ----------------
__global__ void split_f32(const float* __restrict__ src, __nv_bfloat16* __restrict__ hi,
                          __nv_bfloat16* __restrict__ lo, int n) {
    int i = (blockIdx.x * blockDim.x + threadIdx.x) * 4;
    if (i >= n) return;
    float4 v = *(const float4*)&src[i];
    __nv_bfloat16 h0, l0, h1, l1, h2, l2, h3, l3;
    split1(v.x, &h0, &l0); split1(v.y, &h1, &l1);
    split1(v.z, &h2, &l2); split1(v.w, &h3, &l3);
    hi[i] = h0; hi[i + 1] = h1; hi[i + 2] = h2; hi[i + 3] = h3;
    lo[i] = l0; lo[i + 1] = l1; lo[i + 2] = l2; lo[i + 3] = l3;
}

// ---------------- patch extraction (writes split bf16) ----------------
__global__ void extract_patches(const float* __restrict__ images,
                                __nv_bfloat16* __restrict__ Phi,
                                __nv_bfloat16* __restrict__ Plo) {
    int idx = blockIdx.x * blockDim.x + threadIdx.x;
    if (idx >= PROWS * DD) return;
    int row = idx / DD;
    int col = idx - row * DD;
    int n = row / NPATCH;
    int p = row - n * NPATCH;
    int py = p / NP, px = p - py * NP;
    int c = col / (PS * PS);
    int r = col - c * PS * PS;
    int i = r / PS, j = r - i * PS;
    int H = NP * PS;
    float v = images[(((size_t)n * CC + c) * H + (py * PS + i)) * H + (px * PS + j)];
    __nv_bfloat16 h, l;
    split1(v, &h, &l);
    Phi[idx] = h;
    Plo[idx] = l;
}

// ---------------- assemble tokens + cls + pos ----------------
__global__ void assemble(const float* __restrict__ tok, const float* __restrict__ cls,
                         const float* __restrict__ pos, float* __restrict__ x) {
    int idx = blockIdx.x * blockDim.x + threadIdx.x;
    if (idx >= ROWS * DD) return;
    int row = idx / DD;
    int d = idx - row * DD;
    int n = row / SS;
    int s = row - n * SS;
    float v;
    if (s == 0) v = cls[d];
    else        v = tok[((size_t)n * NPATCH + (s - 1)) * DD + d];
    x[idx] = v + pos[(size_t)s * DD + d];
}

// ---------------- layernorm -> fp32 out ----------------
__global__ __launch_bounds__(256) void ln_kernel(const float* __restrict__ x,
                                                 const float* __restrict__ w,
                                                 const float* __restrict__ b,
                                                 float* __restrict__ out) {
    int row = blockIdx.x;
    int tid = threadIdx.x;
    const float* xr = x + (size_t)row * DD;
    float v0 = xr[tid], v1 = xr[tid + 256], v2 = xr[tid + 512];
    __shared__ float sh[8];
    int lane = tid & 31, wp = tid >> 5;

    float s = v0 + v1 + v2;
    #pragma unroll
    for (int o = 16; o; o >>= 1) s += __shfl_xor_sync(0xffffffffu, s, o);
    if (lane == 0) sh[wp] = s;
    __syncthreads();
    float total = 0.f;
    #pragma unroll
    for (int i = 0; i < 8; i++) total += sh[i];
    float mean = total * (1.0f / DD);
    __syncthreads();

    float d0 = v0 - mean, d1 = v1 - mean, d2 = v2 - mean;
    float sq = d0 * d0 + d1 * d1 + d2 * d2;
    #pragma unroll
    for (int o = 16; o; o >>= 1) sq += __shfl_xor_sync(0xffffffffu, sq, o);
    if (lane == 0) sh[wp] = sq;
    __syncthreads();
    float tot2 = 0.f;
    #pragma unroll
    for (int i = 0; i < 8; i++) tot2 += sh[i];
    float rstd = rsqrtf(tot2 * (1.0f / DD) + 1e-5f);

    float* orow = out + (size_t)row * DD;
    orow[tid]       = d0 * rstd * w[tid]       + b[tid];
    orow[tid + 256] = d1 * rstd * w[tid + 256] + b[tid + 256];
    orow[tid + 512] = d2 * rstd * w[tid + 512] + b[tid + 512];
}

// ---------------- layernorm -> split bf16 out ----------------
__global__ __launch_bounds__(256) void ln_kernel_split(const float* __restrict__ x,
                                                       const float* __restrict__ w,
                                                       const float* __restrict__ b,
                                                       __nv_bfloat16* __restrict__ ohi,
                                                       __nv_bfloat16* __restrict__ olo) {
    int row = blockIdx.x;
    int tid = threadIdx.x;
    const float* xr = x + (size_t)row * DD;
    float v0 = xr[tid], v1 = xr[tid + 256], v2 = xr[tid + 512];
    __shared__ float sh[8];
    int lane = tid & 31, wp = tid >> 5;

    float s = v0 + v1 + v2;
    #pragma unroll
    for (int o = 16; o; o >>= 1) s += __shfl_xor_sync(0xffffffffu, s, o);
    if (lane == 0) sh[wp] = s;
    __syncthreads();
    float total = 0.f;
    #pragma unroll
    for (int i = 0; i < 8; i++) total += sh[i];
    float mean = total * (1.0f / DD);
    __syncthreads();

    float d0 = v0 - mean, d1 = v1 - mean, d2 = v2 - mean;
    float sq = d0 * d0 + d1 * d1 + d2 * d2;
    #pragma unroll
    for (int o = 16; o; o >>= 1) sq += __shfl_xor_sync(0xffffffffu, sq, o);
    if (lane == 0) sh[wp] = sq;
    __syncthreads();
    float tot2 = 0.f;
    #pragma unroll
    for (int i = 0; i < 8; i++) tot2 += sh[i];
    float rstd = rsqrtf(tot2 * (1.0f / DD) + 1e-5f);

    size_t base = (size_t)row * DD;
    float r0 = d0 * rstd * w[tid]       + b[tid];
    float r1 = d1 * rstd * w[tid + 256] + b[tid + 256];
    float r2 = d2 * rstd * w[tid + 512] + b[tid + 512];
    __nv_bfloat16 h, l;
    split1(r0, &h, &l); ohi[base + tid]       = h; olo[base + tid]       = l;
    split1(r1, &h, &l); ohi[base + tid + 256] = h; olo[base + tid + 256] = l;
    split1(r2, &h, &l); ohi[base + tid + 512] = h; olo[base + tid + 512] = l;
}

// ================= bf16x3 tensor-core GEMM (pre-split inputs, cp.async pipeline) ======
#define BM 128
#define BN 128
#define BKK 32
#define ASTR 40
#define BSTR 136
#define ASZ (BM*ASTR)                 // 5120 bf16
#define BSZ (BKK*BSTR)                // 4352 bf16
#define STAGE_ELEMS (2*(ASZ+BSZ))     // 18944 bf16
#define STAGE_BYTES (STAGE_ELEMS*2)   // 37888
#define NSTAGE 3
#define GEMM_SMEM_BYTES (NSTAGE * STAGE_BYTES)

__device__ __forceinline__ void ldsm_x4(uint32_t addr, uint32_t* r) {
    asm volatile("ldmatrix.sync.aligned.m8n8.x4.shared.b16 {%0,%1,%2,%3}, [%4];\n"
                 : "=r"(r[0]), "=r"(r[1]), "=r"(r[2]), "=r"(r[3]) : "r"(addr));
}
__device__ __forceinline__ void ldsm_x4_t(uint32_t addr, uint32_t* r) {
    asm volatile("ldmatrix.sync.aligned.m8n8.x4.trans.shared.b16 {%0,%1,%2,%3}, [%4];\n"
                 : "=r"(r[0]), "=r"(r[1]), "=r"(r[2]), "=r"(r[3]) : "r"(addr));
}
__device__ __forceinline__ void mma_bf16(float* c, const uint32_t* a, const uint32_t* b) {
    asm volatile("mma.sync.aligned.m16n8k16.row.col.f32.bf16.bf16.f32 "
                 "{%0,%1,%2,%3},{%4,%5,%6,%7},{%8,%9},{%0,%1,%2,%3};\n"
                 : "+f"(c[0]), "+f"(c[1]), "+f"(c[2]), "+f"(c[3])
                 : "r"(a[0]), "r"(a[1]), "r"(a[2]), "r"(a[3]), "r"(b[0]), "r"(b[1]));
}
__device__ __forceinline__ void cpa16(uint32_t dst, const void* src, int bytes) {
    asm volatile("cp.async.cg.shared.global [%0], [%1], 16, %2;\n"
                 :: "r"(dst), "l"(src), "r"(bytes));
}
__device__ __forceinline__ void cp_commit() {
    asm volatile("cp.async.commit_group;\n");
}
__device__ __forceinline__ void cp_wait1() {
    asm volatile("cp.async.wait_group 1;\n");
}

__device__ __forceinline__ void gemm_issue_stage(
    uint32_t smem_u32, int stage,
    const __nv_bfloat16* __restrict__ Ahi, const __nv_bfloat16* __restrict__ Alo, int lda,
    const __nv_bfloat16* __restrict__ Bhi, const __nv_bfloat16* __restrict__ Blo, int ldb,
    int M, int m0, int n0, int kb, int tid)
{
    uint32_t s = smem_u32 + (uint32_t)stage * STAGE_BYTES;
    uint32_t sAhi = s;
    uint32_t sAlo = s + ASZ * 2;
    uint32_t sBhi = s + 2 * ASZ * 2;
    uint32_t sBlo = s + (2 * ASZ + BSZ) * 2;
    #pragma unroll
    for (int i = 0; i < 2; i++) {
        int chunk = tid + 256 * i;
        int row = chunk >> 2;
        int c16 = chunk & 3;
        int gr = m0 + row;
        int bytes = (gr < M) ? 16 : 0;
        size_t goff = (size_t)gr * lda + kb + c16 * 8;
        uint32_t doff = (uint32_t)(row * ASTR + c16 * 8) * 2;
        cpa16(sAhi + doff, Ahi + goff, bytes);
        cpa16(sAlo + doff, Alo + goff, bytes);
    }
    #pragma unroll
    for (int i = 0; i < 2; i++) {
        int chunk = tid + 256 * i;
        int row = chunk >> 4;
        int c16 = chunk & 15;
        size_t goff = (size_t)(kb + row) * ldb + n0 + c16 * 8;
        uint32_t doff = (uint32_t)(row * BSTR + c16 * 8) * 2;
        cpa16(sBhi + doff, Bhi + goff, 16);
        cpa16(sBlo + doff, Blo + goff, 16);
    }
}

__global__ __launch_bounds__(256, 1) void gemm_bf16x3(
    const __nv_bfloat16* __restrict__ Ahi, const __nv_bfloat16* __restrict__ Alo, int lda,
    const __nv_bfloat16* __restrict__ Bhi, const __nv_bfloat16* __restrict__ Blo, int ldb,
    float* __restrict__ C, __nv_bfloat16* __restrict__ Chi, __nv_bfloat16* __restrict__ Clo,
    int ldc, const float* __restrict__ bias,
    int M, int N, int K, int flags)
{
    extern __shared__ __nv_bfloat16 smbuf[];
    int tid = threadIdx.x;
    int m0 = blockIdx.y * BM;
    int n0 = blockIdx.x * BN;
    int warp = tid >> 5;
    int lane = tid & 31;
    int wm = (warp >> 2) * 64;
    int wn = (warp & 3) * 32;

    float acc[4][4][4];
    #pragma unroll
    for (int i = 0; i < 4; i++)
        #pragma unroll
        for (int j = 0; j < 4; j++)
            #pragma unroll
            for (int c = 0; c < 4; c++) acc[i][j][c] = 0.f;

    uint32_t smem_u32 = (uint32_t)__cvta_generic_to_shared(smbuf);
    const int nk = K / BKK;

    gemm_issue_stage(smem_u32, 0, Ahi, Alo, lda, Bhi, Blo, ldb, M, m0, n0, 0, tid);
    cp_commit();
    gemm_issue_stage(smem_u32, 1, Ahi, Alo, lda, Bhi, Blo, ldb, M, m0, n0, BKK, tid);
    cp_commit();

    for (int kt = 0; kt < nk; kt++) {
        cp_wait1();
        __syncthreads();

        int st = kt % NSTAGE;
        uint32_t s = smem_u32 + (uint32_t)st * STAGE_BYTES;
        uint32_t ahi_base = s;
        uint32_t alo_base = s + ASZ * 2;
        uint32_t bhi_base = s + 2 * ASZ * 2;
        uint32_t blo_base = s + (2 * ASZ + BSZ) * 2;

        #pragma unroll
        for (int ks = 0; ks < 2; ks++) {
            int kc = ks * 16;
            uint32_t afh[4][4];
            uint32_t afl[4][4];
            uint32_t bfh[4][2];
            uint32_t bfl[4][2];
            int arow = lane & 15;
            int acol = kc + (lane >> 4) * 8;
            #pragma unroll
            for (int mi = 0; mi < 4; mi++) {
                uint32_t off = (uint32_t)(((wm + mi * 16 + arow) * ASTR + acol) * 2);
                ldsm_x4(ahi_base + off, afh[mi]);
                ldsm_x4(alo_base + off, afl[mi]);
            }
            int brow = kc + ((lane >> 3) & 1) * 8 + (lane & 7);
            #pragma unroll
            for (int j = 0; j < 2; j++) {
                int bcol = wn + j * 16 + (lane >> 4) * 8;
                uint32_t off = (uint32_t)((brow * BSTR + bcol) * 2);
                uint32_t th[4];
                uint32_t tl[4];
                ldsm_x4_t(bhi_base + off, th);
                ldsm_x4_t(blo_base + off, tl);
                bfh[2 * j][0] = th[0];
                bfh[2 * j][1] = th[1];
                bfh[2 * j + 1][0] = th[2];
                bfh[2 * j + 1][1] = th[3];
                bfl[2 * j][0] = tl[0];
                bfl[2 * j][1] = tl[1];
                bfl[2 * j + 1][0] = tl[2];
                bfl[2 * j + 1][1] = tl[3];
            }
            #pragma unroll
            for (int mi = 0; mi < 4; mi++) {
                #pragma unroll
                for (int ni = 0; ni < 4; ni++) {
                    mma_bf16(acc[mi][ni], afh[mi], bfh[ni]);
                    mma_bf16(acc[mi][ni], afh[mi], bfl[ni]);
                    mma_bf16(acc[mi][ni], afl[mi], bfh[ni]);
                }
            }
        }

        int nxt = kt + NSTAGE - 1;
        if (nxt < nk) {
            gemm_issue_stage(smem_u32, nxt % NSTAGE, Ahi, Alo, lda, Bhi, Blo, ldb,
                             M, m0, n0, nxt * BKK, tid);
        }
        cp_commit();
    }

    // ---- epilogue ----
    #pragma unroll
    for (int mi = 0; mi < 4; mi++) {
        int r0 = m0 + wm + mi * 16 + (lane >> 2);
        #pragma unroll
        for (int ni = 0; ni < 4; ni++) {
            int c0 = n0 + wn + ni * 8 + (lane & 3) * 2;
            #pragma unroll
            for (int half = 0; half < 2; half++) {
                int r = r0 + half * 8;
                if (r >= M) continue;
                #pragma unroll
                for (int e = 0; e < 2; e++) {
                    int c = c0 + e;
                    float val = acc[mi][ni][half * 2 + e];
                    if (flags & FLAG_BIAS) val += bias[c];
                    if (flags & FLAG_GELU) val = gelu_exact(val);
                    if (flags & FLAG_SPLIT) {
                        __nv_bfloat16 h, l;
                        split1(val, &h, &l);
                        Chi[(size_t)r * ldc + c] = h;
                        Clo[(size_t)r * ldc + c] = l;
                    } else {
                        float* p = &C[(size_t)r * ldc + c];
                        if (flags & FLAG_RES) *p += val; else *p = val;
                    }
                }
            }
        }
    }
}

// ---------------- fused QKV: block per (m-block 64, head) ----------------
#define QKV_SMEM_BYTES ((64*68 + 3*64*68) * 4)

__global__ __launch_bounds__(256) void qkv_kernel(
    const float* __restrict__ h,
    const float* __restrict__ Wq, const float* __restrict__ Wk, const float* __restrict__ Wv,
    const float* __restrict__ bq, const float* __restrict__ bk, const float* __restrict__ bv,
    float* __restrict__ q, float* __restrict__ k, float* __restrict__ v)
{
    extern __shared__ float qsm[];
    float* As = qsm;                 // [kk][m] 64x68
    float* Ws = qsm + 64 * 68;       // [3][kk][e] 3x64x68
    int m0 = blockIdx.x * 64;
    int head = blockIdx.y;
    int tid = threadIdx.x;

    for (int idx = tid; idx < 64 * 64; idx += 256) {
        int r = idx >> 6, c = idx & 63;
        float val = 0.f;
        if (m0 + r < ROWS) val = h[(size_t)(m0 + r) * DD + head * DH + c];
        As[c * 68 + r] = val;
    }
    const float* w0 = Wq + head * DH * DH;
    const float* w1 = Wk + head * DH * DH;
    const float* w2 = Wv + head * DH * DH;
    for (int idx = tid; idx < 64 * 64; idx += 256) {
        int d = idx >> 6, e = idx & 63;
        Ws[0 * 4352 + d * 68 + e] = w0[d * 64 + e];
        Ws[1 * 4352 + d * 68 + e] = w1[d * 64 + e];
        Ws[2 * 4352 + d * 68 + e] = w2[d * 64 + e];
    }
    __syncthreads();

    int tx = tid & 15, ty = tid >> 4;
    float aq[4][4], ak[4][4], av[4][4];
    #pragma unroll
    for (int i = 0; i < 4; i++)
        #pragma unroll
        for (int j = 0; j < 4; j++) { aq[i][j] = 0.f; ak[i][j] = 0.f; av[i][j] = 0.f; }

    for (int kk = 0; kk < 64; kk++) {
        float4 a = *(float4*)&As[kk * 68 + ty * 4];
        float4 b0 = *(float4*)&Ws[0 * 4352 + kk * 68 + tx * 4];
        float4 b1 = *(float4*)&Ws[1 * 4352 + kk * 68 + tx * 4];
        float4 b2 = *(float4*)&Ws[2 * 4352 + kk * 68 + tx * 4];
        float ar[4] = {a.x, a.y, a.z, a.w};
        float q4[4] = {b0.x, b0.y, b0.z, b0.w};
        float k4[4] = {b1.x, b1.y, b1.z, b1.w};
        float v4[4] = {b2.x, b2.y, b2.z, b2.w};
        #pragma unroll
        for (int i = 0; i < 4; i++) {
            #pragma unroll
            for (int j = 0; j < 4; j++) {
                aq[i][j] += ar[i] * q4[j];
                ak[i][j] += ar[i] * k4[j];
                av[i][j] += ar[i] * v4[j];
            }
        }
    }

    #pragma unroll
    for (int i = 0; i < 4; i++) {
        int r = m0 + ty * 4 + i;
        if (r >= ROWS) continue;
        size_t base = (size_t)r * DD + head * DH;
        #pragma unroll
        for (int j = 0; j < 4; j++) {
            int c = tx * 4 + j;
            q[base + c] = aq[i][j] + bq[head * DH + c];
            k[base + c] = ak[i][j] + bk[head * DH + c];
            v[base + c] = av[i][j] + bv[head * DH + c];
        }
    }
}

// ---------------- small GEMM (head projection) ----------------
__global__ __launch_bounds__(256) void gemm64(const float* __restrict__ A, long long lda, long long strideA,
                                              const float* __restrict__ B, int ldb, long long strideB,
                                              float* __restrict__ C, int ldc, long long strideC,
                                              const float* __restrict__ bias, long long strideBias,
                                              int M, int N, int K, int flags) {
    int bz = blockIdx.z;
    A += (size_t)bz * strideA;
    B += (size_t)bz * strideB;
    C += (size_t)bz * strideC;
    if (bias) bias += (size_t)bz * strideBias;

    __shared__ float As[16][64];
    __shared__ float Bs[16][68];
    int tid = threadIdx.x;
    int m0 = blockIdx.y * 64, n0 = blockIdx.x * 64;
    int arow = tid >> 2, akcol = (tid & 3) * 4;
    int brow = tid >> 4, bcol = (tid & 15) * 4;
    int tx = tid & 15, ty = tid >> 4;

    float acc[4][4];
    #pragma unroll
    for (int i = 0; i < 4; i++)
        #pragma unroll
        for (int j = 0; j < 4; j++) acc[i][j] = 0.f;

    for (int k0 = 0; k0 < K; k0 += 16) {
        float4 a4 = make_float4(0.f, 0.f, 0.f, 0.f);
        int gm = m0 + arow;
        if (gm < M) a4 = *(const float4*)&A[(size_t)gm * lda + k0 + akcol];
        As[akcol + 0][arow] = a4.x;
        As[akcol + 1][arow] = a4.y;
        As[akcol + 2][arow] = a4.z;
        As[akcol + 3][arow] = a4.w;

        float4 b4;
        int gn = n0 + bcol;
        const float* Brow = &B[(size_t)(k0 + brow) * ldb];
        if (gn + 3 < N) {
            b4 = *(const float4*)&Brow[gn];
        } else {
            b4.x = (gn + 0 < N) ? Brow[gn + 0] : 0.f;
            b4.y = (gn + 1 < N) ? Brow[gn + 1] : 0.f;
            b4.z = (gn + 2 < N) ? Brow[gn + 2] : 0.f;
            b4.w = (gn + 3 < N) ? Brow[gn + 3] : 0.f;
        }
        *(float4*)&Bs[brow][bcol] = b4;
        __syncthreads();

        #pragma unroll
        for (int kk = 0; kk < 16; kk++) {
            float4 a0 = *(float4*)&As[kk][ty * 4];
            float4 b0 = *(float4*)&Bs[kk][tx * 4];
            float ar[4] = {a0.x, a0.y, a0.z, a0.w};
            float br[4] = {b0.x, b0.y, b0.z, b0.w};
            #pragma unroll
            for (int i = 0; i < 4; i++)
                #pragma unroll
                for (int j = 0; j < 4; j++) acc[i][j] += ar[i] * br[j];
        }
        __syncthreads();
    }

    #pragma unroll
    for (int i = 0; i < 4; i++) {
        int r = m0 + ty * 4 + i;
        if (r >= M) continue;
        #pragma unroll
        for (int j = 0; j < 4; j++) {
            int c = n0 + tx * 4 + j;
            if (c >= N) continue;
            float val = acc[i][j];
            if (flags & FLAG_BIAS) val += bias[c];
            if (flags & FLAG_GELU) val = gelu_exact(val);
            float* p = &C[(size_t)r * ldc + c];
            if (flags & FLAG_RES) *p += val; else *p = val;
        }
    }
}

// ---------------- fused attention: block per (n, head) ----------------
#define ATT_SMEM_FLOATS (SS*65*2 + 8*200 + 8*64)

__global__ __launch_bounds__(256) void attn_kernel(const float* __restrict__ q,
                                                   const float* __restrict__ k,
                                                   const float* __restrict__ v,
                                                   float* __restrict__ x) {
    extern __shared__ float smf[];
    float* ks = smf;
    float* vs = smf + SS * 65;
    float* sc = vs + SS * 65;
    float* qs = sc + 8 * 200;

    int nh = blockIdx.x;
    int n = nh / HH, h = nh - n * HH;
    int tid = threadIdx.x;
    int wp = tid >> 5, lane = tid & 31;

    const float* kb = k + ((size_t)n * SS) * DD + h * DH;
    const float* vb = v + ((size_t)n * SS) * DD + h * DH;

    for (int idx = tid; idx < SS * 16; idx += 256) {
        int t = idx >> 4;
        int e4 = (idx & 15) * 4;
        float4 kk4 = *(const float4*)&kb[(size_t)t * DD + e4];
        float4 vv4 = *(const float4*)&vb[(size_t)t * DD + e4];
        int base = t * 65 + e4;
        ks[base + 0] = kk4.x; ks[base + 1] = kk4.y; ks[base + 2] = kk4.z; ks[base + 3] = kk4.w;
        vs[base + 0] = vv4.x; vs[base + 1] = vv4.y; vs[base + 2] = vv4.z; vs[base + 3] = vv4.w;
    }
    __syncthreads();

    const float scale = 0.125f;
    float* myqs = qs + wp * 64;
    float* mysc = sc + wp * 200;

    for (int s = wp; s < SS; s += 8) {
        const float* qrow = q + ((size_t)(n * SS + s)) * DD + h * DH;
        myqs[lane]      = qrow[lane];
        myqs[lane + 32] = qrow[lane + 32];
        __syncwarp();

        float qreg[DH];
        #pragma unroll
        for (int e = 0; e < DH; e++) qreg[e] = myqs[e];

        float sreg[7];
        float mx = -1e30f;
        int cnt = 0;
        for (int t = lane; t < SS; t += 32) {
            float a = 0.f;
            #pragma unroll
            for (int e = 0; e < DH; e++) a += qreg[e] * ks[t * 65 + e];
            a *= scale;
            sreg[cnt++] = a;
            mx = fmaxf(mx, a);
        }
        #pragma unroll
        for (int o = 16; o; o >>= 1) mx = fmaxf(mx, __shfl_xor_sync(0xffffffffu, mx, o));
        float sum = 0.f;
        for (int i = 0; i < cnt; i++) {
            sreg[i] = __expf(sreg[i] - mx);
            sum += sreg[i];
        }
        #pragma unroll
        for (int o = 16; o; o >>= 1) sum += __shfl_xor_sync(0xffffffffu, sum, o);
        float inv = 1.0f / sum;
        {
            int i = 0;
            for (int t = lane; t < SS; t += 32) mysc[t] = sreg[i++] * inv;
        }
        __syncwarp();

        float o0 = 0.f, o1 = 0.f;
        for (int t = 0; t < SS; t++) {
            float p = mysc[t];
            o0 += p * vs[t * 65 + lane];
            o1 += p * vs[t * 65 + lane + 32];
        }
        float* xr = x + ((size_t)(n * SS + s)) * DD + h * DH;
        xr[lane]      += o0;
        xr[lane + 32] += o1;
        __syncwarp();
    }
}

// ---------------- final softmax over 1000 classes ----------------
__global__ __launch_bounds__(256) void softmax_out(const float* __restrict__ logits,
                                                   float* __restrict__ out) {
    int n = blockIdx.x;
    int tid = threadIdx.x;
    const float* l = logits + (size_t)n * OUTC;
    __shared__ float sh[8];
    int lane = tid & 31, wp = tid >> 5;

    float mx = -1e30f;
    for (int c = tid; c < OUTC; c += 256) mx = fmaxf(mx, l[c]);
    #pragma unroll
    for (int o = 16; o; o >>= 1) mx = fmaxf(mx, __shfl_xor_sync(0xffffffffu, mx, o));
    if (lane == 0) sh[wp] = mx;
    __syncthreads();
    float gmx = sh[0];
    #pragma unroll
    for (int i = 1; i < 8; i++) gmx = fmaxf(gmx, sh[i]);
    __syncthreads();

    float sum = 0.f;
    for (int c = tid; c < OUTC; c += 256) sum += __expf(l[c] - gmx);
    #pragma unroll
    for (int o = 16; o; o >>= 1) sum += __shfl_xor_sync(0xffffffffu, sum, o);
    if (lane == 0) sh[wp] = sum;
    __syncthreads();
    float tot = 0.f;
    #pragma unroll
    for (int i = 0; i < 8; i++) tot += sh[i];
    float inv = 1.0f / tot;

    for (int c = tid; c < OUTC; c += 256) out[(size_t)n * OUTC + c] = __expf(l[c] - gmx) * inv;
}

// ---------------- launch ----------------
extern "C" void kernel_launch(void* const* d_in, const int* in_sizes, int n_in,
                              void* d_out, int out_size) {
    const float* images = (const float*)d_in[0];
    const float* Wm     = (const float*)d_in[1];
    const float* bm     = (const float*)d_in[2];
    const float* cls    = (const float*)d_in[3];
    const float* pos    = (const float*)d_in[4];
    const float* ln1w   = (const float*)d_in[5];
    const float* ln1b   = (const float*)d_in[6];
    const float* Wq     = (const float*)d_in[7];
    const float* bq     = (const float*)d_in[8];
    const float* Wk     = (const float*)d_in[9];
    const float* bk     = (const float*)d_in[10];
    const float* Wv     = (const float*)d_in[11];
    const float* bv     = (const float*)d_in[12];
    const float* ln2w   = (const float*)d_in[13];
    const float* ln2b   = (const float*)d_in[14];
    const float* W1     = (const float*)d_in[15];
    const float* b1     = (const float*)d_in[16];
    const float* W2     = (const float*)d_in[17];
    const float* b2     = (const float*)d_in[18];
    const float* Wout   = (const float*)d_in[19];
    const float* bout   = (const float*)d_in[20];
    float* out = (float*)d_out;

    float *p_x, *p_h, *p_q, *p_k, *p_v, *p_logits;
    cudaGetSymbolAddress((void**)&p_x, g_x);
    cudaGetSymbolAddress((void**)&p_h, g_h);
    cudaGetSymbolAddress((void**)&p_q, g_q);
    cudaGetSymbolAddress((void**)&p_k, g_k);
    cudaGetSymbolAddress((void**)&p_v, g_v);
    cudaGetSymbolAddress((void**)&p_logits, g_logits);

    __nv_bfloat16 *p_patch_hi, *p_patch_lo, *p_h_hi, *p_h_lo, *p_u_hi, *p_u_lo;
    __nv_bfloat16 *p_Wm_hi, *p_Wm_lo, *p_W1_hi, *p_W1_lo, *p_W2_hi, *p_W2_lo;
    cudaGetSymbolAddress((void**)&p_patch_hi, g_patch_hi);
    cudaGetSymbolAddress((void**)&p_patch_lo, g_patch_lo);
    cudaGetSymbolAddress((void**)&p_h_hi, g_h_hi);
    cudaGetSymbolAddress((void**)&p_h_lo, g_h_lo);
    cudaGetSymbolAddress((void**)&p_u_hi, g_u_hi);
    cudaGetSymbolAddress((void**)&p_u_lo, g_u_lo);
    cudaGetSymbolAddress((void**)&p_Wm_hi, g_Wm_hi);
    cudaGetSymbolAddress((void**)&p_Wm_lo, g_Wm_lo);
    cudaGetSymbolAddress((void**)&p_W1_hi, g_W1_hi);
    cudaGetSymbolAddress((void**)&p_W1_lo, g_W1_lo);
    cudaGetSymbolAddress((void**)&p_W2_hi, g_W2_hi);
    cudaGetSymbolAddress((void**)&p_W2_lo, g_W2_lo);

    const int att_smem = ATT_SMEM_FLOATS * sizeof(float);
    cudaFuncSetAttribute(attn_kernel, cudaFuncAttributeMaxDynamicSharedMemorySize, att_smem);
    cudaFuncSetAttribute(gemm_bf16x3, cudaFuncAttributeMaxDynamicSharedMemorySize, GEMM_SMEM_BYTES);
    cudaFuncSetAttribute(qkv_kernel, cudaFuncAttributeMaxDynamicSharedMemorySize, QKV_SMEM_BYTES);

    // ---- one-time weight splits ----
    split_f32<<<(DD * DD / 4 + 255) / 256, 256>>>(Wm, p_Wm_hi, p_Wm_lo, DD * DD);
    split_f32<<<(LL * DD * FF / 4 + 255) / 256, 256>>>(W1, p_W1_hi, p_W1_lo, LL * DD * FF);
    split_f32<<<(LL * FF * DD / 4 + 255) / 256, 256>>>(W2, p_W2_hi, p_W2_lo, LL * FF * DD);

    // ---- patch extraction + embed GEMM ----
    extract_patches<<<(PROWS * DD + 255) / 256, 256>>>(images, p_patch_hi, p_patch_lo);
    gemm_bf16x3<<<dim3(DD / 128, (PROWS + 127) / 128), 256, GEMM_SMEM_BYTES>>>(
        p_patch_hi, p_patch_lo, DD, p_Wm_hi, p_Wm_lo, DD,
        p_h, nullptr, nullptr, DD, bm, PROWS, DD, DD, FLAG_BIAS);
    assemble<<<(ROWS * DD + 255) / 256, 256>>>(p_h, cls, pos, p_x);

    for (int l = 0; l < LL; l++) {
        ln_kernel<<<ROWS, 256>>>(p_x, ln1w + l * DD, ln1b + l * DD, p_h);

        qkv_kernel<<<dim3((ROWS + 63) / 64, HH), 256, QKV_SMEM_BYTES>>>(
            p_h,
            Wq + (size_t)l * HH * DH * DH, Wk + (size_t)l * HH * DH * DH, Wv + (size_t)l * HH * DH * DH,
            bq + (size_t)l * DD, bk + (size_t)l * DD, bv + (size_t)l * DD,
            p_q, p_k, p_v);

        attn_kernel<<<NN * HH, 256, att_smem>>>(p_q, p_k, p_v, p_x);

        ln_kernel_split<<<ROWS, 256>>>(p_x, ln2w + l * DD, ln2b + l * DD, p_h_hi, p_h_lo);

        gemm_bf16x3<<<dim3(FF / 128, (ROWS + 127) / 128), 256, GEMM_SMEM_BYTES>>>(
            p_h_hi, p_h_lo, DD,
            p_W1_hi + (size_t)l * DD * FF, p_W1_lo + (size_t)l * DD * FF, FF,
            nullptr, p_u_hi, p_u_lo, FF, b1 + (size_t)l * FF,
            ROWS, FF, DD, FLAG_BIAS | FLAG_GELU | FLAG_SPLIT);

        gemm_bf16x3<<<dim3(DD / 128, (ROWS + 127) / 128), 256, GEMM_SMEM_BYTES>>>(
            p_u_hi, p_u_lo, FF,
            p_W2_hi + (size_t)l * FF * DD, p_W2_lo + (size_t)l * FF * DD, DD,
            p_x, nullptr, nullptr, DD, b2 + (size_t)l * DD,
            ROWS, DD, FF, FLAG_BIAS | FLAG_RES);
    }

    // classification head: cls rows have stride SS*DD
    gemm64<<<dim3((OUTC + 63) / 64, 1, 1), 256>>>(
        p_x, (long long)SS * DD, 0,
        Wout, OUTC, 0,
        p_logits, OUTC, 0,
        bout, 0,
        NN, OUTC, DD, FLAG_BIAS);

    softmax_out<<<NN, 256>>>(p_logits, out);
}

// round 6
// speedup vs baseline: 1.7888x; 1.0448x over previous
#include <cuda_runtime.h>
#include <cuda_bf16.h>
#include <math.h>
#include <stdint.h>

// ---------------- problem constants ----------------
#define NN 32
#define CC 3
#define NP 14
#define PS 16
#define DD 768
#define HH 12
#define DH 64
#define SS 197
#define LL 8
#define FF 3072
#define OUTC 1000
#define NPATCH (NP*NP)    // 196
#define ROWS (NN*SS)      // 6304
#define PROWS (NN*NPATCH) // 6272

#define FLAG_BIAS 1
#define FLAG_GELU 2
#define FLAG_RES  4
#define FLAG_SPLIT 8

// ---------------- scratch (device globals; no runtime allocation) ----------------
__device__ float g_x[ROWS * DD];
__device__ float g_h[ROWS * DD];
__device__ float g_q[ROWS * DD];
__device__ float g_k[ROWS * DD];
__device__ float g_v[ROWS * DD];
__device__ float g_logits[NN * OUTC];

__device__ __nv_bfloat16 g_patch_hi[PROWS * DD];
__device__ __nv_bfloat16 g_patch_lo[PROWS * DD];
__device__ __nv_bfloat16 g_h_hi[ROWS * DD];
__device__ __nv_bfloat16 g_h_lo[ROWS * DD];
__device__ __nv_bfloat16 g_u_hi[ROWS * FF];
__device__ __nv_bfloat16 g_u_lo[ROWS * FF];
__device__ __nv_bfloat16 g_Wm_hi[DD * DD];
__device__ __nv_bfloat16 g_Wm_lo[DD * DD];
__device__ __nv_bfloat16 g_W1_hi[LL * DD * FF];
__device__ __nv_bfloat16 g_W1_lo[LL * DD * FF];
__device__ __nv_bfloat16 g_W2_hi[LL * FF * DD];
__device__ __nv_bfloat16 g_W2_lo[LL * FF * DD];

__device__ __forceinline__ float gelu_exact(float x) {
    return 0.5f * x * (1.0f + erff(x * 0.70710678118654752f));
}
__device__ __forceinline__ void split1(float x, __nv_bfloat16* hi, __nv_bfloat16* lo) {
    __nv_bfloat16 h = __float2bfloat16(x);
    *hi = h;
    *lo = __float2bfloat16(x - __bfloat162float(h));
}

// ---------------- generic fp32 -> bf16 hi/lo split ----------------
__global__ void split_f32(const float* __restrict__ src, __nv_bfloat16* __restrict__ hi,
                          __nv_bfloat16* __restrict__ lo, int n) {
    int i = (blockIdx.x * blockDim.x + threadIdx.x) * 4;
    if (i >= n) return;
    float4 v = *(const float4*)&src[i];
    __nv_bfloat16 h0, l0, h1, l1, h2, l2, h3, l3;
    split1(v.x, &h0, &l0); split1(v.y, &h1, &l1);
    split1(v.z, &h2, &l2); split1(v.w, &h3, &l3);
    hi[i] = h0; hi[i + 1] = h1; hi[i + 2] = h2; hi[i + 3] = h3;
    lo[i] = l0; lo[i + 1] = l1; lo[i + 2] = l2; lo[i + 3] = l3;
}

// ---------------- patch extraction (writes split bf16) ----------------
__global__ void extract_patches(const float* __restrict__ images,
                                __nv_bfloat16* __restrict__ Phi,
                                __nv_bfloat16* __restrict__ Plo) {
    int idx = blockIdx.x * blockDim.x + threadIdx.x;
    if (idx >= PROWS * DD) return;
    int row = idx / DD;
    int col = idx - row * DD;
    int n = row / NPATCH;
    int p = row - n * NPATCH;
    int py = p / NP, px = p - py * NP;
    int c = col / (PS * PS);
    int r = col - c * PS * PS;
    int i = r / PS, j = r - i * PS;
    int H = NP * PS;
    float v = images[(((size_t)n * CC + c) * H + (py * PS + i)) * H + (px * PS + j)];
    __nv_bfloat16 h, l;
    split1(v, &h, &l);
    Phi[idx] = h;
    Plo[idx] = l;
}

// ---------------- assemble tokens + cls + pos ----------------
__global__ void assemble(const float* __restrict__ tok, const float* __restrict__ cls,
                         const float* __restrict__ pos, float* __restrict__ x) {
    int idx = blockIdx.x * blockDim.x + threadIdx.x;
    if (idx >= ROWS * DD) return;
    int row = idx / DD;
    int d = idx - row * DD;
    int n = row / SS;
    int s = row - n * SS;
    float v;
    if (s == 0) v = cls[d];
    else        v = tok[((size_t)n * NPATCH + (s - 1)) * DD + d];
    x[idx] = v + pos[(size_t)s * DD + d];
}

// ---------------- layernorm -> fp32 out ----------------
__global__ __launch_bounds__(256) void ln_kernel(const float* __restrict__ x,
                                                 const float* __restrict__ w,
                                                 const float* __restrict__ b,
                                                 float* __restrict__ out) {
    int row = blockIdx.x;
    int tid = threadIdx.x;
    const float* xr = x + (size_t)row * DD;
    float v0 = xr[tid], v1 = xr[tid + 256], v2 = xr[tid + 512];
    __shared__ float sh[8];
    int lane = tid & 31, wp = tid >> 5;

    float s = v0 + v1 + v2;
    #pragma unroll
    for (int o = 16; o; o >>= 1) s += __shfl_xor_sync(0xffffffffu, s, o);
    if (lane == 0) sh[wp] = s;
    __syncthreads();
    float total = 0.f;
    #pragma unroll
    for (int i = 0; i < 8; i++) total += sh[i];
    float mean = total * (1.0f / DD);
    __syncthreads();

    float d0 = v0 - mean, d1 = v1 - mean, d2 = v2 - mean;
    float sq = d0 * d0 + d1 * d1 + d2 * d2;
    #pragma unroll
    for (int o = 16; o; o >>= 1) sq += __shfl_xor_sync(0xffffffffu, sq, o);
    if (lane == 0) sh[wp] = sq;
    __syncthreads();
    float tot2 = 0.f;
    #pragma unroll
    for (int i = 0; i < 8; i++) tot2 += sh[i];
    float rstd = rsqrtf(tot2 * (1.0f / DD) + 1e-5f);

    float* orow = out + (size_t)row * DD;
    orow[tid]       = d0 * rstd * w[tid]       + b[tid];
    orow[tid + 256] = d1 * rstd * w[tid + 256] + b[tid + 256];
    orow[tid + 512] = d2 * rstd * w[tid + 512] + b[tid + 512];
}

// ---------------- layernorm -> split bf16 out ----------------
__global__ __launch_bounds__(256) void ln_kernel_split(const float* __restrict__ x,
                                                       const float* __restrict__ w,
                                                       const float* __restrict__ b,
                                                       __nv_bfloat16* __restrict__ ohi,
                                                       __nv_bfloat16* __restrict__ olo) {
    int row = blockIdx.x;
    int tid = threadIdx.x;
    const float* xr = x + (size_t)row * DD;
    float v0 = xr[tid], v1 = xr[tid + 256], v2 = xr[tid + 512];
    __shared__ float sh[8];
    int lane = tid & 31, wp = tid >> 5;

    float s = v0 + v1 + v2;
    #pragma unroll
    for (int o = 16; o; o >>= 1) s += __shfl_xor_sync(0xffffffffu, s, o);
    if (lane == 0) sh[wp] = s;
    __syncthreads();
    float total = 0.f;
    #pragma unroll
    for (int i = 0; i < 8; i++) total += sh[i];
    float mean = total * (1.0f / DD);
    __syncthreads();

    float d0 = v0 - mean, d1 = v1 - mean, d2 = v2 - mean;
    float sq = d0 * d0 + d1 * d1 + d2 * d2;
    #pragma unroll
    for (int o = 16; o; o >>= 1) sq += __shfl_xor_sync(0xffffffffu, sq, o);
    if (lane == 0) sh[wp] = sq;
    __syncthreads();
    float tot2 = 0.f;
    #pragma unroll
    for (int i = 0; i < 8; i++) tot2 += sh[i];
    float rstd = rsqrtf(tot2 * (1.0f / DD) + 1e-5f);

    size_t base = (size_t)row * DD;
    float r0 = d0 * rstd * w[tid]       + b[tid];
    float r1 = d1 * rstd * w[tid + 256] + b[tid + 256];
    float r2 = d2 * rstd * w[tid + 512] + b[tid + 512];
    __nv_bfloat16 h, l;
    split1(r0, &h, &l); ohi[base + tid]       = h; olo[base + tid]       = l;
    split1(r1, &h, &l); ohi[base + tid + 256] = h; olo[base + tid + 256] = l;
    split1(r2, &h, &l); ohi[base + tid + 512] = h; olo[base + tid + 512] = l;
}

// ================= bf16x3 tensor-core GEMM (2-stage, 2 CTAs/SM) =================
#define BM 128
#define BN 128
#define BKK 32
#define ASTR 40
#define BSTR 136
#define ASZ (BM*ASTR)                 // 5120 bf16
#define BSZ (BKK*BSTR)                // 4352 bf16
#define STAGE_ELEMS (2*(ASZ+BSZ))     // 18944 bf16
#define STAGE_BYTES (STAGE_ELEMS*2)   // 37888
#define GEMM_SMEM_BYTES (2 * STAGE_BYTES)  // 75776 -> two CTAs per SM

__device__ __forceinline__ void ldsm_x4(uint32_t addr, uint32_t* r) {
    asm volatile("ldmatrix.sync.aligned.m8n8.x4.shared.b16 {%0,%1,%2,%3}, [%4];\n"
                 : "=r"(r[0]), "=r"(r[1]), "=r"(r[2]), "=r"(r[3]) : "r"(addr));
}
__device__ __forceinline__ void ldsm_x4_t(uint32_t addr, uint32_t* r) {
    asm volatile("ldmatrix.sync.aligned.m8n8.x4.trans.shared.b16 {%0,%1,%2,%3}, [%4];\n"
                 : "=r"(r[0]), "=r"(r[1]), "=r"(r[2]), "=r"(r[3]) : "r"(addr));
}
__device__ __forceinline__ void mma_bf16(float* c, const uint32_t* a, const uint32_t* b) {
    asm volatile("mma.sync.aligned.m16n8k16.row.col.f32.bf16.bf16.f32 "
                 "{%0,%1,%2,%3},{%4,%5,%6,%7},{%8,%9},{%0,%1,%2,%3};\n"
                 : "+f"(c[0]), "+f"(c[1]), "+f"(c[2]), "+f"(c[3])
                 : "r"(a[0]), "r"(a[1]), "r"(a[2]), "r"(a[3]), "r"(b[0]), "r"(b[1]));
}
__device__ __forceinline__ void cpa16(uint32_t dst, const void* src, int bytes) {
    asm volatile("cp.async.cg.shared.global [%0], [%1], 16, %2;\n"
                 :: "r"(dst), "l"(src), "r"(bytes));
}
__device__ __forceinline__ void cp_commit() {
    asm volatile("cp.async.commit_group;\n");
}
__device__ __forceinline__ void cp_wait1() {
    asm volatile("cp.async.wait_group 1;\n");
}

__device__ __forceinline__ void gemm_issue_stage(
    uint32_t smem_u32, int stage,
    const __nv_bfloat16* __restrict__ Ahi, const __nv_bfloat16* __restrict__ Alo, int lda,
    const __nv_bfloat16* __restrict__ Bhi, const __nv_bfloat16* __restrict__ Blo, int ldb,
    int M, int m0, int n0, int kb, int tid)
{
    uint32_t s = smem_u32 + (uint32_t)stage * STAGE_BYTES;
    uint32_t sAhi = s;
    uint32_t sAlo = s + ASZ * 2;
    uint32_t sBhi = s + 2 * ASZ * 2;
    uint32_t sBlo = s + (2 * ASZ + BSZ) * 2;
    #pragma unroll
    for (int i = 0; i < 2; i++) {
        int chunk = tid + 256 * i;
        int row = chunk >> 2;
        int c16 = chunk & 3;
        int gr = m0 + row;
        int bytes = (gr < M) ? 16 : 0;
        size_t goff = (size_t)gr * lda + kb + c16 * 8;
        uint32_t doff = (uint32_t)(row * ASTR + c16 * 8) * 2;
        cpa16(sAhi + doff, Ahi + goff, bytes);
        cpa16(sAlo + doff, Alo + goff, bytes);
    }
    #pragma unroll
    for (int i = 0; i < 2; i++) {
        int chunk = tid + 256 * i;
        int row = chunk >> 4;
        int c16 = chunk & 15;
        size_t goff = (size_t)(kb + row) * ldb + n0 + c16 * 8;
        uint32_t doff = (uint32_t)(row * BSTR + c16 * 8) * 2;
        cpa16(sBhi + doff, Bhi + goff, 16);
        cpa16(sBlo + doff, Blo + goff, 16);
    }
}

__global__ __launch_bounds__(256, 2) void gemm_bf16x3(
    const __nv_bfloat16* __restrict__ Ahi, const __nv_bfloat16* __restrict__ Alo, int lda,
    const __nv_bfloat16* __restrict__ Bhi, const __nv_bfloat16* __restrict__ Blo, int ldb,
    float* __restrict__ C, __nv_bfloat16* __restrict__ Chi, __nv_bfloat16* __restrict__ Clo,
    int ldc, const float* __restrict__ bias,
    int M, int N, int K, int flags)
{
    extern __shared__ __nv_bfloat16 smbuf[];
    int tid = threadIdx.x;
    int m0 = blockIdx.y * BM;
    int n0 = blockIdx.x * BN;
    int warp = tid >> 5;
    int lane = tid & 31;
    int wm = (warp >> 2) * 64;
    int wn = (warp & 3) * 32;

    float acc[4][4][4];
    #pragma unroll
    for (int i = 0; i < 4; i++)
        #pragma unroll
        for (int j = 0; j < 4; j++)
            #pragma unroll
            for (int c = 0; c < 4; c++) acc[i][j][c] = 0.f;

    uint32_t smem_u32 = (uint32_t)__cvta_generic_to_shared(smbuf);
    const int nk = K / BKK;

    gemm_issue_stage(smem_u32, 0, Ahi, Alo, lda, Bhi, Blo, ldb, M, m0, n0, 0, tid);
    cp_commit();
    gemm_issue_stage(smem_u32, 1, Ahi, Alo, lda, Bhi, Blo, ldb, M, m0, n0, BKK, tid);
    cp_commit();

    for (int kt = 0; kt < nk; kt++) {
        cp_wait1();
        __syncthreads();

        int st = kt & 1;
        uint32_t s = smem_u32 + (uint32_t)st * STAGE_BYTES;
        uint32_t ahi_base = s;
        uint32_t alo_base = s + ASZ * 2;
        uint32_t bhi_base = s + 2 * ASZ * 2;
        uint32_t blo_base = s + (2 * ASZ + BSZ) * 2;

        #pragma unroll
        for (int ks = 0; ks < 2; ks++) {
            int kc = ks * 16;
            // B fragments once per k-step (16 regs live)
            uint32_t bfh[4][2];
            uint32_t bfl[4][2];
            int brow = kc + ((lane >> 3) & 1) * 8 + (lane & 7);
            #pragma unroll
            for (int j = 0; j < 2; j++) {
                int bcol = wn + j * 16 + (lane >> 4) * 8;
                uint32_t off = (uint32_t)((brow * BSTR + bcol) * 2);
                uint32_t th[4];
                uint32_t tl[4];
                ldsm_x4_t(bhi_base + off, th);
                ldsm_x4_t(blo_base + off, tl);
                bfh[2 * j][0] = th[0];
                bfh[2 * j][1] = th[1];
                bfh[2 * j + 1][0] = th[2];
                bfh[2 * j + 1][1] = th[3];
                bfl[2 * j][0] = tl[0];
                bfl[2 * j][1] = tl[1];
                bfl[2 * j + 1][0] = tl[2];
                bfl[2 * j + 1][1] = tl[3];
            }
            // A fragments per mi (8 regs live at a time)
            int arow = lane & 15;
            int acol = kc + (lane >> 4) * 8;
            #pragma unroll
            for (int mi = 0; mi < 4; mi++) {
                uint32_t afh[4];
                uint32_t afl[4];
                uint32_t off = (uint32_t)(((wm + mi * 16 + arow) * ASTR + acol) * 2);
                ldsm_x4(ahi_base + off, afh);
                ldsm_x4(alo_base + off, afl);
                #pragma unroll
                for (int ni = 0; ni < 4; ni++) {
                    mma_bf16(acc[mi][ni], afh, bfh[ni]);
                    mma_bf16(acc[mi][ni], afh, bfl[ni]);
                    mma_bf16(acc[mi][ni], afl, bfh[ni]);
                }
            }
        }

        __syncthreads();
        int nxt = kt + 2;
        if (nxt < nk) {
            gemm_issue_stage(smem_u32, st, Ahi, Alo, lda, Bhi, Blo, ldb,
                             M, m0, n0, nxt * BKK, tid);
        }
        cp_commit();
    }

    // ---- epilogue ----
    #pragma unroll
    for (int mi = 0; mi < 4; mi++) {
        int r0 = m0 + wm + mi * 16 + (lane >> 2);
        #pragma unroll
        for (int ni = 0; ni < 4; ni++) {
            int c0 = n0 + wn + ni * 8 + (lane & 3) * 2;
            #pragma unroll
            for (int half = 0; half < 2; half++) {
                int r = r0 + half * 8;
                if (r >= M) continue;
                #pragma unroll
                for (int e = 0; e < 2; e++) {
                    int c = c0 + e;
                    float val = acc[mi][ni][half * 2 + e];
                    if (flags & FLAG_BIAS) val += bias[c];
                    if (flags & FLAG_GELU) val = gelu_exact(val);
                    if (flags & FLAG_SPLIT) {
                        __nv_bfloat16 h, l;
                        split1(val, &h, &l);
                        Chi[(size_t)r * ldc + c] = h;
                        Clo[(size_t)r * ldc + c] = l;
                    } else {
                        float* p = &C[(size_t)r * ldc + c];
                        if (flags & FLAG_RES) *p += val; else *p = val;
                    }
                }
            }
        }
    }
}

// ---------------- fused QKV: block per (m-block 64, head) ----------------
#define QKV_SMEM_BYTES ((64*68 + 3*64*68) * 4)

__global__ __launch_bounds__(256) void qkv_kernel(
    const float* __restrict__ h,
    const float* __restrict__ Wq, const float* __restrict__ Wk, const float* __restrict__ Wv,
    const float* __restrict__ bq, const float* __restrict__ bk, const float* __restrict__ bv,
    float* __restrict__ q, float* __restrict__ k, float* __restrict__ v)
{
    extern __shared__ float qsm[];
    float* As = qsm;
    float* Ws = qsm + 64 * 68;
    int m0 = blockIdx.x * 64;
    int head = blockIdx.y;
    int tid = threadIdx.x;

    for (int idx = tid; idx < 64 * 64; idx += 256) {
        int r = idx >> 6, c = idx & 63;
        float val = 0.f;
        if (m0 + r < ROWS) val = h[(size_t)(m0 + r) * DD + head * DH + c];
        As[c * 68 + r] = val;
    }
    const float* w0 = Wq + head * DH * DH;
    const float* w1 = Wk + head * DH * DH;
    const float* w2 = Wv + head * DH * DH;
    for (int idx = tid; idx < 64 * 64; idx += 256) {
        int d = idx >> 6, e = idx & 63;
        Ws[0 * 4352 + d * 68 + e] = w0[d * 64 + e];
        Ws[1 * 4352 + d * 68 + e] = w1[d * 64 + e];
        Ws[2 * 4352 + d * 68 + e] = w2[d * 64 + e];
    }
    __syncthreads();

    int tx = tid & 15, ty = tid >> 4;
    float aq[4][4], ak[4][4], av[4][4];
    #pragma unroll
    for (int i = 0; i < 4; i++)
        #pragma unroll
        for (int j = 0; j < 4; j++) { aq[i][j] = 0.f; ak[i][j] = 0.f; av[i][j] = 0.f; }

    for (int kk = 0; kk < 64; kk++) {
        float4 a = *(float4*)&As[kk * 68 + ty * 4];
        float4 b0 = *(float4*)&Ws[0 * 4352 + kk * 68 + tx * 4];
        float4 b1 = *(float4*)&Ws[1 * 4352 + kk * 68 + tx * 4];
        float4 b2 = *(float4*)&Ws[2 * 4352 + kk * 68 + tx * 4];
        float ar[4] = {a.x, a.y, a.z, a.w};
        float q4[4] = {b0.x, b0.y, b0.z, b0.w};
        float k4[4] = {b1.x, b1.y, b1.z, b1.w};
        float v4[4] = {b2.x, b2.y, b2.z, b2.w};
        #pragma unroll
        for (int i = 0; i < 4; i++) {
            #pragma unroll
            for (int j = 0; j < 4; j++) {
                aq[i][j] += ar[i] * q4[j];
                ak[i][j] += ar[i] * k4[j];
                av[i][j] += ar[i] * v4[j];
            }
        }
    }

    #pragma unroll
    for (int i = 0; i < 4; i++) {
        int r = m0 + ty * 4 + i;
        if (r >= ROWS) continue;
        size_t base = (size_t)r * DD + head * DH;
        #pragma unroll
        for (int j = 0; j < 4; j++) {
            int c = tx * 4 + j;
            q[base + c] = aq[i][j] + bq[head * DH + c];
            k[base + c] = ak[i][j] + bk[head * DH + c];
            v[base + c] = av[i][j] + bv[head * DH + c];
        }
    }
}

// ---------------- small GEMM (classification head) ----------------
__global__ __launch_bounds__(256) void gemm64(const float* __restrict__ A, long long lda, long long strideA,
                                              const float* __restrict__ B, int ldb, long long strideB,
                                              float* __restrict__ C, int ldc, long long strideC,
                                              const float* __restrict__ bias, long long strideBias,
                                              int M, int N, int K, int flags) {
    int bz = blockIdx.z;
    A += (size_t)bz * strideA;
    B += (size_t)bz * strideB;
    C += (size_t)bz * strideC;
    if (bias) bias += (size_t)bz * strideBias;

    __shared__ float As[16][64];
    __shared__ float Bs[16][68];
    int tid = threadIdx.x;
    int m0 = blockIdx.y * 64, n0 = blockIdx.x * 64;
    int arow = tid >> 2, akcol = (tid & 3) * 4;
    int brow = tid >> 4, bcol = (tid & 15) * 4;
    int tx = tid & 15, ty = tid >> 4;

    float acc[4][4];
    #pragma unroll
    for (int i = 0; i < 4; i++)
        #pragma unroll
        for (int j = 0; j < 4; j++) acc[i][j] = 0.f;

    for (int k0 = 0; k0 < K; k0 += 16) {
        float4 a4 = make_float4(0.f, 0.f, 0.f, 0.f);
        int gm = m0 + arow;
        if (gm < M) a4 = *(const float4*)&A[(size_t)gm * lda + k0 + akcol];
        As[akcol + 0][arow] = a4.x;
        As[akcol + 1][arow] = a4.y;
        As[akcol + 2][arow] = a4.z;
        As[akcol + 3][arow] = a4.w;

        float4 b4;
        int gn = n0 + bcol;
        const float* Brow = &B[(size_t)(k0 + brow) * ldb];
        if (gn + 3 < N) {
            b4 = *(const float4*)&Brow[gn];
        } else {
            b4.x = (gn + 0 < N) ? Brow[gn + 0] : 0.f;
            b4.y = (gn + 1 < N) ? Brow[gn + 1] : 0.f;
            b4.z = (gn + 2 < N) ? Brow[gn + 2] : 0.f;
            b4.w = (gn + 3 < N) ? Brow[gn + 3] : 0.f;
        }
        *(float4*)&Bs[brow][bcol] = b4;
        __syncthreads();

        #pragma unroll
        for (int kk = 0; kk < 16; kk++) {
            float4 a0 = *(float4*)&As[kk][ty * 4];
            float4 b0 = *(float4*)&Bs[kk][tx * 4];
            float ar[4] = {a0.x, a0.y, a0.z, a0.w};
            float br[4] = {b0.x, b0.y, b0.z, b0.w};
            #pragma unroll
            for (int i = 0; i < 4; i++)
                #pragma unroll
                for (int j = 0; j < 4; j++) acc[i][j] += ar[i] * br[j];
        }
        __syncthreads();
    }

    #pragma unroll
    for (int i = 0; i < 4; i++) {
        int r = m0 + ty * 4 + i;
        if (r >= M) continue;
        #pragma unroll
        for (int j = 0; j < 4; j++) {
            int c = n0 + tx * 4 + j;
            if (c >= N) continue;
            float val = acc[i][j];
            if (flags & FLAG_BIAS) val += bias[c];
            if (flags & FLAG_GELU) val = gelu_exact(val);
            float* p = &C[(size_t)r * ldc + c];
            if (flags & FLAG_RES) *p += val; else *p = val;
        }
    }
}

// ---------------- fused attention: block per (n, head) ----------------
#define ATT_SMEM_FLOATS (SS*65*2 + 8*200 + 8*64)

__global__ __launch_bounds__(256) void attn_kernel(const float* __restrict__ q,
                                                   const float* __restrict__ k,
                                                   const float* __restrict__ v,
                                                   float* __restrict__ x) {
    extern __shared__ float smf[];
    float* ks = smf;
    float* vs = smf + SS * 65;
    float* sc = vs + SS * 65;
    float* qs = sc + 8 * 200;

    int nh = blockIdx.x;
    int n = nh / HH, h = nh - n * HH;
    int tid = threadIdx.x;
    int wp = tid >> 5, lane = tid & 31;

    const float* kb = k + ((size_t)n * SS) * DD + h * DH;
    const float* vb = v + ((size_t)n * SS) * DD + h * DH;

    for (int idx = tid; idx < SS * 16; idx += 256) {
        int t = idx >> 4;
        int e4 = (idx & 15) * 4;
        float4 kk4 = *(const float4*)&kb[(size_t)t * DD + e4];
        float4 vv4 = *(const float4*)&vb[(size_t)t * DD + e4];
        int base = t * 65 + e4;
        ks[base + 0] = kk4.x; ks[base + 1] = kk4.y; ks[base + 2] = kk4.z; ks[base + 3] = kk4.w;
        vs[base + 0] = vv4.x; vs[base + 1] = vv4.y; vs[base + 2] = vv4.z; vs[base + 3] = vv4.w;
    }
    __syncthreads();

    const float scale = 0.125f;
    float* myqs = qs + wp * 64;
    float* mysc = sc + wp * 200;

    for (int s = wp; s < SS; s += 8) {
        const float* qrow = q + ((size_t)(n * SS + s)) * DD + h * DH;
        myqs[lane]      = qrow[lane];
        myqs[lane + 32] = qrow[lane + 32];
        __syncwarp();

        float qreg[DH];
        #pragma unroll
        for (int e = 0; e < DH; e++) qreg[e] = myqs[e];

        float sreg[7];
        float mx = -1e30f;
        int cnt = 0;
        for (int t = lane; t < SS; t += 32) {
            float a = 0.f;
            #pragma unroll
            for (int e = 0; e < DH; e++) a += qreg[e] * ks[t * 65 + e];
            a *= scale;
            sreg[cnt++] = a;
            mx = fmaxf(mx, a);
        }
        #pragma unroll
        for (int o = 16; o; o >>= 1) mx = fmaxf(mx, __shfl_xor_sync(0xffffffffu, mx, o));
        float sum = 0.f;
        for (int i = 0; i < cnt; i++) {
            sreg[i] = __expf(sreg[i] - mx);
            sum += sreg[i];
        }
        #pragma unroll
        for (int o = 16; o; o >>= 1) sum += __shfl_xor_sync(0xffffffffu, sum, o);
        float inv = 1.0f / sum;
        {
            int i = 0;
            for (int t = lane; t < SS; t += 32) mysc[t] = sreg[i++] * inv;
        }
        __syncwarp();

        float o0 = 0.f, o1 = 0.f;
        for (int t = 0; t < SS; t++) {
            float p = mysc[t];
            o0 += p * vs[t * 65 + lane];
            o1 += p * vs[t * 65 + lane + 32];
        }
        float* xr = x + ((size_t)(n * SS + s)) * DD + h * DH;
        xr[lane]      += o0;
        xr[lane + 32] += o1;
        __syncwarp();
    }
}

// ---------------- final softmax over 1000 classes ----------------
__global__ __launch_bounds__(256) void softmax_out(const float* __restrict__ logits,
                                                   float* __restrict__ out) {
    int n = blockIdx.x;
    int tid = threadIdx.x;
    const float* l = logits + (size_t)n * OUTC;
    __shared__ float sh[8];
    int lane = tid & 31, wp = tid >> 5;

    float mx = -1e30f;
    for (int c = tid; c < OUTC; c += 256) mx = fmaxf(mx, l[c]);
    #pragma unroll
    for (int o = 16; o; o >>= 1) mx = fmaxf(mx, __shfl_xor_sync(0xffffffffu, mx, o));
    if (lane == 0) sh[wp] = mx;
    __syncthreads();
    float gmx = sh[0];
    #pragma unroll
    for (int i = 1; i < 8; i++) gmx = fmaxf(gmx, sh[i]);
    __syncthreads();

    float sum = 0.f;
    for (int c = tid; c < OUTC; c += 256) sum += __expf(l[c] - gmx);
    #pragma unroll
    for (int o = 16; o; o >>= 1) sum += __shfl_xor_sync(0xffffffffu, sum, o);
    if (lane == 0) sh[wp] = sum;
    __syncthreads();
    float tot = 0.f;
    #pragma unroll
    for (int i = 0; i < 8; i++) tot += sh[i];
    float inv = 1.0f / tot;

    for (int c = tid; c < OUTC; c += 256) out[(size_t)n * OUTC + c] = __expf(l[c] - gmx) * inv;
}

// ---------------- launch ----------------
extern "C" void kernel_launch(void* const* d_in, const int* in_sizes, int n_in,
                              void* d_out, int out_size) {
    const float* images = (const float*)d_in[0];
    const float* Wm     = (const float*)d_in[1];
    const float* bm     = (const float*)d_in[2];
    const float* cls    = (const float*)d_in[3];
    const float* pos    = (const float*)d_in[4];
    const float* ln1w   = (const float*)d_in[5];
    const float* ln1b   = (const float*)d_in[6];
    const float* Wq     = (const float*)d_in[7];
    const float* bq     = (const float*)d_in[8];
    const float* Wk     = (const float*)d_in[9];
    const float* bk     = (const float*)d_in[10];
    const float* Wv     = (const float*)d_in[11];
    const float* bv     = (const float*)d_in[12];
    const float* ln2w   = (const float*)d_in[13];
    const float* ln2b   = (const float*)d_in[14];
    const float* W1     = (const float*)d_in[15];
    const float* b1     = (const float*)d_in[16];
    const float* W2     = (const float*)d_in[17];
    const float* b2     = (const float*)d_in[18];
    const float* Wout   = (const float*)d_in[19];
    const float* bout   = (const float*)d_in[20];
    float* out = (float*)d_out;

    float *p_x, *p_h, *p_q, *p_k, *p_v, *p_logits;
    cudaGetSymbolAddress((void**)&p_x, g_x);
    cudaGetSymbolAddress((void**)&p_h, g_h);
    cudaGetSymbolAddress((void**)&p_q, g_q);
    cudaGetSymbolAddress((void**)&p_k, g_k);
    cudaGetSymbolAddress((void**)&p_v, g_v);
    cudaGetSymbolAddress((void**)&p_logits, g_logits);

    __nv_bfloat16 *p_patch_hi, *p_patch_lo, *p_h_hi, *p_h_lo, *p_u_hi, *p_u_lo;
    __nv_bfloat16 *p_Wm_hi, *p_Wm_lo, *p_W1_hi, *p_W1_lo, *p_W2_hi, *p_W2_lo;
    cudaGetSymbolAddress((void**)&p_patch_hi, g_patch_hi);
    cudaGetSymbolAddress((void**)&p_patch_lo, g_patch_lo);
    cudaGetSymbolAddress((void**)&p_h_hi, g_h_hi);
    cudaGetSymbolAddress((void**)&p_h_lo, g_h_lo);
    cudaGetSymbolAddress((void**)&p_u_hi, g_u_hi);
    cudaGetSymbolAddress((void**)&p_u_lo, g_u_lo);
    cudaGetSymbolAddress((void**)&p_Wm_hi, g_Wm_hi);
    cudaGetSymbolAddress((void**)&p_Wm_lo, g_Wm_lo);
    cudaGetSymbolAddress((void**)&p_W1_hi, g_W1_hi);
    cudaGetSymbolAddress((void**)&p_W1_lo, g_W1_lo);
    cudaGetSymbolAddress((void**)&p_W2_hi, g_W2_hi);
    cudaGetSymbolAddress((void**)&p_W2_lo, g_W2_lo);

    const int att_smem = ATT_SMEM_FLOATS * sizeof(float);
    cudaFuncSetAttribute(attn_kernel, cudaFuncAttributeMaxDynamicSharedMemorySize, att_smem);
    cudaFuncSetAttribute(gemm_bf16x3, cudaFuncAttributeMaxDynamicSharedMemorySize, GEMM_SMEM_BYTES);
    cudaFuncSetAttribute(qkv_kernel, cudaFuncAttributeMaxDynamicSharedMemorySize, QKV_SMEM_BYTES);

    // ---- one-time weight splits ----
    split_f32<<<(DD * DD / 4 + 255) / 256, 256>>>(Wm, p_Wm_hi, p_Wm_lo, DD * DD);
    split_f32<<<(LL * DD * FF / 4 + 255) / 256, 256>>>(W1, p_W1_hi, p_W1_lo, LL * DD * FF);
    split_f32<<<(LL * FF * DD / 4 + 255) / 256, 256>>>(W2, p_W2_hi, p_W2_lo, LL * FF * DD);

    // ---- patch extraction + embed GEMM ----
    extract_patches<<<(PROWS * DD + 255) / 256, 256>>>(images, p_patch_hi, p_patch_lo);
    gemm_bf16x3<<<dim3(DD / 128, (PROWS + 127) / 128), 256, GEMM_SMEM_BYTES>>>(
        p_patch_hi, p_patch_lo, DD, p_Wm_hi, p_Wm_lo, DD,
        p_h, nullptr, nullptr, DD, bm, PROWS, DD, DD, FLAG_BIAS);
    assemble<<<(ROWS * DD + 255) / 256, 256>>>(p_h, cls, pos, p_x);

    for (int l = 0; l < LL; l++) {
        ln_kernel<<<ROWS, 256>>>(p_x, ln1w + l * DD, ln1b + l * DD, p_h);

        qkv_kernel<<<dim3((ROWS + 63) / 64, HH), 256, QKV_SMEM_BYTES>>>(
            p_h,
            Wq + (size_t)l * HH * DH * DH, Wk + (size_t)l * HH * DH * DH, Wv + (size_t)l * HH * DH * DH,
            bq + (size_t)l * DD, bk + (size_t)l * DD, bv + (size_t)l * DD,
            p_q, p_k, p_v);

        attn_kernel<<<NN * HH, 256, att_smem>>>(p_q, p_k, p_v, p_x);

        ln_kernel_split<<<ROWS, 256>>>(p_x, ln2w + l * DD, ln2b + l * DD, p_h_hi, p_h_lo);

        gemm_bf16x3<<<dim3(FF / 128, (ROWS + 127) / 128), 256, GEMM_SMEM_BYTES>>>(
            p_h_hi, p_h_lo, DD,
            p_W1_hi + (size_t)l * DD * FF, p_W1_lo + (size_t)l * DD * FF, FF,
            nullptr, p_u_hi, p_u_lo, FF, b1 + (size_t)l * FF,
            ROWS, FF, DD, FLAG_BIAS | FLAG_GELU | FLAG_SPLIT);

        gemm_bf16x3<<<dim3(DD / 128, (ROWS + 127) / 128), 256, GEMM_SMEM_BYTES>>>(
            p_u_hi, p_u_lo, FF,
            p_W2_hi + (size_t)l * FF * DD, p_W2_lo + (size_t)l * FF * DD, DD,
            p_x, nullptr, nullptr, DD, b2 + (size_t)l * DD,
            ROWS, DD, FF, FLAG_BIAS | FLAG_RES);
    }

    // classification head: cls rows have stride SS*DD
    gemm64<<<dim3((OUTC + 63) / 64, 1, 1), 256>>>(
        p_x, (long long)SS * DD, 0,
        Wout, OUTC, 0,
        p_logits, OUTC, 0,
        bout, 0,
        NN, OUTC, DD, FLAG_BIAS);

    softmax_out<<<NN, 256>>>(p_logits, out);
}

// round 7
// speedup vs baseline: 2.0441x; 1.1427x over previous
#include <cuda_runtime.h>
#include <cuda_fp16.h>
#include <math.h>
#include <stdint.h>

// ---------------- problem constants ----------------
#define NN 32
#define CC 3
#define NP 14
#define PS 16
#define DD 768
#define HH 12
#define DH 64
#define SS 197
#define LL 8
#define FF 3072
#define OUTC 1000
#define NPATCH (NP*NP)    // 196
#define ROWS (NN*SS)      // 6304
#define PROWS (NN*NPATCH) // 6272

#define FLAG_BIAS 1
#define FLAG_GELU 2
#define FLAG_RES  4
#define FLAG_SPLIT 8

// ---------------- scratch (device globals; no runtime allocation) ----------------
__device__ float g_x[ROWS * DD];
__device__ float g_h[ROWS * DD];
__device__ float g_q[ROWS * DD];
__device__ float g_k[ROWS * DD];
__device__ float g_v[ROWS * DD];
__device__ float g_logits[NN * OUTC];

__device__ __half g_patch_hi[PROWS * DD];
__device__ __half g_patch_lo[PROWS * DD];
__device__ __half g_h_hi[ROWS * DD];
__device__ __half g_h_lo[ROWS * DD];
__device__ __half g_u_hi[ROWS * FF];
__device__ __half g_u_lo[ROWS * FF];
__device__ __half g_Wm_f16[DD * DD];
__device__ __half g_W1_f16[LL * DD * FF];
__device__ __half g_W2_f16[LL * FF * DD];

__device__ __forceinline__ float gelu_exact(float x) {
    return 0.5f * x * (1.0f + erff(x * 0.70710678118654752f));
}
__device__ __forceinline__ void split1h(float x, __half* hi, __half* lo) {
    __half h = __float2half(x);
    *hi = h;
    *lo = __float2half(x - __half2float(h));
}

// ---------------- fp32 -> fp16 weight conversion ----------------
__global__ void conv_f16(const float* __restrict__ src, __half* __restrict__ dst, int n) {
    int i = (blockIdx.x * blockDim.x + threadIdx.x) * 4;
    if (i >= n) return;
    float4 v = *(const float4*)&src[i];
    __half2* d = (__half2*)&dst[i];
    d[0] = __floats2half2_rn(v.x, v.y);
    d[1] = __floats2half2_rn(v.z, v.w);
}

// ---------------- patch extraction (writes split fp16) ----------------
__global__ void extract_patches(const float* __restrict__ images,
                                __half* __restrict__ Phi,
                                __half* __restrict__ Plo) {
    int idx = blockIdx.x * blockDim.x + threadIdx.x;
    if (idx >= PROWS * DD) return;
    int row = idx / DD;
    int col = idx - row * DD;
    int n = row / NPATCH;
    int p = row - n * NPATCH;
    int py = p / NP, px = p - py * NP;
    int c = col / (PS * PS);
    int r = col - c * PS * PS;
    int i = r / PS, j = r - i * PS;
    int H = NP * PS;
    float v = images[(((size_t)n * CC + c) * H + (py * PS + i)) * H + (px * PS + j)];
    __half h, l;
    split1h(v, &h, &l);
    Phi[idx] = h;
    Plo[idx] = l;
}

// ---------------- assemble tokens + cls + pos ----------------
__global__ void assemble(const float* __restrict__ tok, const float* __restrict__ cls,
                         const float* __restrict__ pos, float* __restrict__ x) {
    int idx = blockIdx.x * blockDim.x + threadIdx.x;
    if (idx >= ROWS * DD) return;
    int row = idx / DD;
    int d = idx - row * DD;
    int n = row / SS;
    int s = row - n * SS;
    float v;
    if (s == 0) v = cls[d];
    else        v = tok[((size_t)n * NPATCH + (s - 1)) * DD + d];
    x[idx] = v + pos[(size_t)s * DD + d];
}

// ---------------- layernorm -> fp32 out ----------------
__global__ __launch_bounds__(256) void ln_kernel(const float* __restrict__ x,
                                                 const float* __restrict__ w,
                                                 const float* __restrict__ b,
                                                 float* __restrict__ out) {
    int row = blockIdx.x;
    int tid = threadIdx.x;
    const float* xr = x + (size_t)row * DD;
    float v0 = xr[tid], v1 = xr[tid + 256], v2 = xr[tid + 512];
    __shared__ float sh[8];
    int lane = tid & 31, wp = tid >> 5;

    float s = v0 + v1 + v2;
    #pragma unroll
    for (int o = 16; o; o >>= 1) s += __shfl_xor_sync(0xffffffffu, s, o);
    if (lane == 0) sh[wp] = s;
    __syncthreads();
    float total = 0.f;
    #pragma unroll
    for (int i = 0; i < 8; i++) total += sh[i];
    float mean = total * (1.0f / DD);
    __syncthreads();

    float d0 = v0 - mean, d1 = v1 - mean, d2 = v2 - mean;
    float sq = d0 * d0 + d1 * d1 + d2 * d2;
    #pragma unroll
    for (int o = 16; o; o >>= 1) sq += __shfl_xor_sync(0xffffffffu, sq, o);
    if (lane == 0) sh[wp] = sq;
    __syncthreads();
    float tot2 = 0.f;
    #pragma unroll
    for (int i = 0; i < 8; i++) tot2 += sh[i];
    float rstd = rsqrtf(tot2 * (1.0f / DD) + 1e-5f);

    float* orow = out + (size_t)row * DD;
    orow[tid]       = d0 * rstd * w[tid]       + b[tid];
    orow[tid + 256] = d1 * rstd * w[tid + 256] + b[tid + 256];
    orow[tid + 512] = d2 * rstd * w[tid + 512] + b[tid + 512];
}

// ---------------- layernorm -> split fp16 out ----------------
__global__ __launch_bounds__(256) void ln_kernel_split(const float* __restrict__ x,
                                                       const float* __restrict__ w,
                                                       const float* __restrict__ b,
                                                       __half* __restrict__ ohi,
                                                       __half* __restrict__ olo) {
    int row = blockIdx.x;
    int tid = threadIdx.x;
    const float* xr = x + (size_t)row * DD;
    float v0 = xr[tid], v1 = xr[tid + 256], v2 = xr[tid + 512];
    __shared__ float sh[8];
    int lane = tid & 31, wp = tid >> 5;

    float s = v0 + v1 + v2;
    #pragma unroll
    for (int o = 16; o; o >>= 1) s += __shfl_xor_sync(0xffffffffu, s, o);
    if (lane == 0) sh[wp] = s;
    __syncthreads();
    float total = 0.f;
    #pragma unroll
    for (int i = 0; i < 8; i++) total += sh[i];
    float mean = total * (1.0f / DD);
    __syncthreads();

    float d0 = v0 - mean, d1 = v1 - mean, d2 = v2 - mean;
    float sq = d0 * d0 + d1 * d1 + d2 * d2;
    #pragma unroll
    for (int o = 16; o; o >>= 1) sq += __shfl_xor_sync(0xffffffffu, sq, o);
    if (lane == 0) sh[wp] = sq;
    __syncthreads();
    float tot2 = 0.f;
    #pragma unroll
    for (int i = 0; i < 8; i++) tot2 += sh[i];
    float rstd = rsqrtf(tot2 * (1.0f / DD) + 1e-5f);

    size_t base = (size_t)row * DD;
    float r0 = d0 * rstd * w[tid]       + b[tid];
    float r1 = d1 * rstd * w[tid + 256] + b[tid + 256];
    float r2 = d2 * rstd * w[tid + 512] + b[tid + 512];
    __half h, l;
    split1h(r0, &h, &l); ohi[base + tid]       = h; olo[base + tid]       = l;
    split1h(r1, &h, &l); ohi[base + tid + 256] = h; olo[base + tid + 256] = l;
    split1h(r2, &h, &l); ohi[base + tid + 512] = h; olo[base + tid + 512] = l;
}

// ================= fp16x2 tensor-core GEMM (A split hi/lo, B single fp16) ==========
#define BM 128
#define BN 128
#define BKK 32
#define ASTR 40
#define BSTR 136
#define ASZ (BM*ASTR)                 // 5120 halves
#define BSZ (BKK*BSTR)                // 4352 halves
#define STAGE_ELEMS (2*ASZ + BSZ)     // 14592 halves
#define STAGE_BYTES (STAGE_ELEMS*2)   // 29184
#define GEMM_SMEM_BYTES (2 * STAGE_BYTES)  // 58368 -> two CTAs per SM

__device__ __forceinline__ void ldsm_x4(uint32_t addr, uint32_t* r) {
    asm volatile("ldmatrix.sync.aligned.m8n8.x4.shared.b16 {%0,%1,%2,%3}, [%4];\n"
                 : "=r"(r[0]), "=r"(r[1]), "=r"(r[2]), "=r"(r[3]) : "r"(addr));
}
__device__ __forceinline__ void ldsm_x4_t(uint32_t addr, uint32_t* r) {
    asm volatile("ldmatrix.sync.aligned.m8n8.x4.trans.shared.b16 {%0,%1,%2,%3}, [%4];\n"
                 : "=r"(r[0]), "=r"(r[1]), "=r"(r[2]), "=r"(r[3]) : "r"(addr));
}
__device__ __forceinline__ void mma_f16(float* c, const uint32_t* a, const uint32_t* b) {
    asm volatile("mma.sync.aligned.m16n8k16.row.col.f32.f16.f16.f32 "
                 "{%0,%1,%2,%3},{%4,%5,%6,%7},{%8,%9},{%0,%1,%2,%3};\n"
                 : "+f"(c[0]), "+f"(c[1]), "+f"(c[2]), "+f"(c[3])
                 : "r"(a[0]), "r"(a[1]), "r"(a[2]), "r"(a[3]), "r"(b[0]), "r"(b[1]));
}
__device__ __forceinline__ void cpa16(uint32_t dst, const void* src, int bytes) {
    asm volatile("cp.async.cg.shared.global [%0], [%1], 16, %2;\n"
                 :: "r"(dst), "l"(src), "r"(bytes));
}
__device__ __forceinline__ void cp_commit() {
    asm volatile("cp.async.commit_group;\n");
}
__device__ __forceinline__ void cp_wait1() {
    asm volatile("cp.async.wait_group 1;\n");
}

__device__ __forceinline__ void gemm_issue_stage(
    uint32_t smem_u32, int stage,
    const __half* __restrict__ Ahi, const __half* __restrict__ Alo, int lda,
    const __half* __restrict__ B, int ldb,
    int M, int m0, int n0, int kb, int tid)
{
    uint32_t s = smem_u32 + (uint32_t)stage * STAGE_BYTES;
    uint32_t sAhi = s;
    uint32_t sAlo = s + ASZ * 2;
    uint32_t sB   = s + 2 * ASZ * 2;
    #pragma unroll
    for (int i = 0; i < 2; i++) {
        int chunk = tid + 256 * i;
        int row = chunk >> 2;
        int c16 = chunk & 3;
        int gr = m0 + row;
        int bytes = (gr < M) ? 16 : 0;
        size_t goff = (size_t)gr * lda + kb + c16 * 8;
        uint32_t doff = (uint32_t)(row * ASTR + c16 * 8) * 2;
        cpa16(sAhi + doff, Ahi + goff, bytes);
        cpa16(sAlo + doff, Alo + goff, bytes);
    }
    #pragma unroll
    for (int i = 0; i < 2; i++) {
        int chunk = tid + 256 * i;
        int row = chunk >> 4;
        int c16 = chunk & 15;
        size_t goff = (size_t)(kb + row) * ldb + n0 + c16 * 8;
        uint32_t doff = (uint32_t)(row * BSTR + c16 * 8) * 2;
        cpa16(sB + doff, B + goff, 16);
    }
}

__global__ __launch_bounds__(256, 2) void gemm_f16x2(
    const __half* __restrict__ Ahi, const __half* __restrict__ Alo, int lda,
    const __half* __restrict__ B, int ldb,
    float* __restrict__ C, __half* __restrict__ Chi, __half* __restrict__ Clo,
    int ldc, const float* __restrict__ bias,
    int M, int N, int K, int flags)
{
    extern __shared__ __half smbuf[];
    int tid = threadIdx.x;
    int m0 = blockIdx.y * BM;
    int n0 = blockIdx.x * BN;
    int warp = tid >> 5;
    int lane = tid & 31;
    int wm = (warp >> 2) * 64;
    int wn = (warp & 3) * 32;

    float acc[4][4][4];
    #pragma unroll
    for (int i = 0; i < 4; i++)
        #pragma unroll
        for (int j = 0; j < 4; j++)
            #pragma unroll
            for (int c = 0; c < 4; c++) acc[i][j][c] = 0.f;

    uint32_t smem_u32 = (uint32_t)__cvta_generic_to_shared(smbuf);
    const int nk = K / BKK;

    gemm_issue_stage(smem_u32, 0, Ahi, Alo, lda, B, ldb, M, m0, n0, 0, tid);
    cp_commit();
    gemm_issue_stage(smem_u32, 1, Ahi, Alo, lda, B, ldb, M, m0, n0, BKK, tid);
    cp_commit();

    for (int kt = 0; kt < nk; kt++) {
        cp_wait1();
        __syncthreads();

        int st = kt & 1;
        uint32_t s = smem_u32 + (uint32_t)st * STAGE_BYTES;
        uint32_t ahi_base = s;
        uint32_t alo_base = s + ASZ * 2;
        uint32_t b_base   = s + 2 * ASZ * 2;

        #pragma unroll
        for (int ks = 0; ks < 2; ks++) {
            int kc = ks * 16;
            // B fragments once per k-step (8 regs live)
            uint32_t bf[4][2];
            int brow = kc + ((lane >> 3) & 1) * 8 + (lane & 7);
            #pragma unroll
            for (int j = 0; j < 2; j++) {
                int bcol = wn + j * 16 + (lane >> 4) * 8;
                uint32_t off = (uint32_t)((brow * BSTR + bcol) * 2);
                uint32_t th[4];
                ldsm_x4_t(b_base + off, th);
                bf[2 * j][0] = th[0];
                bf[2 * j][1] = th[1];
                bf[2 * j + 1][0] = th[2];
                bf[2 * j + 1][1] = th[3];
            }
            // A fragments per mi (8 regs live at a time)
            int arow = lane & 15;
            int acol = kc + (lane >> 4) * 8;
            #pragma unroll
            for (int mi = 0; mi < 4; mi++) {
                uint32_t afh[4];
                uint32_t afl[4];
                uint32_t off = (uint32_t)(((wm + mi * 16 + arow) * ASTR + acol) * 2);
                ldsm_x4(ahi_base + off, afh);
                ldsm_x4(alo_base + off, afl);
                #pragma unroll
                for (int ni = 0; ni < 4; ni++) {
                    mma_f16(acc[mi][ni], afh, bf[ni]);
                    mma_f16(acc[mi][ni], afl, bf[ni]);
                }
            }
        }

        __syncthreads();
        int nxt = kt + 2;
        if (nxt < nk) {
            gemm_issue_stage(smem_u32, st, Ahi, Alo, lda, B, ldb,
                             M, m0, n0, nxt * BKK, tid);
        }
        cp_commit();
    }

    // ---- epilogue ----
    #pragma unroll
    for (int mi = 0; mi < 4; mi++) {
        int r0 = m0 + wm + mi * 16 + (lane >> 2);
        #pragma unroll
        for (int ni = 0; ni < 4; ni++) {
            int c0 = n0 + wn + ni * 8 + (lane & 3) * 2;
            #pragma unroll
            for (int half = 0; half < 2; half++) {
                int r = r0 + half * 8;
                if (r >= M) continue;
                #pragma unroll
                for (int e = 0; e < 2; e++) {
                    int c = c0 + e;
                    float val = acc[mi][ni][half * 2 + e];
                    if (flags & FLAG_BIAS) val += bias[c];
                    if (flags & FLAG_GELU) val = gelu_exact(val);
                    if (flags & FLAG_SPLIT) {
                        __half h, l;
                        split1h(val, &h, &l);
                        Chi[(size_t)r * ldc + c] = h;
                        Clo[(size_t)r * ldc + c] = l;
                    } else {
                        float* p = &C[(size_t)r * ldc + c];
                        if (flags & FLAG_RES) *p += val; else *p = val;
                    }
                }
            }
        }
    }
}

// ---------------- fused QKV: block per (m-block 64, head) ----------------
#define QKV_SMEM_BYTES ((64*68 + 3*64*68) * 4)

__global__ __launch_bounds__(256) void qkv_kernel(
    const float* __restrict__ h,
    const float* __restrict__ Wq, const float* __restrict__ Wk, const float* __restrict__ Wv,
    const float* __restrict__ bq, const float* __restrict__ bk, const float* __restrict__ bv,
    float* __restrict__ q, float* __restrict__ k, float* __restrict__ v)
{
    extern __shared__ float qsm[];
    float* As = qsm;
    float* Ws = qsm + 64 * 68;
    int m0 = blockIdx.x * 64;
    int head = blockIdx.y;
    int tid = threadIdx.x;

    for (int idx = tid; idx < 64 * 64; idx += 256) {
        int r = idx >> 6, c = idx & 63;
        float val = 0.f;
        if (m0 + r < ROWS) val = h[(size_t)(m0 + r) * DD + head * DH + c];
        As[c * 68 + r] = val;
    }
    const float* w0 = Wq + head * DH * DH;
    const float* w1 = Wk + head * DH * DH;
    const float* w2 = Wv + head * DH * DH;
    for (int idx = tid; idx < 64 * 64; idx += 256) {
        int d = idx >> 6, e = idx & 63;
        Ws[0 * 4352 + d * 68 + e] = w0[d * 64 + e];
        Ws[1 * 4352 + d * 68 + e] = w1[d * 64 + e];
        Ws[2 * 4352 + d * 68 + e] = w2[d * 64 + e];
    }
    __syncthreads();

    int tx = tid & 15, ty = tid >> 4;
    float aq[4][4], ak[4][4], av[4][4];
    #pragma unroll
    for (int i = 0; i < 4; i++)
        #pragma unroll
        for (int j = 0; j < 4; j++) { aq[i][j] = 0.f; ak[i][j] = 0.f; av[i][j] = 0.f; }

    for (int kk = 0; kk < 64; kk++) {
        float4 a = *(float4*)&As[kk * 68 + ty * 4];
        float4 b0 = *(float4*)&Ws[0 * 4352 + kk * 68 + tx * 4];
        float4 b1 = *(float4*)&Ws[1 * 4352 + kk * 68 + tx * 4];
        float4 b2 = *(float4*)&Ws[2 * 4352 + kk * 68 + tx * 4];
        float ar[4] = {a.x, a.y, a.z, a.w};
        float q4[4] = {b0.x, b0.y, b0.z, b0.w};
        float k4[4] = {b1.x, b1.y, b1.z, b1.w};
        float v4[4] = {b2.x, b2.y, b2.z, b2.w};
        #pragma unroll
        for (int i = 0; i < 4; i++) {
            #pragma unroll
            for (int j = 0; j < 4; j++) {
                aq[i][j] += ar[i] * q4[j];
                ak[i][j] += ar[i] * k4[j];
                av[i][j] += ar[i] * v4[j];
            }
        }
    }

    #pragma unroll
    for (int i = 0; i < 4; i++) {
        int r = m0 + ty * 4 + i;
        if (r >= ROWS) continue;
        size_t base = (size_t)r * DD + head * DH;
        #pragma unroll
        for (int j = 0; j < 4; j++) {
            int c = tx * 4 + j;
            q[base + c] = aq[i][j] + bq[head * DH + c];
            k[base + c] = ak[i][j] + bk[head * DH + c];
            v[base + c] = av[i][j] + bv[head * DH + c];
        }
    }
}

// ---------------- small GEMM (classification head) ----------------
__global__ __launch_bounds__(256) void gemm64(const float* __restrict__ A, long long lda, long long strideA,
                                              const float* __restrict__ B, int ldb, long long strideB,
                                              float* __restrict__ C, int ldc, long long strideC,
                                              const float* __restrict__ bias, long long strideBias,
                                              int M, int N, int K, int flags) {
    int bz = blockIdx.z;
    A += (size_t)bz * strideA;
    B += (size_t)bz * strideB;
    C += (size_t)bz * strideC;
    if (bias) bias += (size_t)bz * strideBias;

    __shared__ float As[16][64];
    __shared__ float Bs[16][68];
    int tid = threadIdx.x;
    int m0 = blockIdx.y * 64, n0 = blockIdx.x * 64;
    int arow = tid >> 2, akcol = (tid & 3) * 4;
    int brow = tid >> 4, bcol = (tid & 15) * 4;
    int tx = tid & 15, ty = tid >> 4;

    float acc[4][4];
    #pragma unroll
    for (int i = 0; i < 4; i++)
        #pragma unroll
        for (int j = 0; j < 4; j++) acc[i][j] = 0.f;

    for (int k0 = 0; k0 < K; k0 += 16) {
        float4 a4 = make_float4(0.f, 0.f, 0.f, 0.f);
        int gm = m0 + arow;
        if (gm < M) a4 = *(const float4*)&A[(size_t)gm * lda + k0 + akcol];
        As[akcol + 0][arow] = a4.x;
        As[akcol + 1][arow] = a4.y;
        As[akcol + 2][arow] = a4.z;
        As[akcol + 3][arow] = a4.w;

        float4 b4;
        int gn = n0 + bcol;
        const float* Brow = &B[(size_t)(k0 + brow) * ldb];
        if (gn + 3 < N) {
            b4 = *(const float4*)&Brow[gn];
        } else {
            b4.x = (gn + 0 < N) ? Brow[gn + 0] : 0.f;
            b4.y = (gn + 1 < N) ? Brow[gn + 1] : 0.f;
            b4.z = (gn + 2 < N) ? Brow[gn + 2] : 0.f;
            b4.w = (gn + 3 < N) ? Brow[gn + 3] : 0.f;
        }
        *(float4*)&Bs[brow][bcol] = b4;
        __syncthreads();

        #pragma unroll
        for (int kk = 0; kk < 16; kk++) {
            float4 a0 = *(float4*)&As[kk][ty * 4];
            float4 b0 = *(float4*)&Bs[kk][tx * 4];
            float ar[4] = {a0.x, a0.y, a0.z, a0.w};
            float br[4] = {b0.x, b0.y, b0.z, b0.w};
            #pragma unroll
            for (int i = 0; i < 4; i++)
                #pragma unroll
                for (int j = 0; j < 4; j++) acc[i][j] += ar[i] * br[j];
        }
        __syncthreads();
    }

    #pragma unroll
    for (int i = 0; i < 4; i++) {
        int r = m0 + ty * 4 + i;
        if (r >= M) continue;
        #pragma unroll
        for (int j = 0; j < 4; j++) {
            int c = n0 + tx * 4 + j;
            if (c >= N) continue;
            float val = acc[i][j];
            if (flags & FLAG_BIAS) val += bias[c];
            if (flags & FLAG_GELU) val = gelu_exact(val);
            float* p = &C[(size_t)r * ldc + c];
            if (flags & FLAG_RES) *p += val; else *p = val;
        }
    }
}

// ---------------- fused attention: block per (n, head) ----------------
#define ATT_SMEM_FLOATS (SS*65*2 + 8*200 + 8*64)

__global__ __launch_bounds__(256) void attn_kernel(const float* __restrict__ q,
                                                   const float* __restrict__ k,
                                                   const float* __restrict__ v,
                                                   float* __restrict__ x) {
    extern __shared__ float smf[];
    float* ks = smf;
    float* vs = smf + SS * 65;
    float* sc = vs + SS * 65;
    float* qs = sc + 8 * 200;

    int nh = blockIdx.x;
    int n = nh / HH, h = nh - n * HH;
    int tid = threadIdx.x;
    int wp = tid >> 5, lane = tid & 31;

    const float* kb = k + ((size_t)n * SS) * DD + h * DH;
    const float* vb = v + ((size_t)n * SS) * DD + h * DH;

    for (int idx = tid; idx < SS * 16; idx += 256) {
        int t = idx >> 4;
        int e4 = (idx & 15) * 4;
        float4 kk4 = *(const float4*)&kb[(size_t)t * DD + e4];
        float4 vv4 = *(const float4*)&vb[(size_t)t * DD + e4];
        int base = t * 65 + e4;
        ks[base + 0] = kk4.x; ks[base + 1] = kk4.y; ks[base + 2] = kk4.z; ks[base + 3] = kk4.w;
        vs[base + 0] = vv4.x; vs[base + 1] = vv4.y; vs[base + 2] = vv4.z; vs[base + 3] = vv4.w;
    }
    __syncthreads();

    const float scale = 0.125f;
    float* myqs = qs + wp * 64;
    float* mysc = sc + wp * 200;

    for (int s = wp; s < SS; s += 8) {
        const float* qrow = q + ((size_t)(n * SS + s)) * DD + h * DH;
        myqs[lane]      = qrow[lane];
        myqs[lane + 32] = qrow[lane + 32];
        __syncwarp();

        float qreg[DH];
        #pragma unroll
        for (int e = 0; e < DH; e++) qreg[e] = myqs[e];

        float sreg[7];
        float mx = -1e30f;
        int cnt = 0;
        for (int t = lane; t < SS; t += 32) {
            float a = 0.f;
            #pragma unroll
            for (int e = 0; e < DH; e++) a += qreg[e] * ks[t * 65 + e];
            a *= scale;
            sreg[cnt++] = a;
            mx = fmaxf(mx, a);
        }
        #pragma unroll
        for (int o = 16; o; o >>= 1) mx = fmaxf(mx, __shfl_xor_sync(0xffffffffu, mx, o));
        float sum = 0.f;
        for (int i = 0; i < cnt; i++) {
            sreg[i] = __expf(sreg[i] - mx);
            sum += sreg[i];
        }
        #pragma unroll
        for (int o = 16; o; o >>= 1) sum += __shfl_xor_sync(0xffffffffu, sum, o);
        float inv = 1.0f / sum;
        {
            int i = 0;
            for (int t = lane; t < SS; t += 32) mysc[t] = sreg[i++] * inv;
        }
        __syncwarp();

        float o0 = 0.f, o1 = 0.f;
        for (int t = 0; t < SS; t++) {
            float p = mysc[t];
            o0 += p * vs[t * 65 + lane];
            o1 += p * vs[t * 65 + lane + 32];
        }
        float* xr = x + ((size_t)(n * SS + s)) * DD + h * DH;
        xr[lane]      += o0;
        xr[lane + 32] += o1;
        __syncwarp();
    }
}

// ---------------- final softmax over 1000 classes ----------------
__global__ __launch_bounds__(256) void softmax_out(const float* __restrict__ logits,
                                                   float* __restrict__ out) {
    int n = blockIdx.x;
    int tid = threadIdx.x;
    const float* l = logits + (size_t)n * OUTC;
    __shared__ float sh[8];
    int lane = tid & 31, wp = tid >> 5;

    float mx = -1e30f;
    for (int c = tid; c < OUTC; c += 256) mx = fmaxf(mx, l[c]);
    #pragma unroll
    for (int o = 16; o; o >>= 1) mx = fmaxf(mx, __shfl_xor_sync(0xffffffffu, mx, o));
    if (lane == 0) sh[wp] = mx;
    __syncthreads();
    float gmx = sh[0];
    #pragma unroll
    for (int i = 1; i < 8; i++) gmx = fmaxf(gmx, sh[i]);
    __syncthreads();

    float sum = 0.f;
    for (int c = tid; c < OUTC; c += 256) sum += __expf(l[c] - gmx);
    #pragma unroll
    for (int o = 16; o; o >>= 1) sum += __shfl_xor_sync(0xffffffffu, sum, o);
    if (lane == 0) sh[wp] = sum;
    __syncthreads();
    float tot = 0.f;
    #pragma unroll
    for (int i = 0; i < 8; i++) tot += sh[i];
    float inv = 1.0f / tot;

    for (int c = tid; c < OUTC; c += 256) out[(size_t)n * OUTC + c] = __expf(l[c] - gmx) * inv;
}

// ---------------- launch ----------------
extern "C" void kernel_launch(void* const* d_in, const int* in_sizes, int n_in,
                              void* d_out, int out_size) {
    const float* images = (const float*)d_in[0];
    const float* Wm     = (const float*)d_in[1];
    const float* bm     = (const float*)d_in[2];
    const float* cls    = (const float*)d_in[3];
    const float* pos    = (const float*)d_in[4];
    const float* ln1w   = (const float*)d_in[5];
    const float* ln1b   = (const float*)d_in[6];
    const float* Wq     = (const float*)d_in[7];
    const float* bq     = (const float*)d_in[8];
    const float* Wk     = (const float*)d_in[9];
    const float* bk     = (const float*)d_in[10];
    const float* Wv     = (const float*)d_in[11];
    const float* bv     = (const float*)d_in[12];
    const float* ln2w   = (const float*)d_in[13];
    const float* ln2b   = (const float*)d_in[14];
    const float* W1     = (const float*)d_in[15];
    const float* b1     = (const float*)d_in[16];
    const float* W2     = (const float*)d_in[17];
    const float* b2     = (const float*)d_in[18];
    const float* Wout   = (const float*)d_in[19];
    const float* bout   = (const float*)d_in[20];
    float* out = (float*)d_out;

    float *p_x, *p_h, *p_q, *p_k, *p_v, *p_logits;
    cudaGetSymbolAddress((void**)&p_x, g_x);
    cudaGetSymbolAddress((void**)&p_h, g_h);
    cudaGetSymbolAddress((void**)&p_q, g_q);
    cudaGetSymbolAddress((void**)&p_k, g_k);
    cudaGetSymbolAddress((void**)&p_v, g_v);
    cudaGetSymbolAddress((void**)&p_logits, g_logits);

    __half *p_patch_hi, *p_patch_lo, *p_h_hi, *p_h_lo, *p_u_hi, *p_u_lo;
    __half *p_Wm, *p_W1, *p_W2;
    cudaGetSymbolAddress((void**)&p_patch_hi, g_patch_hi);
    cudaGetSymbolAddress((void**)&p_patch_lo, g_patch_lo);
    cudaGetSymbolAddress((void**)&p_h_hi, g_h_hi);
    cudaGetSymbolAddress((void**)&p_h_lo, g_h_lo);
    cudaGetSymbolAddress((void**)&p_u_hi, g_u_hi);
    cudaGetSymbolAddress((void**)&p_u_lo, g_u_lo);
    cudaGetSymbolAddress((void**)&p_Wm, g_Wm_f16);
    cudaGetSymbolAddress((void**)&p_W1, g_W1_f16);
    cudaGetSymbolAddress((void**)&p_W2, g_W2_f16);

    const int att_smem = ATT_SMEM_FLOATS * sizeof(float);
    cudaFuncSetAttribute(attn_kernel, cudaFuncAttributeMaxDynamicSharedMemorySize, att_smem);
    cudaFuncSetAttribute(gemm_f16x2, cudaFuncAttributeMaxDynamicSharedMemorySize, GEMM_SMEM_BYTES);
    cudaFuncSetAttribute(qkv_kernel, cudaFuncAttributeMaxDynamicSharedMemorySize, QKV_SMEM_BYTES);

    // ---- one-time weight conversions ----
    conv_f16<<<(DD * DD / 4 + 255) / 256, 256>>>(Wm, p_Wm, DD * DD);
    conv_f16<<<(LL * DD * FF / 4 + 255) / 256, 256>>>(W1, p_W1, LL * DD * FF);
    conv_f16<<<(LL * FF * DD / 4 + 255) / 256, 256>>>(W2, p_W2, LL * FF * DD);

    // ---- patch extraction + embed GEMM ----
    extract_patches<<<(PROWS * DD + 255) / 256, 256>>>(images, p_patch_hi, p_patch_lo);
    gemm_f16x2<<<dim3(DD / 128, (PROWS + 127) / 128), 256, GEMM_SMEM_BYTES>>>(
        p_patch_hi, p_patch_lo, DD, p_Wm, DD,
        p_h, nullptr, nullptr, DD, bm, PROWS, DD, DD, FLAG_BIAS);
    assemble<<<(ROWS * DD + 255) / 256, 256>>>(p_h, cls, pos, p_x);

    for (int l = 0; l < LL; l++) {
        ln_kernel<<<ROWS, 256>>>(p_x, ln1w + l * DD, ln1b + l * DD, p_h);

        qkv_kernel<<<dim3((ROWS + 63) / 64, HH), 256, QKV_SMEM_BYTES>>>(
            p_h,
            Wq + (size_t)l * HH * DH * DH, Wk + (size_t)l * HH * DH * DH, Wv + (size_t)l * HH * DH * DH,
            bq + (size_t)l * DD, bk + (size_t)l * DD, bv + (size_t)l * DD,
            p_q, p_k, p_v);

        attn_kernel<<<NN * HH, 256, att_smem>>>(p_q, p_k, p_v, p_x);

        ln_kernel_split<<<ROWS, 256>>>(p_x, ln2w + l * DD, ln2b + l * DD, p_h_hi, p_h_lo);

        gemm_f16x2<<<dim3(FF / 128, (ROWS + 127) / 128), 256, GEMM_SMEM_BYTES>>>(
            p_h_hi, p_h_lo, DD,
            p_W1 + (size_t)l * DD * FF, FF,
            nullptr, p_u_hi, p_u_lo, FF, b1 + (size_t)l * FF,
            ROWS, FF, DD, FLAG_BIAS | FLAG_GELU | FLAG_SPLIT);

        gemm_f16x2<<<dim3(DD / 128, (ROWS + 127) / 128), 256, GEMM_SMEM_BYTES>>>(
            p_u_hi, p_u_lo, FF,
            p_W2 + (size_t)l * FF * DD, DD,
            p_x, nullptr, nullptr, DD, b2 + (size_t)l * DD,
            ROWS, DD, FF, FLAG_BIAS | FLAG_RES);
    }

    // classification head: cls rows have stride SS*DD
    gemm64<<<dim3((OUTC + 63) / 64, 1, 1), 256>>>(
        p_x, (long long)SS * DD, 0,
        Wout, OUTC, 0,
        p_logits, OUTC, 0,
        bout, 0,
        NN, OUTC, DD, FLAG_BIAS);

    softmax_out<<<NN, 256>>>(p_logits, out);
}

// round 8
// speedup vs baseline: 2.5413x; 1.2432x over previous
#include <cuda_runtime.h>
#include <cuda_fp16.h>
#include <math.h>
#include <stdint.h>

// ---------------- problem constants ----------------
#define NN 32
#define CC 3
#define NP 14
#define PS 16
#define DD 768
#define HH 12
#define DH 64
#define SS 197
#define LL 8
#define FF 3072
#define OUTC 1000
#define NPATCH (NP*NP)    // 196
#define ROWS (NN*SS)      // 6304
#define PROWS (NN*NPATCH) // 6272

#define FLAG_BIAS 1
#define FLAG_GELU 2
#define FLAG_RES  4
#define FLAG_HALF_OUT 8

// ---------------- scratch (device globals; no runtime allocation) ----------------
__device__ float g_x[ROWS * DD];
__device__ float g_h[ROWS * DD];
__device__ float g_q[ROWS * DD];
__device__ float g_k[ROWS * DD];
__device__ float g_v[ROWS * DD];
__device__ float g_logits[NN * OUTC];

__device__ __half g_patch_f16[PROWS * DD];
__device__ __half g_h_f16[ROWS * DD];
__device__ __half g_u_f16[ROWS * FF];
__device__ __half g_Wm_f16[DD * DD];
__device__ __half g_W1_f16[LL * DD * FF];
__device__ __half g_W2_f16[LL * FF * DD];

__device__ __forceinline__ float gelu_exact(float x) {
    return 0.5f * x * (1.0f + erff(x * 0.70710678118654752f));
}

// ---------------- fp32 -> fp16 conversion ----------------
__global__ void conv_f16(const float* __restrict__ src, __half* __restrict__ dst, int n) {
    int i = (blockIdx.x * blockDim.x + threadIdx.x) * 4;
    if (i >= n) return;
    float4 v = *(const float4*)&src[i];
    __half2* d = (__half2*)&dst[i];
    d[0] = __floats2half2_rn(v.x, v.y);
    d[1] = __floats2half2_rn(v.z, v.w);
}

// ---------------- patch extraction (writes fp16) ----------------
__global__ void extract_patches(const float* __restrict__ images,
                                __half* __restrict__ P) {
    int idx = blockIdx.x * blockDim.x + threadIdx.x;
    if (idx >= PROWS * DD) return;
    int row = idx / DD;
    int col = idx - row * DD;
    int n = row / NPATCH;
    int p = row - n * NPATCH;
    int py = p / NP, px = p - py * NP;
    int c = col / (PS * PS);
    int r = col - c * PS * PS;
    int i = r / PS, j = r - i * PS;
    int H = NP * PS;
    float v = images[(((size_t)n * CC + c) * H + (py * PS + i)) * H + (px * PS + j)];
    P[idx] = __float2half(v);
}

// ---------------- assemble tokens + cls + pos ----------------
__global__ void assemble(const float* __restrict__ tok, const float* __restrict__ cls,
                         const float* __restrict__ pos, float* __restrict__ x) {
    int idx = blockIdx.x * blockDim.x + threadIdx.x;
    if (idx >= ROWS * DD) return;
    int row = idx / DD;
    int d = idx - row * DD;
    int n = row / SS;
    int s = row - n * SS;
    float v;
    if (s == 0) v = cls[d];
    else        v = tok[((size_t)n * NPATCH + (s - 1)) * DD + d];
    x[idx] = v + pos[(size_t)s * DD + d];
}

// ---------------- layernorm -> fp32 out ----------------
__global__ __launch_bounds__(256) void ln_kernel(const float* __restrict__ x,
                                                 const float* __restrict__ w,
                                                 const float* __restrict__ b,
                                                 float* __restrict__ out) {
    int row = blockIdx.x;
    int tid = threadIdx.x;
    const float* xr = x + (size_t)row * DD;
    float v0 = xr[tid], v1 = xr[tid + 256], v2 = xr[tid + 512];
    __shared__ float sh[8];
    int lane = tid & 31, wp = tid >> 5;

    float s = v0 + v1 + v2;
    #pragma unroll
    for (int o = 16; o; o >>= 1) s += __shfl_xor_sync(0xffffffffu, s, o);
    if (lane == 0) sh[wp] = s;
    __syncthreads();
    float total = 0.f;
    #pragma unroll
    for (int i = 0; i < 8; i++) total += sh[i];
    float mean = total * (1.0f / DD);
    __syncthreads();

    float d0 = v0 - mean, d1 = v1 - mean, d2 = v2 - mean;
    float sq = d0 * d0 + d1 * d1 + d2 * d2;
    #pragma unroll
    for (int o = 16; o; o >>= 1) sq += __shfl_xor_sync(0xffffffffu, sq, o);
    if (lane == 0) sh[wp] = sq;
    __syncthreads();
    float tot2 = 0.f;
    #pragma unroll
    for (int i = 0; i < 8; i++) tot2 += sh[i];
    float rstd = rsqrtf(tot2 * (1.0f / DD) + 1e-5f);

    float* orow = out + (size_t)row * DD;
    orow[tid]       = d0 * rstd * w[tid]       + b[tid];
    orow[tid + 256] = d1 * rstd * w[tid + 256] + b[tid + 256];
    orow[tid + 512] = d2 * rstd * w[tid + 512] + b[tid + 512];
}

// ---------------- layernorm -> fp16 out ----------------
__global__ __launch_bounds__(256) void ln_kernel_f16(const float* __restrict__ x,
                                                     const float* __restrict__ w,
                                                     const float* __restrict__ b,
                                                     __half* __restrict__ oh) {
    int row = blockIdx.x;
    int tid = threadIdx.x;
    const float* xr = x + (size_t)row * DD;
    float v0 = xr[tid], v1 = xr[tid + 256], v2 = xr[tid + 512];
    __shared__ float sh[8];
    int lane = tid & 31, wp = tid >> 5;

    float s = v0 + v1 + v2;
    #pragma unroll
    for (int o = 16; o; o >>= 1) s += __shfl_xor_sync(0xffffffffu, s, o);
    if (lane == 0) sh[wp] = s;
    __syncthreads();
    float total = 0.f;
    #pragma unroll
    for (int i = 0; i < 8; i++) total += sh[i];
    float mean = total * (1.0f / DD);
    __syncthreads();

    float d0 = v0 - mean, d1 = v1 - mean, d2 = v2 - mean;
    float sq = d0 * d0 + d1 * d1 + d2 * d2;
    #pragma unroll
    for (int o = 16; o; o >>= 1) sq += __shfl_xor_sync(0xffffffffu, sq, o);
    if (lane == 0) sh[wp] = sq;
    __syncthreads();
    float tot2 = 0.f;
    #pragma unroll
    for (int i = 0; i < 8; i++) tot2 += sh[i];
    float rstd = rsqrtf(tot2 * (1.0f / DD) + 1e-5f);

    size_t base = (size_t)row * DD;
    oh[base + tid]       = __float2half(d0 * rstd * w[tid]       + b[tid]);
    oh[base + tid + 256] = __float2half(d1 * rstd * w[tid + 256] + b[tid + 256]);
    oh[base + tid + 512] = __float2half(d2 * rstd * w[tid + 512] + b[tid + 512]);
}

// ================= fp16 tensor-core GEMM (3-stage cp.async, 2 CTAs/SM) ==========
#define BM 128
#define BN 128
#define BKK 32
#define ASTR 40
#define BSTR 136
#define ASZ (BM*ASTR)                 // 5120 halves
#define BSZ (BKK*BSTR)                // 4352 halves
#define STAGE_ELEMS (ASZ + BSZ)       // 9472 halves
#define STAGE_BYTES (STAGE_ELEMS*2)   // 18944
#define NSTAGE 3
#define GEMM_SMEM_BYTES (NSTAGE * STAGE_BYTES)  // 56832 -> two CTAs per SM

__device__ __forceinline__ void ldsm_x4(uint32_t addr, uint32_t* r) {
    asm volatile("ldmatrix.sync.aligned.m8n8.x4.shared.b16 {%0,%1,%2,%3}, [%4];\n"
                 : "=r"(r[0]), "=r"(r[1]), "=r"(r[2]), "=r"(r[3]) : "r"(addr));
}
__device__ __forceinline__ void ldsm_x4_t(uint32_t addr, uint32_t* r) {
    asm volatile("ldmatrix.sync.aligned.m8n8.x4.trans.shared.b16 {%0,%1,%2,%3}, [%4];\n"
                 : "=r"(r[0]), "=r"(r[1]), "=r"(r[2]), "=r"(r[3]) : "r"(addr));
}
__device__ __forceinline__ void mma_f16(float* c, const uint32_t* a, const uint32_t* b) {
    asm volatile("mma.sync.aligned.m16n8k16.row.col.f32.f16.f16.f32 "
                 "{%0,%1,%2,%3},{%4,%5,%6,%7},{%8,%9},{%0,%1,%2,%3};\n"
                 : "+f"(c[0]), "+f"(c[1]), "+f"(c[2]), "+f"(c[3])
                 : "r"(a[0]), "r"(a[1]), "r"(a[2]), "r"(a[3]), "r"(b[0]), "r"(b[1]));
}
__device__ __forceinline__ void cpa16(uint32_t dst, const void* src, int bytes) {
    asm volatile("cp.async.cg.shared.global [%0], [%1], 16, %2;\n"
                 :: "r"(dst), "l"(src), "r"(bytes));
}
__device__ __forceinline__ void cp_commit() {
    asm volatile("cp.async.commit_group;\n");
}
__device__ __forceinline__ void cp_wait2() {
    asm volatile("cp.async.wait_group 2;\n");
}

__device__ __forceinline__ void gemm_issue_stage(
    uint32_t smem_u32, int stage,
    const __half* __restrict__ A, int lda,
    const __half* __restrict__ B, int ldb,
    int M, int m0, int n0, int kb, int tid)
{
    uint32_t s = smem_u32 + (uint32_t)stage * STAGE_BYTES;
    uint32_t sA = s;
    uint32_t sB = s + ASZ * 2;
    #pragma unroll
    for (int i = 0; i < 2; i++) {
        int chunk = tid + 256 * i;
        int row = chunk >> 2;
        int c16 = chunk & 3;
        int gr = m0 + row;
        int bytes = (gr < M) ? 16 : 0;
        size_t goff = (size_t)gr * lda + kb + c16 * 8;
        uint32_t doff = (uint32_t)(row * ASTR + c16 * 8) * 2;
        cpa16(sA + doff, A + goff, bytes);
    }
    #pragma unroll
    for (int i = 0; i < 2; i++) {
        int chunk = tid + 256 * i;
        int row = chunk >> 4;
        int c16 = chunk & 15;
        size_t goff = (size_t)(kb + row) * ldb + n0 + c16 * 8;
        uint32_t doff = (uint32_t)(row * BSTR + c16 * 8) * 2;
        cpa16(sB + doff, B + goff, 16);
    }
}

__global__ __launch_bounds__(256, 2) void gemm_f16(
    const __half* __restrict__ A, int lda,
    const __half* __restrict__ B, int ldb,
    float* __restrict__ C, __half* __restrict__ Ch,
    int ldc, const float* __restrict__ bias,
    int M, int N, int K, int flags)
{
    extern __shared__ __half smbuf[];
    int tid = threadIdx.x;
    int m0 = blockIdx.y * BM;
    int n0 = blockIdx.x * BN;
    int warp = tid >> 5;
    int lane = tid & 31;
    int wm = (warp >> 2) * 64;
    int wn = (warp & 3) * 32;

    float acc[4][4][4];
    #pragma unroll
    for (int i = 0; i < 4; i++)
        #pragma unroll
        for (int j = 0; j < 4; j++)
            #pragma unroll
            for (int c = 0; c < 4; c++) acc[i][j][c] = 0.f;

    uint32_t smem_u32 = (uint32_t)__cvta_generic_to_shared(smbuf);
    const int nk = K / BKK;

    gemm_issue_stage(smem_u32, 0, A, lda, B, ldb, M, m0, n0, 0, tid);
    cp_commit();
    gemm_issue_stage(smem_u32, 1, A, lda, B, ldb, M, m0, n0, BKK, tid);
    cp_commit();
    gemm_issue_stage(smem_u32, 2, A, lda, B, ldb, M, m0, n0, 2 * BKK, tid);
    cp_commit();

    int st = 0;
    for (int kt = 0; kt < nk; kt++) {
        cp_wait2();
        __syncthreads();

        uint32_t s = smem_u32 + (uint32_t)st * STAGE_BYTES;
        uint32_t a_base = s;
        uint32_t b_base = s + ASZ * 2;

        #pragma unroll
        for (int ks = 0; ks < 2; ks++) {
            int kc = ks * 16;
            uint32_t bf[4][2];
            int brow = kc + ((lane >> 3) & 1) * 8 + (lane & 7);
            #pragma unroll
            for (int j = 0; j < 2; j++) {
                int bcol = wn + j * 16 + (lane >> 4) * 8;
                uint32_t off = (uint32_t)((brow * BSTR + bcol) * 2);
                uint32_t th[4];
                ldsm_x4_t(b_base + off, th);
                bf[2 * j][0] = th[0];
                bf[2 * j][1] = th[1];
                bf[2 * j + 1][0] = th[2];
                bf[2 * j + 1][1] = th[3];
            }
            int arow = lane & 15;
            int acol = kc + (lane >> 4) * 8;
            #pragma unroll
            for (int mi = 0; mi < 4; mi++) {
                uint32_t af[4];
                uint32_t off = (uint32_t)(((wm + mi * 16 + arow) * ASTR + acol) * 2);
                ldsm_x4(a_base + off, af);
                #pragma unroll
                for (int ni = 0; ni < 4; ni++) {
                    mma_f16(acc[mi][ni], af, bf[ni]);
                }
            }
        }

        __syncthreads();
        int nxt = kt + NSTAGE;
        if (nxt < nk) {
            gemm_issue_stage(smem_u32, st, A, lda, B, ldb, M, m0, n0, nxt * BKK, tid);
        }
        cp_commit();
        st = (st + 1 == NSTAGE) ? 0 : st + 1;
    }

    // ---- epilogue ----
    #pragma unroll
    for (int mi = 0; mi < 4; mi++) {
        int r0 = m0 + wm + mi * 16 + (lane >> 2);
        #pragma unroll
        for (int ni = 0; ni < 4; ni++) {
            int c0 = n0 + wn + ni * 8 + (lane & 3) * 2;
            #pragma unroll
            for (int half = 0; half < 2; half++) {
                int r = r0 + half * 8;
                if (r >= M) continue;
                #pragma unroll
                for (int e = 0; e < 2; e++) {
                    int c = c0 + e;
                    float val = acc[mi][ni][half * 2 + e];
                    if (flags & FLAG_BIAS) val += bias[c];
                    if (flags & FLAG_GELU) val = gelu_exact(val);
                    if (flags & FLAG_HALF_OUT) {
                        Ch[(size_t)r * ldc + c] = __float2half(val);
                    } else {
                        float* p = &C[(size_t)r * ldc + c];
                        if (flags & FLAG_RES) *p += val; else *p = val;
                    }
                }
            }
        }
    }
}

// ---------------- fused QKV: block per (m-block 64, head) ----------------
#define QKV_SMEM_BYTES ((64*68 + 3*64*68) * 4)

__global__ __launch_bounds__(256) void qkv_kernel(
    const float* __restrict__ h,
    const float* __restrict__ Wq, const float* __restrict__ Wk, const float* __restrict__ Wv,
    const float* __restrict__ bq, const float* __restrict__ bk, const float* __restrict__ bv,
    float* __restrict__ q, float* __restrict__ k, float* __restrict__ v)
{
    extern __shared__ float qsm[];
    float* As = qsm;
    float* Ws = qsm + 64 * 68;
    int m0 = blockIdx.x * 64;
    int head = blockIdx.y;
    int tid = threadIdx.x;

    for (int idx = tid; idx < 64 * 64; idx += 256) {
        int r = idx >> 6, c = idx & 63;
        float val = 0.f;
        if (m0 + r < ROWS) val = h[(size_t)(m0 + r) * DD + head * DH + c];
        As[c * 68 + r] = val;
    }
    const float* w0 = Wq + head * DH * DH;
    const float* w1 = Wk + head * DH * DH;
    const float* w2 = Wv + head * DH * DH;
    for (int idx = tid; idx < 64 * 64; idx += 256) {
        int d = idx >> 6, e = idx & 63;
        Ws[0 * 4352 + d * 68 + e] = w0[d * 64 + e];
        Ws[1 * 4352 + d * 68 + e] = w1[d * 64 + e];
        Ws[2 * 4352 + d * 68 + e] = w2[d * 64 + e];
    }
    __syncthreads();

    int tx = tid & 15, ty = tid >> 4;
    float aq[4][4], ak[4][4], av[4][4];
    #pragma unroll
    for (int i = 0; i < 4; i++)
        #pragma unroll
        for (int j = 0; j < 4; j++) { aq[i][j] = 0.f; ak[i][j] = 0.f; av[i][j] = 0.f; }

    for (int kk = 0; kk < 64; kk++) {
        float4 a = *(float4*)&As[kk * 68 + ty * 4];
        float4 b0 = *(float4*)&Ws[0 * 4352 + kk * 68 + tx * 4];
        float4 b1 = *(float4*)&Ws[1 * 4352 + kk * 68 + tx * 4];
        float4 b2 = *(float4*)&Ws[2 * 4352 + kk * 68 + tx * 4];
        float ar[4] = {a.x, a.y, a.z, a.w};
        float q4[4] = {b0.x, b0.y, b0.z, b0.w};
        float k4[4] = {b1.x, b1.y, b1.z, b1.w};
        float v4[4] = {b2.x, b2.y, b2.z, b2.w};
        #pragma unroll
        for (int i = 0; i < 4; i++) {
            #pragma unroll
            for (int j = 0; j < 4; j++) {
                aq[i][j] += ar[i] * q4[j];
                ak[i][j] += ar[i] * k4[j];
                av[i][j] += ar[i] * v4[j];
            }
        }
    }

    #pragma unroll
    for (int i = 0; i < 4; i++) {
        int r = m0 + ty * 4 + i;
        if (r >= ROWS) continue;
        size_t base = (size_t)r * DD + head * DH;
        #pragma unroll
        for (int j = 0; j < 4; j++) {
            int c = tx * 4 + j;
            q[base + c] = aq[i][j] + bq[head * DH + c];
            k[base + c] = ak[i][j] + bk[head * DH + c];
            v[base + c] = av[i][j] + bv[head * DH + c];
        }
    }
}

// ---------------- small GEMM (classification head) ----------------
__global__ __launch_bounds__(256) void gemm64(const float* __restrict__ A, long long lda, long long strideA,
                                              const float* __restrict__ B, int ldb, long long strideB,
                                              float* __restrict__ C, int ldc, long long strideC,
                                              const float* __restrict__ bias, long long strideBias,
                                              int M, int N, int K, int flags) {
    int bz = blockIdx.z;
    A += (size_t)bz * strideA;
    B += (size_t)bz * strideB;
    C += (size_t)bz * strideC;
    if (bias) bias += (size_t)bz * strideBias;

    __shared__ float As[16][64];
    __shared__ float Bs[16][68];
    int tid = threadIdx.x;
    int m0 = blockIdx.y * 64, n0 = blockIdx.x * 64;
    int arow = tid >> 2, akcol = (tid & 3) * 4;
    int brow = tid >> 4, bcol = (tid & 15) * 4;
    int tx = tid & 15, ty = tid >> 4;

    float acc[4][4];
    #pragma unroll
    for (int i = 0; i < 4; i++)
        #pragma unroll
        for (int j = 0; j < 4; j++) acc[i][j] = 0.f;

    for (int k0 = 0; k0 < K; k0 += 16) {
        float4 a4 = make_float4(0.f, 0.f, 0.f, 0.f);
        int gm = m0 + arow;
        if (gm < M) a4 = *(const float4*)&A[(size_t)gm * lda + k0 + akcol];
        As[akcol + 0][arow] = a4.x;
        As[akcol + 1][arow] = a4.y;
        As[akcol + 2][arow] = a4.z;
        As[akcol + 3][arow] = a4.w;

        float4 b4;
        int gn = n0 + bcol;
        const float* Brow = &B[(size_t)(k0 + brow) * ldb];
        if (gn + 3 < N) {
            b4 = *(const float4*)&Brow[gn];
        } else {
            b4.x = (gn + 0 < N) ? Brow[gn + 0] : 0.f;
            b4.y = (gn + 1 < N) ? Brow[gn + 1] : 0.f;
            b4.z = (gn + 2 < N) ? Brow[gn + 2] : 0.f;
            b4.w = (gn + 3 < N) ? Brow[gn + 3] : 0.f;
        }
        *(float4*)&Bs[brow][bcol] = b4;
        __syncthreads();

        #pragma unroll
        for (int kk = 0; kk < 16; kk++) {
            float4 a0 = *(float4*)&As[kk][ty * 4];
            float4 b0 = *(float4*)&Bs[kk][tx * 4];
            float ar[4] = {a0.x, a0.y, a0.z, a0.w};
            float br[4] = {b0.x, b0.y, b0.z, b0.w};
            #pragma unroll
            for (int i = 0; i < 4; i++)
                #pragma unroll
                for (int j = 0; j < 4; j++) acc[i][j] += ar[i] * br[j];
        }
        __syncthreads();
    }

    #pragma unroll
    for (int i = 0; i < 4; i++) {
        int r = m0 + ty * 4 + i;
        if (r >= M) continue;
        #pragma unroll
        for (int j = 0; j < 4; j++) {
            int c = n0 + tx * 4 + j;
            if (c >= N) continue;
            float val = acc[i][j];
            if (flags & FLAG_BIAS) val += bias[c];
            if (flags & FLAG_GELU) val = gelu_exact(val);
            float* p = &C[(size_t)r * ldc + c];
            if (flags & FLAG_RES) *p += val; else *p = val;
        }
    }
}

// ---------------- fused attention: block per (n, head) ----------------
#define ATT_SMEM_FLOATS (SS*65*2 + 8*200 + 8*64)

__global__ __launch_bounds__(256) void attn_kernel(const float* __restrict__ q,
                                                   const float* __restrict__ k,
                                                   const float* __restrict__ v,
                                                   float* __restrict__ x) {
    extern __shared__ float smf[];
    float* ks = smf;
    float* vs = smf + SS * 65;
    float* sc = vs + SS * 65;
    float* qs = sc + 8 * 200;

    int nh = blockIdx.x;
    int n = nh / HH, h = nh - n * HH;
    int tid = threadIdx.x;
    int wp = tid >> 5, lane = tid & 31;

    const float* kb = k + ((size_t)n * SS) * DD + h * DH;
    const float* vb = v + ((size_t)n * SS) * DD + h * DH;

    for (int idx = tid; idx < SS * 16; idx += 256) {
        int t = idx >> 4;
        int e4 = (idx & 15) * 4;
        float4 kk4 = *(const float4*)&kb[(size_t)t * DD + e4];
        float4 vv4 = *(const float4*)&vb[(size_t)t * DD + e4];
        int base = t * 65 + e4;
        ks[base + 0] = kk4.x; ks[base + 1] = kk4.y; ks[base + 2] = kk4.z; ks[base + 3] = kk4.w;
        vs[base + 0] = vv4.x; vs[base + 1] = vv4.y; vs[base + 2] = vv4.z; vs[base + 3] = vv4.w;
    }
    __syncthreads();

    const float scale = 0.125f;
    float* myqs = qs + wp * 64;
    float* mysc = sc + wp * 200;

    for (int s = wp; s < SS; s += 8) {
        const float* qrow = q + ((size_t)(n * SS + s)) * DD + h * DH;
        myqs[lane]      = qrow[lane];
        myqs[lane + 32] = qrow[lane + 32];
        __syncwarp();

        float qreg[DH];
        #pragma unroll
        for (int e = 0; e < DH; e++) qreg[e] = myqs[e];

        float sreg[7];
        float mx = -1e30f;
        int cnt = 0;
        for (int t = lane; t < SS; t += 32) {
            float a = 0.f;
            #pragma unroll
            for (int e = 0; e < DH; e++) a += qreg[e] * ks[t * 65 + e];
            a *= scale;
            sreg[cnt++] = a;
            mx = fmaxf(mx, a);
        }
        #pragma unroll
        for (int o = 16; o; o >>= 1) mx = fmaxf(mx, __shfl_xor_sync(0xffffffffu, mx, o));
        float sum = 0.f;
        for (int i = 0; i < cnt; i++) {
            sreg[i] = __expf(sreg[i] - mx);
            sum += sreg[i];
        }
        #pragma unroll
        for (int o = 16; o; o >>= 1) sum += __shfl_xor_sync(0xffffffffu, sum, o);
        float inv = 1.0f / sum;
        {
            int i = 0;
            for (int t = lane; t < SS; t += 32) mysc[t] = sreg[i++] * inv;
        }
        __syncwarp();

        float o0 = 0.f, o1 = 0.f;
        for (int t = 0; t < SS; t++) {
            float p = mysc[t];
            o0 += p * vs[t * 65 + lane];
            o1 += p * vs[t * 65 + lane + 32];
        }
        float* xr = x + ((size_t)(n * SS + s)) * DD + h * DH;
        xr[lane]      += o0;
        xr[lane + 32] += o1;
        __syncwarp();
    }
}

// ---------------- final softmax over 1000 classes ----------------
__global__ __launch_bounds__(256) void softmax_out(const float* __restrict__ logits,
                                                   float* __restrict__ out) {
    int n = blockIdx.x;
    int tid = threadIdx.x;
    const float* l = logits + (size_t)n * OUTC;
    __shared__ float sh[8];
    int lane = tid & 31, wp = tid >> 5;

    float mx = -1e30f;
    for (int c = tid; c < OUTC; c += 256) mx = fmaxf(mx, l[c]);
    #pragma unroll
    for (int o = 16; o; o >>= 1) mx = fmaxf(mx, __shfl_xor_sync(0xffffffffu, mx, o));
    if (lane == 0) sh[wp] = mx;
    __syncthreads();
    float gmx = sh[0];
    #pragma unroll
    for (int i = 1; i < 8; i++) gmx = fmaxf(gmx, sh[i]);
    __syncthreads();

    float sum = 0.f;
    for (int c = tid; c < OUTC; c += 256) sum += __expf(l[c] - gmx);
    #pragma unroll
    for (int o = 16; o; o >>= 1) sum += __shfl_xor_sync(0xffffffffu, sum, o);
    if (lane == 0) sh[wp] = sum;
    __syncthreads();
    float tot = 0.f;
    #pragma unroll
    for (int i = 0; i < 8; i++) tot += sh[i];
    float inv = 1.0f / tot;

    for (int c = tid; c < OUTC; c += 256) out[(size_t)n * OUTC + c] = __expf(l[c] - gmx) * inv;
}

// ---------------- launch ----------------
extern "C" void kernel_launch(void* const* d_in, const int* in_sizes, int n_in,
                              void* d_out, int out_size) {
    const float* images = (const float*)d_in[0];
    const float* Wm     = (const float*)d_in[1];
    const float* bm     = (const float*)d_in[2];
    const float* cls    = (const float*)d_in[3];
    const float* pos    = (const float*)d_in[4];
    const float* ln1w   = (const float*)d_in[5];
    const float* ln1b   = (const float*)d_in[6];
    const float* Wq     = (const float*)d_in[7];
    const float* bq     = (const float*)d_in[8];
    const float* Wk     = (const float*)d_in[9];
    const float* bk     = (const float*)d_in[10];
    const float* Wv     = (const float*)d_in[11];
    const float* bv     = (const float*)d_in[12];
    const float* ln2w   = (const float*)d_in[13];
    const float* ln2b   = (const float*)d_in[14];
    const float* W1     = (const float*)d_in[15];
    const float* b1     = (const float*)d_in[16];
    const float* W2     = (const float*)d_in[17];
    const float* b2     = (const float*)d_in[18];
    const float* Wout   = (const float*)d_in[19];
    const float* bout   = (const float*)d_in[20];
    float* out = (float*)d_out;

    float *p_x, *p_h, *p_q, *p_k, *p_v, *p_logits;
    cudaGetSymbolAddress((void**)&p_x, g_x);
    cudaGetSymbolAddress((void**)&p_h, g_h);
    cudaGetSymbolAddress((void**)&p_q, g_q);
    cudaGetSymbolAddress((void**)&p_k, g_k);
    cudaGetSymbolAddress((void**)&p_v, g_v);
    cudaGetSymbolAddress((void**)&p_logits, g_logits);

    __half *p_patch, *p_hh, *p_u, *p_Wm, *p_W1, *p_W2;
    cudaGetSymbolAddress((void**)&p_patch, g_patch_f16);
    cudaGetSymbolAddress((void**)&p_hh, g_h_f16);
    cudaGetSymbolAddress((void**)&p_u, g_u_f16);
    cudaGetSymbolAddress((void**)&p_Wm, g_Wm_f16);
    cudaGetSymbolAddress((void**)&p_W1, g_W1_f16);
    cudaGetSymbolAddress((void**)&p_W2, g_W2_f16);

    const int att_smem = ATT_SMEM_FLOATS * sizeof(float);
    cudaFuncSetAttribute(attn_kernel, cudaFuncAttributeMaxDynamicSharedMemorySize, att_smem);
    cudaFuncSetAttribute(gemm_f16, cudaFuncAttributeMaxDynamicSharedMemorySize, GEMM_SMEM_BYTES);
    cudaFuncSetAttribute(qkv_kernel, cudaFuncAttributeMaxDynamicSharedMemorySize, QKV_SMEM_BYTES);

    // ---- one-time weight conversions ----
    conv_f16<<<(DD * DD / 4 + 255) / 256, 256>>>(Wm, p_Wm, DD * DD);
    conv_f16<<<(LL * DD * FF / 4 + 255) / 256, 256>>>(W1, p_W1, LL * DD * FF);
    conv_f16<<<(LL * FF * DD / 4 + 255) / 256, 256>>>(W2, p_W2, LL * FF * DD);

    // ---- patch extraction + embed GEMM ----
    extract_patches<<<(PROWS * DD + 255) / 256, 256>>>(images, p_patch);
    gemm_f16<<<dim3(DD / 128, (PROWS + 127) / 128), 256, GEMM_SMEM_BYTES>>>(
        p_patch, DD, p_Wm, DD,
        p_h, nullptr, DD, bm, PROWS, DD, DD, FLAG_BIAS);
    assemble<<<(ROWS * DD + 255) / 256, 256>>>(p_h, cls, pos, p_x);

    for (int l = 0; l < LL; l++) {
        ln_kernel<<<ROWS, 256>>>(p_x, ln1w + l * DD, ln1b + l * DD, p_h);

        qkv_kernel<<<dim3((ROWS + 63) / 64, HH), 256, QKV_SMEM_BYTES>>>(
            p_h,
            Wq + (size_t)l * HH * DH * DH, Wk + (size_t)l * HH * DH * DH, Wv + (size_t)l * HH * DH * DH,
            bq + (size_t)l * DD, bk + (size_t)l * DD, bv + (size_t)l * DD,
            p_q, p_k, p_v);

        attn_kernel<<<NN * HH, 256, att_smem>>>(p_q, p_k, p_v, p_x);

        ln_kernel_f16<<<ROWS, 256>>>(p_x, ln2w + l * DD, ln2b + l * DD, p_hh);

        gemm_f16<<<dim3(FF / 128, (ROWS + 127) / 128), 256, GEMM_SMEM_BYTES>>>(
            p_hh, DD,
            p_W1 + (size_t)l * DD * FF, FF,
            nullptr, p_u, FF, b1 + (size_t)l * FF,
            ROWS, FF, DD, FLAG_BIAS | FLAG_GELU | FLAG_HALF_OUT);

        gemm_f16<<<dim3(DD / 128, (ROWS + 127) / 128), 256, GEMM_SMEM_BYTES>>>(
            p_u, FF,
            p_W2 + (size_t)l * FF * DD, DD,
            p_x, nullptr, DD, b2 + (size_t)l * DD,
            ROWS, DD, FF, FLAG_BIAS | FLAG_RES);
    }

    // classification head: cls rows have stride SS*DD
    gemm64<<<dim3((OUTC + 63) / 64, 1, 1), 256>>>(
        p_x, (long long)SS * DD, 0,
        Wout, OUTC, 0,
        p_logits, OUTC, 0,
        bout, 0,
        NN, OUTC, DD, FLAG_BIAS);

    softmax_out<<<NN, 256>>>(p_logits, out);
}

// round 9
// speedup vs baseline: 4.5077x; 1.7738x over previous
#include <cuda_runtime.h>
#include <cuda_fp16.h>
#include <math.h>
#include <stdint.h>

// ---------------- problem constants ----------------
#define NN 32
#define CC 3
#define NP 14
#define PS 16
#define DD 768
#define HH 12
#define DH 64
#define SS 197
#define LL 8
#define FF 3072
#define OUTC 1000
#define NPATCH (NP*NP)    // 196
#define ROWS (NN*SS)      // 6304
#define PROWS (NN*NPATCH) // 6272

#define FLAG_BIAS 1
#define FLAG_GELU 2
#define FLAG_RES  4
#define FLAG_HALF_OUT 8

// ---------------- scratch (device globals; no runtime allocation) ----------------
__device__ float g_x[ROWS * DD];
__device__ float g_h[ROWS * DD];
__device__ float g_logits[NN * OUTC];

__device__ __half g_q_f16[ROWS * DD];
__device__ __half g_k_f16[ROWS * DD];
__device__ __half g_v_f16[ROWS * DD];
__device__ __half g_patch_f16[PROWS * DD];
__device__ __half g_h_f16[ROWS * DD];
__device__ __half g_u_f16[ROWS * FF];
__device__ __half g_Wm_f16[DD * DD];
__device__ __half g_W1_f16[LL * DD * FF];
__device__ __half g_W2_f16[LL * FF * DD];

__device__ __forceinline__ float gelu_exact(float x) {
    return 0.5f * x * (1.0f + erff(x * 0.70710678118654752f));
}

// ---------------- fp32 -> fp16 conversion ----------------
__global__ void conv_f16(const float* __restrict__ src, __half* __restrict__ dst, int n) {
    int i = (blockIdx.x * blockDim.x + threadIdx.x) * 4;
    if (i >= n) return;
    float4 v = *(const float4*)&src[i];
    __half2* d = (__half2*)&dst[i];
    d[0] = __floats2half2_rn(v.x, v.y);
    d[1] = __floats2half2_rn(v.z, v.w);
}

// ---------------- patch extraction (writes fp16) ----------------
__global__ void extract_patches(const float* __restrict__ images,
                                __half* __restrict__ P) {
    int idx = blockIdx.x * blockDim.x + threadIdx.x;
    if (idx >= PROWS * DD) return;
    int row = idx / DD;
    int col = idx - row * DD;
    int n = row / NPATCH;
    int p = row - n * NPATCH;
    int py = p / NP, px = p - py * NP;
    int c = col / (PS * PS);
    int r = col - c * PS * PS;
    int i = r / PS, j = r - i * PS;
    int H = NP * PS;
    float v = images[(((size_t)n * CC + c) * H + (py * PS + i)) * H + (px * PS + j)];
    P[idx] = __float2half(v);
}

// ---------------- assemble tokens + cls + pos ----------------
__global__ void assemble(const float* __restrict__ tok, const float* __restrict__ cls,
                         const float* __restrict__ pos, float* __restrict__ x) {
    int idx = blockIdx.x * blockDim.x + threadIdx.x;
    if (idx >= ROWS * DD) return;
    int row = idx / DD;
    int d = idx - row * DD;
    int n = row / SS;
    int s = row - n * SS;
    float v;
    if (s == 0) v = cls[d];
    else        v = tok[((size_t)n * NPATCH + (s - 1)) * DD + d];
    x[idx] = v + pos[(size_t)s * DD + d];
}

// ---------------- layernorm -> fp32 out ----------------
__global__ __launch_bounds__(256) void ln_kernel(const float* __restrict__ x,
                                                 const float* __restrict__ w,
                                                 const float* __restrict__ b,
                                                 float* __restrict__ out) {
    int row = blockIdx.x;
    int tid = threadIdx.x;
    const float* xr = x + (size_t)row * DD;
    float v0 = xr[tid], v1 = xr[tid + 256], v2 = xr[tid + 512];
    __shared__ float sh[8];
    int lane = tid & 31, wp = tid >> 5;

    float s = v0 + v1 + v2;
    #pragma unroll
    for (int o = 16; o; o >>= 1) s += __shfl_xor_sync(0xffffffffu, s, o);
    if (lane == 0) sh[wp] = s;
    __syncthreads();
    float total = 0.f;
    #pragma unroll
    for (int i = 0; i < 8; i++) total += sh[i];
    float mean = total * (1.0f / DD);
    __syncthreads();

    float d0 = v0 - mean, d1 = v1 - mean, d2 = v2 - mean;
    float sq = d0 * d0 + d1 * d1 + d2 * d2;
    #pragma unroll
    for (int o = 16; o; o >>= 1) sq += __shfl_xor_sync(0xffffffffu, sq, o);
    if (lane == 0) sh[wp] = sq;
    __syncthreads();
    float tot2 = 0.f;
    #pragma unroll
    for (int i = 0; i < 8; i++) tot2 += sh[i];
    float rstd = rsqrtf(tot2 * (1.0f / DD) + 1e-5f);

    float* orow = out + (size_t)row * DD;
    orow[tid]       = d0 * rstd * w[tid]       + b[tid];
    orow[tid + 256] = d1 * rstd * w[tid + 256] + b[tid + 256];
    orow[tid + 512] = d2 * rstd * w[tid + 512] + b[tid + 512];
}

// ---------------- layernorm -> fp16 out ----------------
__global__ __launch_bounds__(256) void ln_kernel_f16(const float* __restrict__ x,
                                                     const float* __restrict__ w,
                                                     const float* __restrict__ b,
                                                     __half* __restrict__ oh) {
    int row = blockIdx.x;
    int tid = threadIdx.x;
    const float* xr = x + (size_t)row * DD;
    float v0 = xr[tid], v1 = xr[tid + 256], v2 = xr[tid + 512];
    __shared__ float sh[8];
    int lane = tid & 31, wp = tid >> 5;

    float s = v0 + v1 + v2;
    #pragma unroll
    for (int o = 16; o; o >>= 1) s += __shfl_xor_sync(0xffffffffu, s, o);
    if (lane == 0) sh[wp] = s;
    __syncthreads();
    float total = 0.f;
    #pragma unroll
    for (int i = 0; i < 8; i++) total += sh[i];
    float mean = total * (1.0f / DD);
    __syncthreads();

    float d0 = v0 - mean, d1 = v1 - mean, d2 = v2 - mean;
    float sq = d0 * d0 + d1 * d1 + d2 * d2;
    #pragma unroll
    for (int o = 16; o; o >>= 1) sq += __shfl_xor_sync(0xffffffffu, sq, o);
    if (lane == 0) sh[wp] = sq;
    __syncthreads();
    float tot2 = 0.f;
    #pragma unroll
    for (int i = 0; i < 8; i++) tot2 += sh[i];
    float rstd = rsqrtf(tot2 * (1.0f / DD) + 1e-5f);

    size_t base = (size_t)row * DD;
    oh[base + tid]       = __float2half(d0 * rstd * w[tid]       + b[tid]);
    oh[base + tid + 256] = __float2half(d1 * rstd * w[tid + 256] + b[tid + 256]);
    oh[base + tid + 512] = __float2half(d2 * rstd * w[tid + 512] + b[tid + 512]);
}

// ================= fp16 tensor-core GEMM (3-stage cp.async, 2 CTAs/SM) ==========
#define BM 128
#define BN 128
#define BKK 32
#define ASTR 40
#define BSTR 136
#define ASZ (BM*ASTR)
#define BSZ (BKK*BSTR)
#define STAGE_ELEMS (ASZ + BSZ)
#define STAGE_BYTES (STAGE_ELEMS*2)
#define NSTAGE 3
#define GEMM_SMEM_BYTES (NSTAGE * STAGE_BYTES)

__device__ __forceinline__ void ldsm_x4(uint32_t addr, uint32_t* r) {
    asm volatile("ldmatrix.sync.aligned.m8n8.x4.shared.b16 {%0,%1,%2,%3}, [%4];\n"
                 : "=r"(r[0]), "=r"(r[1]), "=r"(r[2]), "=r"(r[3]) : "r"(addr));
}
__device__ __forceinline__ void ldsm_x4_t(uint32_t addr, uint32_t* r) {
    asm volatile("ldmatrix.sync.aligned.m8n8.x4.trans.shared.b16 {%0,%1,%2,%3}, [%4];\n"
                 : "=r"(r[0]), "=r"(r[1]), "=r"(r[2]), "=r"(r[3]) : "r"(addr));
}
__device__ __forceinline__ void mma_f16(float* c, const uint32_t* a, const uint32_t* b) {
    asm volatile("mma.sync.aligned.m16n8k16.row.col.f32.f16.f16.f32 "
                 "{%0,%1,%2,%3},{%4,%5,%6,%7},{%8,%9},{%0,%1,%2,%3};\n"
                 : "+f"(c[0]), "+f"(c[1]), "+f"(c[2]), "+f"(c[3])
                 : "r"(a[0]), "r"(a[1]), "r"(a[2]), "r"(a[3]), "r"(b[0]), "r"(b[1]));
}
__device__ __forceinline__ void cpa16(uint32_t dst, const void* src, int bytes) {
    asm volatile("cp.async.cg.shared.global [%0], [%1], 16, %2;\n"
                 :: "r"(dst), "l"(src), "r"(bytes));
}
__device__ __forceinline__ void cp_commit() {
    asm volatile("cp.async.commit_group;\n");
}
__device__ __forceinline__ void cp_wait2() {
    asm volatile("cp.async.wait_group 2;\n");
}

__device__ __forceinline__ void gemm_issue_stage(
    uint32_t smem_u32, int stage,
    const __half* __restrict__ A, int lda,
    const __half* __restrict__ B, int ldb,
    int M, int m0, int n0, int kb, int tid)
{
    uint32_t s = smem_u32 + (uint32_t)stage * STAGE_BYTES;
    uint32_t sA = s;
    uint32_t sB = s + ASZ * 2;
    #pragma unroll
    for (int i = 0; i < 2; i++) {
        int chunk = tid + 256 * i;
        int row = chunk >> 2;
        int c16 = chunk & 3;
        int gr = m0 + row;
        int bytes = (gr < M) ? 16 : 0;
        size_t goff = (size_t)gr * lda + kb + c16 * 8;
        uint32_t doff = (uint32_t)(row * ASTR + c16 * 8) * 2;
        cpa16(sA + doff, A + goff, bytes);
    }
    #pragma unroll
    for (int i = 0; i < 2; i++) {
        int chunk = tid + 256 * i;
        int row = chunk >> 4;
        int c16 = chunk & 15;
        size_t goff = (size_t)(kb + row) * ldb + n0 + c16 * 8;
        uint32_t doff = (uint32_t)(row * BSTR + c16 * 8) * 2;
        cpa16(sB + doff, B + goff, 16);
    }
}

__global__ __launch_bounds__(256, 2) void gemm_f16(
    const __half* __restrict__ A, int lda,
    const __half* __restrict__ B, int ldb,
    float* __restrict__ C, __half* __restrict__ Ch,
    int ldc, const float* __restrict__ bias,
    int M, int N, int K, int flags)
{
    extern __shared__ __half smbuf[];
    int tid = threadIdx.x;
    int m0 = blockIdx.y * BM;
    int n0 = blockIdx.x * BN;
    int warp = tid >> 5;
    int lane = tid & 31;
    int wm = (warp >> 2) * 64;
    int wn = (warp & 3) * 32;

    float acc[4][4][4];
    #pragma unroll
    for (int i = 0; i < 4; i++)
        #pragma unroll
        for (int j = 0; j < 4; j++)
            #pragma unroll
            for (int c = 0; c < 4; c++) acc[i][j][c] = 0.f;

    uint32_t smem_u32 = (uint32_t)__cvta_generic_to_shared(smbuf);
    const int nk = K / BKK;

    gemm_issue_stage(smem_u32, 0, A, lda, B, ldb, M, m0, n0, 0, tid);
    cp_commit();
    gemm_issue_stage(smem_u32, 1, A, lda, B, ldb, M, m0, n0, BKK, tid);
    cp_commit();
    gemm_issue_stage(smem_u32, 2, A, lda, B, ldb, M, m0, n0, 2 * BKK, tid);
    cp_commit();

    int st = 0;
    for (int kt = 0; kt < nk; kt++) {
        cp_wait2();
        __syncthreads();

        uint32_t s = smem_u32 + (uint32_t)st * STAGE_BYTES;
        uint32_t a_base = s;
        uint32_t b_base = s + ASZ * 2;

        #pragma unroll
        for (int ks = 0; ks < 2; ks++) {
            int kc = ks * 16;
            uint32_t bf[4][2];
            int brow = kc + ((lane >> 3) & 1) * 8 + (lane & 7);
            #pragma unroll
            for (int j = 0; j < 2; j++) {
                int bcol = wn + j * 16 + (lane >> 4) * 8;
                uint32_t off = (uint32_t)((brow * BSTR + bcol) * 2);
                uint32_t th[4];
                ldsm_x4_t(b_base + off, th);
                bf[2 * j][0] = th[0];
                bf[2 * j][1] = th[1];
                bf[2 * j + 1][0] = th[2];
                bf[2 * j + 1][1] = th[3];
            }
            int arow = lane & 15;
            int acol = kc + (lane >> 4) * 8;
            #pragma unroll
            for (int mi = 0; mi < 4; mi++) {
                uint32_t af[4];
                uint32_t off = (uint32_t)(((wm + mi * 16 + arow) * ASTR + acol) * 2);
                ldsm_x4(a_base + off, af);
                #pragma unroll
                for (int ni = 0; ni < 4; ni++) {
                    mma_f16(acc[mi][ni], af, bf[ni]);
                }
            }
        }

        __syncthreads();
        int nxt = kt + NSTAGE;
        if (nxt < nk) {
            gemm_issue_stage(smem_u32, st, A, lda, B, ldb, M, m0, n0, nxt * BKK, tid);
        }
        cp_commit();
        st = (st + 1 == NSTAGE) ? 0 : st + 1;
    }

    // ---- epilogue ----
    #pragma unroll
    for (int mi = 0; mi < 4; mi++) {
        int r0 = m0 + wm + mi * 16 + (lane >> 2);
        #pragma unroll
        for (int ni = 0; ni < 4; ni++) {
            int c0 = n0 + wn + ni * 8 + (lane & 3) * 2;
            #pragma unroll
            for (int half = 0; half < 2; half++) {
                int r = r0 + half * 8;
                if (r >= M) continue;
                #pragma unroll
                for (int e = 0; e < 2; e++) {
                    int c = c0 + e;
                    float val = acc[mi][ni][half * 2 + e];
                    if (flags & FLAG_BIAS) val += bias[c];
                    if (flags & FLAG_GELU) val = gelu_exact(val);
                    if (flags & FLAG_HALF_OUT) {
                        Ch[(size_t)r * ldc + c] = __float2half(val);
                    } else {
                        float* p = &C[(size_t)r * ldc + c];
                        if (flags & FLAG_RES) *p += val; else *p = val;
                    }
                }
            }
        }
    }
}

// ---------------- fused QKV: block per (m-block 64, head), fp16 outputs ----------
#define QKV_SMEM_BYTES ((64*68 + 3*64*68) * 4)

__global__ __launch_bounds__(256) void qkv_kernel(
    const float* __restrict__ h,
    const float* __restrict__ Wq, const float* __restrict__ Wk, const float* __restrict__ Wv,
    const float* __restrict__ bq, const float* __restrict__ bk, const float* __restrict__ bv,
    __half* __restrict__ q, __half* __restrict__ k, __half* __restrict__ v)
{
    extern __shared__ float qsm[];
    float* As = qsm;
    float* Ws = qsm + 64 * 68;
    int m0 = blockIdx.x * 64;
    int head = blockIdx.y;
    int tid = threadIdx.x;

    for (int idx = tid; idx < 64 * 64; idx += 256) {
        int r = idx >> 6, c = idx & 63;
        float val = 0.f;
        if (m0 + r < ROWS) val = h[(size_t)(m0 + r) * DD + head * DH + c];
        As[c * 68 + r] = val;
    }
    const float* w0 = Wq + head * DH * DH;
    const float* w1 = Wk + head * DH * DH;
    const float* w2 = Wv + head * DH * DH;
    for (int idx = tid; idx < 64 * 64; idx += 256) {
        int d = idx >> 6, e = idx & 63;
        Ws[0 * 4352 + d * 68 + e] = w0[d * 64 + e];
        Ws[1 * 4352 + d * 68 + e] = w1[d * 64 + e];
        Ws[2 * 4352 + d * 68 + e] = w2[d * 64 + e];
    }
    __syncthreads();

    int tx = tid & 15, ty = tid >> 4;
    float aq[4][4], ak[4][4], av[4][4];
    #pragma unroll
    for (int i = 0; i < 4; i++)
        #pragma unroll
        for (int j = 0; j < 4; j++) { aq[i][j] = 0.f; ak[i][j] = 0.f; av[i][j] = 0.f; }

    for (int kk = 0; kk < 64; kk++) {
        float4 a = *(float4*)&As[kk * 68 + ty * 4];
        float4 b0 = *(float4*)&Ws[0 * 4352 + kk * 68 + tx * 4];
        float4 b1 = *(float4*)&Ws[1 * 4352 + kk * 68 + tx * 4];
        float4 b2 = *(float4*)&Ws[2 * 4352 + kk * 68 + tx * 4];
        float ar[4] = {a.x, a.y, a.z, a.w};
        float q4[4] = {b0.x, b0.y, b0.z, b0.w};
        float k4[4] = {b1.x, b1.y, b1.z, b1.w};
        float v4[4] = {b2.x, b2.y, b2.z, b2.w};
        #pragma unroll
        for (int i = 0; i < 4; i++) {
            #pragma unroll
            for (int j = 0; j < 4; j++) {
                aq[i][j] += ar[i] * q4[j];
                ak[i][j] += ar[i] * k4[j];
                av[i][j] += ar[i] * v4[j];
            }
        }
    }

    #pragma unroll
    for (int i = 0; i < 4; i++) {
        int r = m0 + ty * 4 + i;
        if (r >= ROWS) continue;
        size_t base = (size_t)r * DD + head * DH;
        #pragma unroll
        for (int j = 0; j < 4; j++) {
            int c = tx * 4 + j;
            q[base + c] = __float2half(aq[i][j] + bq[head * DH + c]);
            k[base + c] = __float2half(ak[i][j] + bk[head * DH + c]);
            v[base + c] = __float2half(av[i][j] + bv[head * DH + c]);
        }
    }
}

// ================= tensor-core attention: block per (n, head) =================
// Q/K/V fp16 in smem [208][72]; scores + softmax + PV all in registers.
#define AT_ROWS 208
#define AT_STR 72
#define ATT_SMEM_BYTES (3 * AT_ROWS * AT_STR * 2)   // 89856

__global__ __launch_bounds__(256, 1) void attn_mma(
    const __half* __restrict__ q, const __half* __restrict__ k,
    const __half* __restrict__ v, float* __restrict__ x)
{
    extern __shared__ __half atsm[];
    __half* Qs = atsm;
    __half* Ks = Qs + AT_ROWS * AT_STR;
    __half* Vs = Ks + AT_ROWS * AT_STR;

    int nh = blockIdx.x;
    int n = nh / HH, h = nh - n * HH;
    int tid = threadIdx.x;
    int warp = tid >> 5, lane = tid & 31;

    // load q/k/v head slices into smem (zero-pad rows 197..207)
    for (int idx = tid; idx < AT_ROWS * 8; idx += 256) {
        int t = idx >> 3;
        int c8 = (idx & 7) * 8;
        uint4 qv = make_uint4(0, 0, 0, 0);
        uint4 kv = qv, vv = qv;
        if (t < SS) {
            size_t g = ((size_t)(n * SS + t)) * DD + h * DH + c8;
            qv = *(const uint4*)(q + g);
            kv = *(const uint4*)(k + g);
            vv = *(const uint4*)(v + g);
        }
        int so = t * AT_STR + c8;
        *(uint4*)(Qs + so) = qv;
        *(uint4*)(Ks + so) = kv;
        *(uint4*)(Vs + so) = vv;
    }
    __syncthreads();

    uint32_t q_base = (uint32_t)__cvta_generic_to_shared(Qs);
    uint32_t k_base = (uint32_t)__cvta_generic_to_shared(Ks);
    uint32_t v_base = (uint32_t)__cvta_generic_to_shared(Vs);
    const float scale = 0.125f;

    // 13 m16 tiles over 208 rows; warp w handles tiles w and w+8
    #pragma unroll 1
    for (int pass = 0; pass < 2; pass++) {
        int mt = warp + pass * 8;
        if (mt >= 13) break;
        int s0 = mt * 16;

        // ---- scores: c[26 n8-tiles][4] ----
        float c[26][4];
        #pragma unroll
        for (int j = 0; j < 26; j++) {
            c[j][0] = 0.f; c[j][1] = 0.f; c[j][2] = 0.f; c[j][3] = 0.f;
        }
        #pragma unroll
        for (int ks = 0; ks < 4; ks++) {
            int kc = ks * 16;
            uint32_t a[4];
            uint32_t aoff = (uint32_t)(((s0 + (lane & 15)) * AT_STR + kc + (lane >> 4) * 8) * 2);
            ldsm_x4(q_base + aoff, a);
            #pragma unroll
            for (int j = 0; j < 13; j++) {
                uint32_t b[4];
                int nrow = j * 16 + (lane >> 4) * 8 + (lane & 7);
                int ncol = kc + ((lane >> 3) & 1) * 8;
                ldsm_x4(k_base + (uint32_t)((nrow * AT_STR + ncol) * 2), b);
                mma_f16(c[2 * j],     a, b);
                mma_f16(c[2 * j + 1], a, b + 2);
            }
        }

        // ---- scale + mask + softmax (rows r=lane>>2 and r+8) ----
        float mx0 = -1e30f, mx1 = -1e30f;
        #pragma unroll
        for (int j = 0; j < 26; j++) {
            int tcol = j * 8 + (lane & 3) * 2;
            #pragma unroll
            for (int e = 0; e < 2; e++) {
                float s0v = c[j][e] * scale;
                float s1v = c[j][2 + e] * scale;
                if (tcol + e >= SS) { s0v = -1e30f; s1v = -1e30f; }
                c[j][e] = s0v;
                c[j][2 + e] = s1v;
                mx0 = fmaxf(mx0, s0v);
                mx1 = fmaxf(mx1, s1v);
            }
        }
        mx0 = fmaxf(mx0, __shfl_xor_sync(0xffffffffu, mx0, 1));
        mx0 = fmaxf(mx0, __shfl_xor_sync(0xffffffffu, mx0, 2));
        mx1 = fmaxf(mx1, __shfl_xor_sync(0xffffffffu, mx1, 1));
        mx1 = fmaxf(mx1, __shfl_xor_sync(0xffffffffu, mx1, 2));

        float sum0 = 0.f, sum1 = 0.f;
        #pragma unroll
        for (int j = 0; j < 26; j++) {
            #pragma unroll
            for (int e = 0; e < 2; e++) {
                float p0 = __expf(c[j][e] - mx0);
                float p1 = __expf(c[j][2 + e] - mx1);
                c[j][e] = p0;
                c[j][2 + e] = p1;
                sum0 += p0;
                sum1 += p1;
            }
        }
        sum0 += __shfl_xor_sync(0xffffffffu, sum0, 1);
        sum0 += __shfl_xor_sync(0xffffffffu, sum0, 2);
        sum1 += __shfl_xor_sync(0xffffffffu, sum1, 1);
        sum1 += __shfl_xor_sync(0xffffffffu, sum1, 2);
        float inv0 = 1.0f / sum0;
        float inv1 = 1.0f / sum1;

        // ---- PV: o[8 n8-tiles][4], A = P (register repack), B = V (trans ldsm) ----
        float o[8][4];
        #pragma unroll
        for (int j = 0; j < 8; j++) {
            o[j][0] = 0.f; o[j][1] = 0.f; o[j][2] = 0.f; o[j][3] = 0.f;
        }
        #pragma unroll
        for (int j = 0; j < 13; j++) {
            uint32_t a[4];
            __half2 h0 = __floats2half2_rn(c[2 * j][0] * inv0, c[2 * j][1] * inv0);
            __half2 h1 = __floats2half2_rn(c[2 * j][2] * inv1, c[2 * j][3] * inv1);
            __half2 h2 = __floats2half2_rn(c[2 * j + 1][0] * inv0, c[2 * j + 1][1] * inv0);
            __half2 h3 = __floats2half2_rn(c[2 * j + 1][2] * inv1, c[2 * j + 1][3] * inv1);
            a[0] = *(uint32_t*)&h0;
            a[1] = *(uint32_t*)&h1;
            a[2] = *(uint32_t*)&h2;
            a[3] = *(uint32_t*)&h3;
            int brow = j * 16 + ((lane >> 3) & 1) * 8 + (lane & 7);
            #pragma unroll
            for (int nj = 0; nj < 4; nj++) {
                uint32_t b[4];
                int bcol = nj * 16 + (lane >> 4) * 8;
                ldsm_x4_t(v_base + (uint32_t)((brow * AT_STR + bcol) * 2), b);
                mma_f16(o[2 * nj],     a, b);
                mma_f16(o[2 * nj + 1], a, b + 2);
            }
        }

        // ---- write with residual add ----
        int rloc = lane >> 2;
        #pragma unroll
        for (int half = 0; half < 2; half++) {
            int srow = s0 + rloc + half * 8;
            if (srow >= SS) continue;
            float* xr = x + ((size_t)(n * SS + srow)) * DD + h * DH;
            #pragma unroll
            for (int nj = 0; nj < 8; nj++) {
                int col = nj * 8 + (lane & 3) * 2;
                xr[col]     += o[nj][half * 2];
                xr[col + 1] += o[nj][half * 2 + 1];
            }
        }
    }
}

// ---------------- small GEMM (classification head) ----------------
__global__ __launch_bounds__(256) void gemm64(const float* __restrict__ A, long long lda, long long strideA,
                                              const float* __restrict__ B, int ldb, long long strideB,
                                              float* __restrict__ C, int ldc, long long strideC,
                                              const float* __restrict__ bias, long long strideBias,
                                              int M, int N, int K, int flags) {
    int bz = blockIdx.z;
    A += (size_t)bz * strideA;
    B += (size_t)bz * strideB;
    C += (size_t)bz * strideC;
    if (bias) bias += (size_t)bz * strideBias;

    __shared__ float As[16][64];
    __shared__ float Bs[16][68];
    int tid = threadIdx.x;
    int m0 = blockIdx.y * 64, n0 = blockIdx.x * 64;
    int arow = tid >> 2, akcol = (tid & 3) * 4;
    int brow = tid >> 4, bcol = (tid & 15) * 4;
    int tx = tid & 15, ty = tid >> 4;

    float acc[4][4];
    #pragma unroll
    for (int i = 0; i < 4; i++)
        #pragma unroll
        for (int j = 0; j < 4; j++) acc[i][j] = 0.f;

    for (int k0 = 0; k0 < K; k0 += 16) {
        float4 a4 = make_float4(0.f, 0.f, 0.f, 0.f);
        int gm = m0 + arow;
        if (gm < M) a4 = *(const float4*)&A[(size_t)gm * lda + k0 + akcol];
        As[akcol + 0][arow] = a4.x;
        As[akcol + 1][arow] = a4.y;
        As[akcol + 2][arow] = a4.z;
        As[akcol + 3][arow] = a4.w;

        float4 b4;
        int gn = n0 + bcol;
        const float* Brow = &B[(size_t)(k0 + brow) * ldb];
        if (gn + 3 < N) {
            b4 = *(const float4*)&Brow[gn];
        } else {
            b4.x = (gn + 0 < N) ? Brow[gn + 0] : 0.f;
            b4.y = (gn + 1 < N) ? Brow[gn + 1] : 0.f;
            b4.z = (gn + 2 < N) ? Brow[gn + 2] : 0.f;
            b4.w = (gn + 3 < N) ? Brow[gn + 3] : 0.f;
        }
        *(float4*)&Bs[brow][bcol] = b4;
        __syncthreads();

        #pragma unroll
        for (int kk = 0; kk < 16; kk++) {
            float4 a0 = *(float4*)&As[kk][ty * 4];
            float4 b0 = *(float4*)&Bs[kk][tx * 4];
            float ar[4] = {a0.x, a0.y, a0.z, a0.w};
            float br[4] = {b0.x, b0.y, b0.z, b0.w};
            #pragma unroll
            for (int i = 0; i < 4; i++)
                #pragma unroll
                for (int j = 0; j < 4; j++) acc[i][j] += ar[i] * br[j];
        }
        __syncthreads();
    }

    #pragma unroll
    for (int i = 0; i < 4; i++) {
        int r = m0 + ty * 4 + i;
        if (r >= M) continue;
        #pragma unroll
        for (int j = 0; j < 4; j++) {
            int c = n0 + tx * 4 + j;
            if (c >= N) continue;
            float val = acc[i][j];
            if (flags & FLAG_BIAS) val += bias[c];
            if (flags & FLAG_GELU) val = gelu_exact(val);
            float* p = &C[(size_t)r * ldc + c];
            if (flags & FLAG_RES) *p += val; else *p = val;
        }
    }
}

// ---------------- final softmax over 1000 classes ----------------
__global__ __launch_bounds__(256) void softmax_out(const float* __restrict__ logits,
                                                   float* __restrict__ out) {
    int n = blockIdx.x;
    int tid = threadIdx.x;
    const float* l = logits + (size_t)n * OUTC;
    __shared__ float sh[8];
    int lane = tid & 31, wp = tid >> 5;

    float mx = -1e30f;
    for (int c = tid; c < OUTC; c += 256) mx = fmaxf(mx, l[c]);
    #pragma unroll
    for (int o = 16; o; o >>= 1) mx = fmaxf(mx, __shfl_xor_sync(0xffffffffu, mx, o));
    if (lane == 0) sh[wp] = mx;
    __syncthreads();
    float gmx = sh[0];
    #pragma unroll
    for (int i = 1; i < 8; i++) gmx = fmaxf(gmx, sh[i]);
    __syncthreads();

    float sum = 0.f;
    for (int c = tid; c < OUTC; c += 256) sum += __expf(l[c] - gmx);
    #pragma unroll
    for (int o = 16; o; o >>= 1) sum += __shfl_xor_sync(0xffffffffu, sum, o);
    if (lane == 0) sh[wp] = sum;
    __syncthreads();
    float tot = 0.f;
    #pragma unroll
    for (int i = 0; i < 8; i++) tot += sh[i];
    float inv = 1.0f / tot;

    for (int c = tid; c < OUTC; c += 256) out[(size_t)n * OUTC + c] = __expf(l[c] - gmx) * inv;
}

// ---------------- launch ----------------
extern "C" void kernel_launch(void* const* d_in, const int* in_sizes, int n_in,
                              void* d_out, int out_size) {
    const float* images = (const float*)d_in[0];
    const float* Wm     = (const float*)d_in[1];
    const float* bm     = (const float*)d_in[2];
    const float* cls    = (const float*)d_in[3];
    const float* pos    = (const float*)d_in[4];
    const float* ln1w   = (const float*)d_in[5];
    const float* ln1b   = (const float*)d_in[6];
    const float* Wq     = (const float*)d_in[7];
    const float* bq     = (const float*)d_in[8];
    const float* Wk     = (const float*)d_in[9];
    const float* bk     = (const float*)d_in[10];
    const float* Wv     = (const float*)d_in[11];
    const float* bv     = (const float*)d_in[12];
    const float* ln2w   = (const float*)d_in[13];
    const float* ln2b   = (const float*)d_in[14];
    const float* W1     = (const float*)d_in[15];
    const float* b1     = (const float*)d_in[16];
    const float* W2     = (const float*)d_in[17];
    const float* b2     = (const float*)d_in[18];
    const float* Wout   = (const float*)d_in[19];
    const float* bout   = (const float*)d_in[20];
    float* out = (float*)d_out;

    float *p_x, *p_h, *p_logits;
    cudaGetSymbolAddress((void**)&p_x, g_x);
    cudaGetSymbolAddress((void**)&p_h, g_h);
    cudaGetSymbolAddress((void**)&p_logits, g_logits);

    __half *p_q, *p_k, *p_v, *p_patch, *p_hh, *p_u, *p_Wm, *p_W1, *p_W2;
    cudaGetSymbolAddress((void**)&p_q, g_q_f16);
    cudaGetSymbolAddress((void**)&p_k, g_k_f16);
    cudaGetSymbolAddress((void**)&p_v, g_v_f16);
    cudaGetSymbolAddress((void**)&p_patch, g_patch_f16);
    cudaGetSymbolAddress((void**)&p_hh, g_h_f16);
    cudaGetSymbolAddress((void**)&p_u, g_u_f16);
    cudaGetSymbolAddress((void**)&p_Wm, g_Wm_f16);
    cudaGetSymbolAddress((void**)&p_W1, g_W1_f16);
    cudaGetSymbolAddress((void**)&p_W2, g_W2_f16);

    cudaFuncSetAttribute(attn_mma, cudaFuncAttributeMaxDynamicSharedMemorySize, ATT_SMEM_BYTES);
    cudaFuncSetAttribute(gemm_f16, cudaFuncAttributeMaxDynamicSharedMemorySize, GEMM_SMEM_BYTES);
    cudaFuncSetAttribute(qkv_kernel, cudaFuncAttributeMaxDynamicSharedMemorySize, QKV_SMEM_BYTES);

    // ---- one-time weight conversions ----
    conv_f16<<<(DD * DD / 4 + 255) / 256, 256>>>(Wm, p_Wm, DD * DD);
    conv_f16<<<(LL * DD * FF / 4 + 255) / 256, 256>>>(W1, p_W1, LL * DD * FF);
    conv_f16<<<(LL * FF * DD / 4 + 255) / 256, 256>>>(W2, p_W2, LL * FF * DD);

    // ---- patch extraction + embed GEMM ----
    extract_patches<<<(PROWS * DD + 255) / 256, 256>>>(images, p_patch);
    gemm_f16<<<dim3(DD / 128, (PROWS + 127) / 128), 256, GEMM_SMEM_BYTES>>>(
        p_patch, DD, p_Wm, DD,
        p_h, nullptr, DD, bm, PROWS, DD, DD, FLAG_BIAS);
    assemble<<<(ROWS * DD + 255) / 256, 256>>>(p_h, cls, pos, p_x);

    for (int l = 0; l < LL; l++) {
        ln_kernel<<<ROWS, 256>>>(p_x, ln1w + l * DD, ln1b + l * DD, p_h);

        qkv_kernel<<<dim3((ROWS + 63) / 64, HH), 256, QKV_SMEM_BYTES>>>(
            p_h,
            Wq + (size_t)l * HH * DH * DH, Wk + (size_t)l * HH * DH * DH, Wv + (size_t)l * HH * DH * DH,
            bq + (size_t)l * DD, bk + (size_t)l * DD, bv + (size_t)l * DD,
            p_q, p_k, p_v);

        attn_mma<<<NN * HH, 256, ATT_SMEM_BYTES>>>(p_q, p_k, p_v, p_x);

        ln_kernel_f16<<<ROWS, 256>>>(p_x, ln2w + l * DD, ln2b + l * DD, p_hh);

        gemm_f16<<<dim3(FF / 128, (ROWS + 127) / 128), 256, GEMM_SMEM_BYTES>>>(
            p_hh, DD,
            p_W1 + (size_t)l * DD * FF, FF,
            nullptr, p_u, FF, b1 + (size_t)l * FF,
            ROWS, FF, DD, FLAG_BIAS | FLAG_GELU | FLAG_HALF_OUT);

        gemm_f16<<<dim3(DD / 128, (ROWS + 127) / 128), 256, GEMM_SMEM_BYTES>>>(
            p_u, FF,
            p_W2 + (size_t)l * FF * DD, DD,
            p_x, nullptr, DD, b2 + (size_t)l * DD,
            ROWS, DD, FF, FLAG_BIAS | FLAG_RES);
    }

    // classification head: cls rows have stride SS*DD
    gemm64<<<dim3((OUTC + 63) / 64, 1, 1), 256>>>(
        p_x, (long long)SS * DD, 0,
        Wout, OUTC, 0,
        p_logits, OUTC, 0,
        bout, 0,
        NN, OUTC, DD, FLAG_BIAS);

    softmax_out<<<NN, 256>>>(p_logits, out);
}

// round 10
// speedup vs baseline: 4.6480x; 1.0311x over previous
#include <cuda_runtime.h>
#include <cuda_fp16.h>
#include <math.h>
#include <stdint.h>

// ---------------- problem constants ----------------
#define NN 32
#define CC 3
#define NP 14
#define PS 16
#define DD 768
#define HH 12
#define DH 64
#define SS 197
#define LL 8
#define FF 3072
#define OUTC 1000
#define NPATCH (NP*NP)    // 196
#define ROWS (NN*SS)      // 6304
#define PROWS (NN*NPATCH) // 6272

#define FLAG_BIAS 1
#define FLAG_GELU 2
#define FLAG_RES  4
#define FLAG_HALF_OUT 8

// ---------------- scratch (device globals; no runtime allocation) ----------------
__device__ float g_x[ROWS * DD];
__device__ float g_h[ROWS * DD];
__device__ float g_logits[NN * OUTC];

__device__ __half g_q_f16[ROWS * DD];
__device__ __half g_k_f16[ROWS * DD];
__device__ __half g_v_f16[ROWS * DD];
__device__ __half g_patch_f16[PROWS * DD];
__device__ __half g_h_f16[ROWS * DD];
__device__ __half g_u_f16[ROWS * FF];
__device__ __half g_Wm_f16[DD * DD];
__device__ __half g_W1_f16[LL * DD * FF];
__device__ __half g_W2_f16[LL * FF * DD];

__device__ __forceinline__ float gelu_exact(float x) {
    return 0.5f * x * (1.0f + erff(x * 0.70710678118654752f));
}

// ---------------- fp32 -> fp16 conversion ----------------
__global__ void conv_f16(const float* __restrict__ src, __half* __restrict__ dst, int n) {
    int i = (blockIdx.x * blockDim.x + threadIdx.x) * 4;
    if (i >= n) return;
    float4 v = *(const float4*)&src[i];
    __half2* d = (__half2*)&dst[i];
    d[0] = __floats2half2_rn(v.x, v.y);
    d[1] = __floats2half2_rn(v.z, v.w);
}

// ---------------- patch extraction (writes fp16) ----------------
__global__ void extract_patches(const float* __restrict__ images,
                                __half* __restrict__ P) {
    int idx = blockIdx.x * blockDim.x + threadIdx.x;
    if (idx >= PROWS * DD) return;
    int row = idx / DD;
    int col = idx - row * DD;
    int n = row / NPATCH;
    int p = row - n * NPATCH;
    int py = p / NP, px = p - py * NP;
    int c = col / (PS * PS);
    int r = col - c * PS * PS;
    int i = r / PS, j = r - i * PS;
    int H = NP * PS;
    float v = images[(((size_t)n * CC + c) * H + (py * PS + i)) * H + (px * PS + j)];
    P[idx] = __float2half(v);
}

// ---------------- assemble tokens + cls + pos ----------------
__global__ void assemble(const float* __restrict__ tok, const float* __restrict__ cls,
                         const float* __restrict__ pos, float* __restrict__ x) {
    int idx = blockIdx.x * blockDim.x + threadIdx.x;
    if (idx >= ROWS * DD) return;
    int row = idx / DD;
    int d = idx - row * DD;
    int n = row / SS;
    int s = row - n * SS;
    float v;
    if (s == 0) v = cls[d];
    else        v = tok[((size_t)n * NPATCH + (s - 1)) * DD + d];
    x[idx] = v + pos[(size_t)s * DD + d];
}

// ---------------- layernorm -> fp16 out ----------------
__global__ __launch_bounds__(256) void ln_kernel_f16(const float* __restrict__ x,
                                                     const float* __restrict__ w,
                                                     const float* __restrict__ b,
                                                     __half* __restrict__ oh) {
    int row = blockIdx.x;
    int tid = threadIdx.x;
    const float* xr = x + (size_t)row * DD;
    float v0 = xr[tid], v1 = xr[tid + 256], v2 = xr[tid + 512];
    __shared__ float sh[8];
    int lane = tid & 31, wp = tid >> 5;

    float s = v0 + v1 + v2;
    #pragma unroll
    for (int o = 16; o; o >>= 1) s += __shfl_xor_sync(0xffffffffu, s, o);
    if (lane == 0) sh[wp] = s;
    __syncthreads();
    float total = 0.f;
    #pragma unroll
    for (int i = 0; i < 8; i++) total += sh[i];
    float mean = total * (1.0f / DD);
    __syncthreads();

    float d0 = v0 - mean, d1 = v1 - mean, d2 = v2 - mean;
    float sq = d0 * d0 + d1 * d1 + d2 * d2;
    #pragma unroll
    for (int o = 16; o; o >>= 1) sq += __shfl_xor_sync(0xffffffffu, sq, o);
    if (lane == 0) sh[wp] = sq;
    __syncthreads();
    float tot2 = 0.f;
    #pragma unroll
    for (int i = 0; i < 8; i++) tot2 += sh[i];
    float rstd = rsqrtf(tot2 * (1.0f / DD) + 1e-5f);

    size_t base = (size_t)row * DD;
    oh[base + tid]       = __float2half(d0 * rstd * w[tid]       + b[tid]);
    oh[base + tid + 256] = __float2half(d1 * rstd * w[tid + 256] + b[tid + 256]);
    oh[base + tid + 512] = __float2half(d2 * rstd * w[tid + 512] + b[tid + 512]);
}

// ================= fp16 tensor-core GEMM (3-stage, single barrier/iter) ==========
#define BM 128
#define BN 128
#define BKK 32
#define ASTR 40
#define BSTR 136
#define ASZ (BM*ASTR)
#define BSZ (BKK*BSTR)
#define STAGE_ELEMS (ASZ + BSZ)
#define STAGE_BYTES (STAGE_ELEMS*2)
#define NSTAGE 3
#define GEMM_SMEM_BYTES (NSTAGE * STAGE_BYTES)

__device__ __forceinline__ void ldsm_x4(uint32_t addr, uint32_t* r) {
    asm volatile("ldmatrix.sync.aligned.m8n8.x4.shared.b16 {%0,%1,%2,%3}, [%4];\n"
                 : "=r"(r[0]), "=r"(r[1]), "=r"(r[2]), "=r"(r[3]) : "r"(addr));
}
__device__ __forceinline__ void ldsm_x4_t(uint32_t addr, uint32_t* r) {
    asm volatile("ldmatrix.sync.aligned.m8n8.x4.trans.shared.b16 {%0,%1,%2,%3}, [%4];\n"
                 : "=r"(r[0]), "=r"(r[1]), "=r"(r[2]), "=r"(r[3]) : "r"(addr));
}
__device__ __forceinline__ void mma_f16(float* c, const uint32_t* a, const uint32_t* b) {
    asm volatile("mma.sync.aligned.m16n8k16.row.col.f32.f16.f16.f32 "
                 "{%0,%1,%2,%3},{%4,%5,%6,%7},{%8,%9},{%0,%1,%2,%3};\n"
                 : "+f"(c[0]), "+f"(c[1]), "+f"(c[2]), "+f"(c[3])
                 : "r"(a[0]), "r"(a[1]), "r"(a[2]), "r"(a[3]), "r"(b[0]), "r"(b[1]));
}
__device__ __forceinline__ void cpa16(uint32_t dst, const void* src, int bytes) {
    asm volatile("cp.async.cg.shared.global [%0], [%1], 16, %2;\n"
                 :: "r"(dst), "l"(src), "r"(bytes));
}
__device__ __forceinline__ void cp_commit() {
    asm volatile("cp.async.commit_group;\n");
}
__device__ __forceinline__ void cp_wait1() {
    asm volatile("cp.async.wait_group 1;\n");
}

__device__ __forceinline__ void gemm_issue_stage(
    uint32_t smem_u32, int stage,
    const __half* __restrict__ A, int lda,
    const __half* __restrict__ B, int ldb,
    int M, int m0, int n0, int kb, int tid)
{
    uint32_t s = smem_u32 + (uint32_t)stage * STAGE_BYTES;
    uint32_t sA = s;
    uint32_t sB = s + ASZ * 2;
    #pragma unroll
    for (int i = 0; i < 2; i++) {
        int chunk = tid + 256 * i;
        int row = chunk >> 2;
        int c16 = chunk & 3;
        int gr = m0 + row;
        int bytes = (gr < M) ? 16 : 0;
        size_t goff = (size_t)gr * lda + kb + c16 * 8;
        uint32_t doff = (uint32_t)(row * ASTR + c16 * 8) * 2;
        cpa16(sA + doff, A + goff, bytes);
    }
    #pragma unroll
    for (int i = 0; i < 2; i++) {
        int chunk = tid + 256 * i;
        int row = chunk >> 4;
        int c16 = chunk & 15;
        size_t goff = (size_t)(kb + row) * ldb + n0 + c16 * 8;
        uint32_t doff = (uint32_t)(row * BSTR + c16 * 8) * 2;
        cpa16(sB + doff, B + goff, 16);
    }
}

__global__ __launch_bounds__(256, 2) void gemm_f16(
    const __half* __restrict__ A, int lda,
    const __half* __restrict__ B, int ldb,
    float* __restrict__ C, __half* __restrict__ Ch,
    int ldc, const float* __restrict__ bias,
    int M, int N, int K, int flags)
{
    extern __shared__ __half smbuf[];
    int tid = threadIdx.x;
    int m0 = blockIdx.y * BM;
    int n0 = blockIdx.x * BN;
    int warp = tid >> 5;
    int lane = tid & 31;
    int wm = (warp >> 2) * 64;
    int wn = (warp & 3) * 32;

    float acc[4][4][4];
    #pragma unroll
    for (int i = 0; i < 4; i++)
        #pragma unroll
        for (int j = 0; j < 4; j++)
            #pragma unroll
            for (int c = 0; c < 4; c++) acc[i][j][c] = 0.f;

    uint32_t smem_u32 = (uint32_t)__cvta_generic_to_shared(smbuf);
    const int nk = K / BKK;

    gemm_issue_stage(smem_u32, 0, A, lda, B, ldb, M, m0, n0, 0, tid);
    cp_commit();
    gemm_issue_stage(smem_u32, 1, A, lda, B, ldb, M, m0, n0, BKK, tid);
    cp_commit();

    int st = 0;
    for (int kt = 0; kt < nk; kt++) {
        cp_wait1();
        __syncthreads();

        // prefetch stage kt+2 into buffer (st+2)%3 (finished by all warps at the barrier)
        int nxt = kt + 2;
        if (nxt < nk) {
            int nst = st + 2;
            if (nst >= NSTAGE) nst -= NSTAGE;
            gemm_issue_stage(smem_u32, nst, A, lda, B, ldb, M, m0, n0, nxt * BKK, tid);
        }
        cp_commit();

        uint32_t s = smem_u32 + (uint32_t)st * STAGE_BYTES;
        uint32_t a_base = s;
        uint32_t b_base = s + ASZ * 2;

        #pragma unroll
        for (int ks = 0; ks < 2; ks++) {
            int kc = ks * 16;
            uint32_t bf[4][2];
            int brow = kc + ((lane >> 3) & 1) * 8 + (lane & 7);
            #pragma unroll
            for (int j = 0; j < 2; j++) {
                int bcol = wn + j * 16 + (lane >> 4) * 8;
                uint32_t off = (uint32_t)((brow * BSTR + bcol) * 2);
                uint32_t th[4];
                ldsm_x4_t(b_base + off, th);
                bf[2 * j][0] = th[0];
                bf[2 * j][1] = th[1];
                bf[2 * j + 1][0] = th[2];
                bf[2 * j + 1][1] = th[3];
            }
            int arow = lane & 15;
            int acol = kc + (lane >> 4) * 8;
            #pragma unroll
            for (int mi = 0; mi < 4; mi++) {
                uint32_t af[4];
                uint32_t off = (uint32_t)(((wm + mi * 16 + arow) * ASTR + acol) * 2);
                ldsm_x4(a_base + off, af);
                #pragma unroll
                for (int ni = 0; ni < 4; ni++) {
                    mma_f16(acc[mi][ni], af, bf[ni]);
                }
            }
        }

        st = (st + 1 == NSTAGE) ? 0 : st + 1;
    }

    // ---- epilogue ----
    #pragma unroll
    for (int mi = 0; mi < 4; mi++) {
        int r0 = m0 + wm + mi * 16 + (lane >> 2);
        #pragma unroll
        for (int ni = 0; ni < 4; ni++) {
            int c0 = n0 + wn + ni * 8 + (lane & 3) * 2;
            #pragma unroll
            for (int half = 0; half < 2; half++) {
                int r = r0 + half * 8;
                if (r >= M) continue;
                #pragma unroll
                for (int e = 0; e < 2; e++) {
                    int c = c0 + e;
                    float val = acc[mi][ni][half * 2 + e];
                    if (flags & FLAG_BIAS) val += bias[c];
                    if (flags & FLAG_GELU) val = gelu_exact(val);
                    if (flags & FLAG_HALF_OUT) {
                        Ch[(size_t)r * ldc + c] = __float2half(val);
                    } else {
                        float* p = &C[(size_t)r * ldc + c];
                        if (flags & FLAG_RES) *p += val; else *p = val;
                    }
                }
            }
        }
    }
}

// ================= tensor-core QKV: block per (m128 tile, head) =================
// A = h_f16 slice [128][72], W = 3 x [64][72] fp16 (converted in-kernel).
#define QKV_ASTR 72
#define QKV_SMEM_BYTES ((128 * QKV_ASTR + 3 * 64 * QKV_ASTR) * 2)   // 46080

__global__ __launch_bounds__(256) void qkv_mma(
    const __half* __restrict__ h,
    const float* __restrict__ Wq, const float* __restrict__ Wk, const float* __restrict__ Wv,
    const float* __restrict__ bq, const float* __restrict__ bk, const float* __restrict__ bv,
    __half* __restrict__ q, __half* __restrict__ k, __half* __restrict__ v)
{
    extern __shared__ __half qsm[];
    __half* As = qsm;                       // [128][72]
    __half* Ws = qsm + 128 * QKV_ASTR;      // [3][64][72]
    int m0 = blockIdx.x * 128;
    int head = blockIdx.y;
    int tid = threadIdx.x;
    int warp = tid >> 5, lane = tid & 31;

    // load A (h slice), zero-pad out-of-range rows
    #pragma unroll
    for (int i = 0; i < 4; i++) {
        int idx = tid + i * 256;
        int row = idx >> 3;
        int c8 = (idx & 7) * 8;
        uint4 val = make_uint4(0, 0, 0, 0);
        int gr = m0 + row;
        if (gr < ROWS) val = *(const uint4*)(h + (size_t)gr * DD + head * DH + c8);
        *(uint4*)(As + row * QKV_ASTR + c8) = val;
    }
    // load + convert weights (3 x 64 x 64 fp32 -> fp16)
    const float* wsrc[3] = {Wq + head * DH * DH, Wk + head * DH * DH, Wv + head * DH * DH};
    for (int idx = tid; idx < 3 * DH * DH; idx += 256) {
        int mat = idx >> 12;
        int rem = idx & 4095;
        int d = rem >> 6, e = rem & 63;
        Ws[mat * 64 * QKV_ASTR + d * QKV_ASTR + e] = __float2half(wsrc[mat][d * 64 + e]);
    }
    __syncthreads();

    uint32_t a_base = (uint32_t)__cvta_generic_to_shared(As);
    uint32_t w_base = (uint32_t)__cvta_generic_to_shared(Ws);

    float acc[3][8][4];
    #pragma unroll
    for (int m = 0; m < 3; m++)
        #pragma unroll
        for (int j = 0; j < 8; j++) {
            acc[m][j][0] = 0.f; acc[m][j][1] = 0.f;
            acc[m][j][2] = 0.f; acc[m][j][3] = 0.f;
        }

    #pragma unroll
    for (int ks = 0; ks < 4; ks++) {
        int kc = ks * 16;
        uint32_t af[4];
        uint32_t aoff = (uint32_t)(((warp * 16 + (lane & 15)) * QKV_ASTR + kc + (lane >> 4) * 8) * 2);
        ldsm_x4(a_base + aoff, af);
        int brow = kc + ((lane >> 3) & 1) * 8 + (lane & 7);
        #pragma unroll
        for (int mat = 0; mat < 3; mat++) {
            #pragma unroll
            for (int j = 0; j < 4; j++) {
                int bcol = j * 16 + (lane >> 4) * 8;
                uint32_t th[4];
                ldsm_x4_t(w_base + (uint32_t)((mat * 64 * QKV_ASTR + brow * QKV_ASTR + bcol) * 2), th);
                mma_f16(acc[mat][2 * j],     af, th);
                mma_f16(acc[mat][2 * j + 1], af, th + 2);
            }
        }
    }

    // store with bias, fp16
    const float* bsrc[3] = {bq + head * DH, bk + head * DH, bv + head * DH};
    __half* osrc[3] = {q, k, v};
    #pragma unroll
    for (int mat = 0; mat < 3; mat++) {
        #pragma unroll
        for (int half = 0; half < 2; half++) {
            int r = m0 + warp * 16 + (lane >> 2) + half * 8;
            if (r >= ROWS) continue;
            __half* orow = osrc[mat] + (size_t)r * DD + head * DH;
            #pragma unroll
            for (int nj = 0; nj < 8; nj++) {
                int col = nj * 8 + (lane & 3) * 2;
                orow[col]     = __float2half(acc[mat][nj][half * 2]     + bsrc[mat][col]);
                orow[col + 1] = __float2half(acc[mat][nj][half * 2 + 1] + bsrc[mat][col + 1]);
            }
        }
    }
}

// ================= tensor-core attention: block per (n, head) =================
#define AT_ROWS 208
#define AT_STR 72
#define ATT_SMEM_BYTES (3 * AT_ROWS * AT_STR * 2)   // 89856

__global__ __launch_bounds__(256, 1) void attn_mma(
    const __half* __restrict__ q, const __half* __restrict__ k,
    const __half* __restrict__ v, float* __restrict__ x)
{
    extern __shared__ __half atsm[];
    __half* Qs = atsm;
    __half* Ks = Qs + AT_ROWS * AT_STR;
    __half* Vs = Ks + AT_ROWS * AT_STR;

    int nh = blockIdx.x;
    int n = nh / HH, h = nh - n * HH;
    int tid = threadIdx.x;
    int warp = tid >> 5, lane = tid & 31;

    for (int idx = tid; idx < AT_ROWS * 8; idx += 256) {
        int t = idx >> 3;
        int c8 = (idx & 7) * 8;
        uint4 qv = make_uint4(0, 0, 0, 0);
        uint4 kv = qv, vv = qv;
        if (t < SS) {
            size_t g = ((size_t)(n * SS + t)) * DD + h * DH + c8;
            qv = *(const uint4*)(q + g);
            kv = *(const uint4*)(k + g);
            vv = *(const uint4*)(v + g);
        }
        int so = t * AT_STR + c8;
        *(uint4*)(Qs + so) = qv;
        *(uint4*)(Ks + so) = kv;
        *(uint4*)(Vs + so) = vv;
    }
    __syncthreads();

    uint32_t q_base = (uint32_t)__cvta_generic_to_shared(Qs);
    uint32_t k_base = (uint32_t)__cvta_generic_to_shared(Ks);
    uint32_t v_base = (uint32_t)__cvta_generic_to_shared(Vs);
    const float scale = 0.125f;

    #pragma unroll 1
    for (int pass = 0; pass < 2; pass++) {
        int mt = warp + pass * 8;
        if (mt >= 13) break;
        int s0 = mt * 16;

        float c[26][4];
        #pragma unroll
        for (int j = 0; j < 26; j++) {
            c[j][0] = 0.f; c[j][1] = 0.f; c[j][2] = 0.f; c[j][3] = 0.f;
        }
        #pragma unroll
        for (int ks = 0; ks < 4; ks++) {
            int kc = ks * 16;
            uint32_t a[4];
            uint32_t aoff = (uint32_t)(((s0 + (lane & 15)) * AT_STR + kc + (lane >> 4) * 8) * 2);
            ldsm_x4(q_base + aoff, a);
            #pragma unroll
            for (int j = 0; j < 13; j++) {
                uint32_t b[4];
                int nrow = j * 16 + (lane >> 4) * 8 + (lane & 7);
                int ncol = kc + ((lane >> 3) & 1) * 8;
                ldsm_x4(k_base + (uint32_t)((nrow * AT_STR + ncol) * 2), b);
                mma_f16(c[2 * j],     a, b);
                mma_f16(c[2 * j + 1], a, b + 2);
            }
        }

        float mx0 = -1e30f, mx1 = -1e30f;
        #pragma unroll
        for (int j = 0; j < 26; j++) {
            int tcol = j * 8 + (lane & 3) * 2;
            #pragma unroll
            for (int e = 0; e < 2; e++) {
                float s0v = c[j][e] * scale;
                float s1v = c[j][2 + e] * scale;
                if (tcol + e >= SS) { s0v = -1e30f; s1v = -1e30f; }
                c[j][e] = s0v;
                c[j][2 + e] = s1v;
                mx0 = fmaxf(mx0, s0v);
                mx1 = fmaxf(mx1, s1v);
            }
        }
        mx0 = fmaxf(mx0, __shfl_xor_sync(0xffffffffu, mx0, 1));
        mx0 = fmaxf(mx0, __shfl_xor_sync(0xffffffffu, mx0, 2));
        mx1 = fmaxf(mx1, __shfl_xor_sync(0xffffffffu, mx1, 1));
        mx1 = fmaxf(mx1, __shfl_xor_sync(0xffffffffu, mx1, 2));

        float sum0 = 0.f, sum1 = 0.f;
        #pragma unroll
        for (int j = 0; j < 26; j++) {
            #pragma unroll
            for (int e = 0; e < 2; e++) {
                float p0 = __expf(c[j][e] - mx0);
                float p1 = __expf(c[j][2 + e] - mx1);
                c[j][e] = p0;
                c[j][2 + e] = p1;
                sum0 += p0;
                sum1 += p1;
            }
        }
        sum0 += __shfl_xor_sync(0xffffffffu, sum0, 1);
        sum0 += __shfl_xor_sync(0xffffffffu, sum0, 2);
        sum1 += __shfl_xor_sync(0xffffffffu, sum1, 1);
        sum1 += __shfl_xor_sync(0xffffffffu, sum1, 2);
        float inv0 = 1.0f / sum0;
        float inv1 = 1.0f / sum1;

        float o[8][4];
        #pragma unroll
        for (int j = 0; j < 8; j++) {
            o[j][0] = 0.f; o[j][1] = 0.f; o[j][2] = 0.f; o[j][3] = 0.f;
        }
        #pragma unroll
        for (int j = 0; j < 13; j++) {
            uint32_t a[4];
            __half2 h0 = __floats2half2_rn(c[2 * j][0] * inv0, c[2 * j][1] * inv0);
            __half2 h1 = __floats2half2_rn(c[2 * j][2] * inv1, c[2 * j][3] * inv1);
            __half2 h2 = __floats2half2_rn(c[2 * j + 1][0] * inv0, c[2 * j + 1][1] * inv0);
            __half2 h3 = __floats2half2_rn(c[2 * j + 1][2] * inv1, c[2 * j + 1][3] * inv1);
            a[0] = *(uint32_t*)&h0;
            a[1] = *(uint32_t*)&h1;
            a[2] = *(uint32_t*)&h2;
            a[3] = *(uint32_t*)&h3;
            int brow = j * 16 + ((lane >> 3) & 1) * 8 + (lane & 7);
            #pragma unroll
            for (int nj = 0; nj < 4; nj++) {
                uint32_t b[4];
                int bcol = nj * 16 + (lane >> 4) * 8;
                ldsm_x4_t(v_base + (uint32_t)((brow * AT_STR + bcol) * 2), b);
                mma_f16(o[2 * nj],     a, b);
                mma_f16(o[2 * nj + 1], a, b + 2);
            }
        }

        int rloc = lane >> 2;
        #pragma unroll
        for (int half = 0; half < 2; half++) {
            int srow = s0 + rloc + half * 8;
            if (srow >= SS) continue;
            float* xr = x + ((size_t)(n * SS + srow)) * DD + h * DH;
            #pragma unroll
            for (int nj = 0; nj < 8; nj++) {
                int col = nj * 8 + (lane & 3) * 2;
                xr[col]     += o[nj][half * 2];
                xr[col + 1] += o[nj][half * 2 + 1];
            }
        }
    }
}

// ---------------- small GEMM (classification head) ----------------
__global__ __launch_bounds__(256) void gemm64(const float* __restrict__ A, long long lda, long long strideA,
                                              const float* __restrict__ B, int ldb, long long strideB,
                                              float* __restrict__ C, int ldc, long long strideC,
                                              const float* __restrict__ bias, long long strideBias,
                                              int M, int N, int K, int flags) {
    int bz = blockIdx.z;
    A += (size_t)bz * strideA;
    B += (size_t)bz * strideB;
    C += (size_t)bz * strideC;
    if (bias) bias += (size_t)bz * strideBias;

    __shared__ float As[16][64];
    __shared__ float Bs[16][68];
    int tid = threadIdx.x;
    int m0 = blockIdx.y * 64, n0 = blockIdx.x * 64;
    int arow = tid >> 2, akcol = (tid & 3) * 4;
    int brow = tid >> 4, bcol = (tid & 15) * 4;
    int tx = tid & 15, ty = tid >> 4;

    float acc[4][4];
    #pragma unroll
    for (int i = 0; i < 4; i++)
        #pragma unroll
        for (int j = 0; j < 4; j++) acc[i][j] = 0.f;

    for (int k0 = 0; k0 < K; k0 += 16) {
        float4 a4 = make_float4(0.f, 0.f, 0.f, 0.f);
        int gm = m0 + arow;
        if (gm < M) a4 = *(const float4*)&A[(size_t)gm * lda + k0 + akcol];
        As[akcol + 0][arow] = a4.x;
        As[akcol + 1][arow] = a4.y;
        As[akcol + 2][arow] = a4.z;
        As[akcol + 3][arow] = a4.w;

        float4 b4;
        int gn = n0 + bcol;
        const float* Brow = &B[(size_t)(k0 + brow) * ldb];
        if (gn + 3 < N) {
            b4 = *(const float4*)&Brow[gn];
        } else {
            b4.x = (gn + 0 < N) ? Brow[gn + 0] : 0.f;
            b4.y = (gn + 1 < N) ? Brow[gn + 1] : 0.f;
            b4.z = (gn + 2 < N) ? Brow[gn + 2] : 0.f;
            b4.w = (gn + 3 < N) ? Brow[gn + 3] : 0.f;
        }
        *(float4*)&Bs[brow][bcol] = b4;
        __syncthreads();

        #pragma unroll
        for (int kk = 0; kk < 16; kk++) {
            float4 a0 = *(float4*)&As[kk][ty * 4];
            float4 b0 = *(float4*)&Bs[kk][tx * 4];
            float ar[4] = {a0.x, a0.y, a0.z, a0.w};
            float br[4] = {b0.x, b0.y, b0.z, b0.w};
            #pragma unroll
            for (int i = 0; i < 4; i++)
                #pragma unroll
                for (int j = 0; j < 4; j++) acc[i][j] += ar[i] * br[j];
        }
        __syncthreads();
    }

    #pragma unroll
    for (int i = 0; i < 4; i++) {
        int r = m0 + ty * 4 + i;
        if (r >= M) continue;
        #pragma unroll
        for (int j = 0; j < 4; j++) {
            int c = n0 + tx * 4 + j;
            if (c >= N) continue;
            float val = acc[i][j];
            if (flags & FLAG_BIAS) val += bias[c];
            if (flags & FLAG_GELU) val = gelu_exact(val);
            float* p = &C[(size_t)r * ldc + c];
            if (flags & FLAG_RES) *p += val; else *p = val;
        }
    }
}

// ---------------- final softmax over 1000 classes ----------------
__global__ __launch_bounds__(256) void softmax_out(const float* __restrict__ logits,
                                                   float* __restrict__ out) {
    int n = blockIdx.x;
    int tid = threadIdx.x;
    const float* l = logits + (size_t)n * OUTC;
    __shared__ float sh[8];
    int lane = tid & 31, wp = tid >> 5;

    float mx = -1e30f;
    for (int c = tid; c < OUTC; c += 256) mx = fmaxf(mx, l[c]);
    #pragma unroll
    for (int o = 16; o; o >>= 1) mx = fmaxf(mx, __shfl_xor_sync(0xffffffffu, mx, o));
    if (lane == 0) sh[wp] = mx;
    __syncthreads();
    float gmx = sh[0];
    #pragma unroll
    for (int i = 1; i < 8; i++) gmx = fmaxf(gmx, sh[i]);
    __syncthreads();

    float sum = 0.f;
    for (int c = tid; c < OUTC; c += 256) sum += __expf(l[c] - gmx);
    #pragma unroll
    for (int o = 16; o; o >>= 1) sum += __shfl_xor_sync(0xffffffffu, sum, o);
    if (lane == 0) sh[wp] = sum;
    __syncthreads();
    float tot = 0.f;
    #pragma unroll
    for (int i = 0; i < 8; i++) tot += sh[i];
    float inv = 1.0f / tot;

    for (int c = tid; c < OUTC; c += 256) out[(size_t)n * OUTC + c] = __expf(l[c] - gmx) * inv;
}

// ---------------- launch ----------------
extern "C" void kernel_launch(void* const* d_in, const int* in_sizes, int n_in,
                              void* d_out, int out_size) {
    const float* images = (const float*)d_in[0];
    const float* Wm     = (const float*)d_in[1];
    const float* bm     = (const float*)d_in[2];
    const float* cls    = (const float*)d_in[3];
    const float* pos    = (const float*)d_in[4];
    const float* ln1w   = (const float*)d_in[5];
    const float* ln1b   = (const float*)d_in[6];
    const float* Wq     = (const float*)d_in[7];
    const float* bq     = (const float*)d_in[8];
    const float* Wk     = (const float*)d_in[9];
    const float* bk     = (const float*)d_in[10];
    const float* Wv     = (const float*)d_in[11];
    const float* bv     = (const float*)d_in[12];
    const float* ln2w   = (const float*)d_in[13];
    const float* ln2b   = (const float*)d_in[14];
    const float* W1     = (const float*)d_in[15];
    const float* b1     = (const float*)d_in[16];
    const float* W2     = (const float*)d_in[17];
    const float* b2     = (const float*)d_in[18];
    const float* Wout   = (const float*)d_in[19];
    const float* bout   = (const float*)d_in[20];
    float* out = (float*)d_out;

    float *p_x, *p_h, *p_logits;
    cudaGetSymbolAddress((void**)&p_x, g_x);
    cudaGetSymbolAddress((void**)&p_h, g_h);
    cudaGetSymbolAddress((void**)&p_logits, g_logits);

    __half *p_q, *p_k, *p_v, *p_patch, *p_hh, *p_u, *p_Wm, *p_W1, *p_W2;
    cudaGetSymbolAddress((void**)&p_q, g_q_f16);
    cudaGetSymbolAddress((void**)&p_k, g_k_f16);
    cudaGetSymbolAddress((void**)&p_v, g_v_f16);
    cudaGetSymbolAddress((void**)&p_patch, g_patch_f16);
    cudaGetSymbolAddress((void**)&p_hh, g_h_f16);
    cudaGetSymbolAddress((void**)&p_u, g_u_f16);
    cudaGetSymbolAddress((void**)&p_Wm, g_Wm_f16);
    cudaGetSymbolAddress((void**)&p_W1, g_W1_f16);
    cudaGetSymbolAddress((void**)&p_W2, g_W2_f16);

    cudaFuncSetAttribute(attn_mma, cudaFuncAttributeMaxDynamicSharedMemorySize, ATT_SMEM_BYTES);
    cudaFuncSetAttribute(gemm_f16, cudaFuncAttributeMaxDynamicSharedMemorySize, GEMM_SMEM_BYTES);
    cudaFuncSetAttribute(qkv_mma, cudaFuncAttributeMaxDynamicSharedMemorySize, QKV_SMEM_BYTES);

    // ---- one-time weight conversions ----
    conv_f16<<<(DD * DD / 4 + 255) / 256, 256>>>(Wm, p_Wm, DD * DD);
    conv_f16<<<(LL * DD * FF / 4 + 255) / 256, 256>>>(W1, p_W1, LL * DD * FF);
    conv_f16<<<(LL * FF * DD / 4 + 255) / 256, 256>>>(W2, p_W2, LL * FF * DD);

    // ---- patch extraction + embed GEMM ----
    extract_patches<<<(PROWS * DD + 255) / 256, 256>>>(images, p_patch);
    gemm_f16<<<dim3(DD / 128, (PROWS + 127) / 128), 256, GEMM_SMEM_BYTES>>>(
        p_patch, DD, p_Wm, DD,
        p_h, nullptr, DD, bm, PROWS, DD, DD, FLAG_BIAS);
    assemble<<<(ROWS * DD + 255) / 256, 256>>>(p_h, cls, pos, p_x);

    for (int l = 0; l < LL; l++) {
        ln_kernel_f16<<<ROWS, 256>>>(p_x, ln1w + l * DD, ln1b + l * DD, p_hh);

        qkv_mma<<<dim3((ROWS + 127) / 128, HH), 256, QKV_SMEM_BYTES>>>(
            p_hh,
            Wq + (size_t)l * HH * DH * DH, Wk + (size_t)l * HH * DH * DH, Wv + (size_t)l * HH * DH * DH,
            bq + (size_t)l * DD, bk + (size_t)l * DD, bv + (size_t)l * DD,
            p_q, p_k, p_v);

        attn_mma<<<NN * HH, 256, ATT_SMEM_BYTES>>>(p_q, p_k, p_v, p_x);

        ln_kernel_f16<<<ROWS, 256>>>(p_x, ln2w + l * DD, ln2b + l * DD, p_hh);

        gemm_f16<<<dim3(FF / 128, (ROWS + 127) / 128), 256, GEMM_SMEM_BYTES>>>(
            p_hh, DD,
            p_W1 + (size_t)l * DD * FF, FF,
            nullptr, p_u, FF, b1 + (size_t)l * FF,
            ROWS, FF, DD, FLAG_BIAS | FLAG_GELU | FLAG_HALF_OUT);

        gemm_f16<<<dim3(DD / 128, (ROWS + 127) / 128), 256, GEMM_SMEM_BYTES>>>(
            p_u, FF,
            p_W2 + (size_t)l * FF * DD, DD,
            p_x, nullptr, DD, b2 + (size_t)l * DD,
            ROWS, DD, FF, FLAG_BIAS | FLAG_RES);
    }

    // classification head: cls rows have stride SS*DD
    gemm64<<<dim3((OUTC + 63) / 64, 1, 1), 256>>>(
        p_x, (long long)SS * DD, 0,
        Wout, OUTC, 0,
        p_logits, OUTC, 0,
        bout, 0,
        NN, OUTC, DD, FLAG_BIAS);

    softmax_out<<<NN, 256>>>(p_logits, out);
}

// round 11
// speedup vs baseline: 5.3049x; 1.1413x over previous
#include <cuda_runtime.h>
#include <cuda_fp16.h>
#include <math.h>
#include <stdint.h>

// ---------------- problem constants ----------------
#define NN 32
#define CC 3
#define NP 14
#define PS 16
#define DD 768
#define HH 12
#define DH 64
#define SS 197
#define LL 8
#define FF 3072
#define OUTC 1000
#define NPATCH (NP*NP)    // 196
#define ROWS (NN*SS)      // 6304
#define PROWS (NN*NPATCH) // 6272

#define FLAG_BIAS 1
#define FLAG_GELU 2
#define FLAG_RES  4
#define FLAG_HALF_OUT 8

// ---------------- scratch (device globals; no runtime allocation) ----------------
__device__ float g_x[ROWS * DD];
__device__ float g_h[ROWS * DD];
__device__ float g_logits[NN * OUTC];

__device__ __half g_patch_f16[PROWS * DD];
__device__ __half g_h_f16[ROWS * DD];
__device__ __half g_u_f16[ROWS * FF];
__device__ __half g_Wm_f16[DD * DD];
__device__ __half g_W1_f16[LL * DD * FF];
__device__ __half g_W2_f16[LL * FF * DD];

__device__ __forceinline__ float gelu_exact(float x) {
    return 0.5f * x * (1.0f + erff(x * 0.70710678118654752f));
}

// ---------------- fp32 -> fp16 conversion ----------------
__global__ void conv_f16(const float* __restrict__ src, __half* __restrict__ dst, int n) {
    int i = (blockIdx.x * blockDim.x + threadIdx.x) * 4;
    if (i >= n) return;
    float4 v = *(const float4*)&src[i];
    __half2* d = (__half2*)&dst[i];
    d[0] = __floats2half2_rn(v.x, v.y);
    d[1] = __floats2half2_rn(v.z, v.w);
}

// ---------------- patch extraction (writes fp16) ----------------
__global__ void extract_patches(const float* __restrict__ images,
                                __half* __restrict__ P) {
    int idx = blockIdx.x * blockDim.x + threadIdx.x;
    if (idx >= PROWS * DD) return;
    int row = idx / DD;
    int col = idx - row * DD;
    int n = row / NPATCH;
    int p = row - n * NPATCH;
    int py = p / NP, px = p - py * NP;
    int c = col / (PS * PS);
    int r = col - c * PS * PS;
    int i = r / PS, j = r - i * PS;
    int H = NP * PS;
    float v = images[(((size_t)n * CC + c) * H + (py * PS + i)) * H + (px * PS + j)];
    P[idx] = __float2half(v);
}

// ---------------- assemble tokens + cls + pos ----------------
__global__ void assemble(const float* __restrict__ tok, const float* __restrict__ cls,
                         const float* __restrict__ pos, float* __restrict__ x) {
    int idx = blockIdx.x * blockDim.x + threadIdx.x;
    if (idx >= ROWS * DD) return;
    int row = idx / DD;
    int d = idx - row * DD;
    int n = row / SS;
    int s = row - n * SS;
    float v;
    if (s == 0) v = cls[d];
    else        v = tok[((size_t)n * NPATCH + (s - 1)) * DD + d];
    x[idx] = v + pos[(size_t)s * DD + d];
}

// ---------------- warp-per-row layernorm -> fp16 out (no barriers) ----------------
__global__ __launch_bounds__(256) void ln_warp(const float* __restrict__ x,
                                               const float* __restrict__ w,
                                               const float* __restrict__ b,
                                               __half* __restrict__ oh) {
    int warp = threadIdx.x >> 5, lane = threadIdx.x & 31;
    int row = blockIdx.x * 8 + warp;
    const float* xr = x + (size_t)row * DD;

    float4 v[6];
    float s = 0.f;
    #pragma unroll
    for (int i = 0; i < 6; i++) {
        v[i] = *(const float4*)&xr[(lane + 32 * i) * 4];
        s += v[i].x + v[i].y + v[i].z + v[i].w;
    }
    #pragma unroll
    for (int o = 16; o; o >>= 1) s += __shfl_xor_sync(0xffffffffu, s, o);
    float mean = s * (1.0f / DD);

    float sq = 0.f;
    #pragma unroll
    for (int i = 0; i < 6; i++) {
        v[i].x -= mean; v[i].y -= mean; v[i].z -= mean; v[i].w -= mean;
        sq += v[i].x * v[i].x + v[i].y * v[i].y + v[i].z * v[i].z + v[i].w * v[i].w;
    }
    #pragma unroll
    for (int o = 16; o; o >>= 1) sq += __shfl_xor_sync(0xffffffffu, sq, o);
    float rstd = rsqrtf(sq * (1.0f / DD) + 1e-5f);

    __half* orow = oh + (size_t)row * DD;
    #pragma unroll
    for (int i = 0; i < 6; i++) {
        int c = (lane + 32 * i) * 4;
        float4 wv = *(const float4*)&w[c];
        float4 bv = *(const float4*)&b[c];
        float r0 = v[i].x * rstd * wv.x + bv.x;
        float r1 = v[i].y * rstd * wv.y + bv.y;
        float r2 = v[i].z * rstd * wv.z + bv.z;
        float r3 = v[i].w * rstd * wv.w + bv.w;
        __half2 h01 = __floats2half2_rn(r0, r1);
        __half2 h23 = __floats2half2_rn(r2, r3);
        uint2 pk;
        pk.x = *(uint32_t*)&h01;
        pk.y = *(uint32_t*)&h23;
        *(uint2*)&orow[c] = pk;
    }
}

// ================= fp16 tensor-core GEMM (3-stage, single barrier/iter) ==========
#define BM 128
#define BN 128
#define BKK 32
#define ASTR 40
#define BSTR 136
#define ASZ (BM*ASTR)
#define BSZ (BKK*BSTR)
#define STAGE_ELEMS (ASZ + BSZ)
#define STAGE_BYTES (STAGE_ELEMS*2)
#define NSTAGE 3
#define GEMM_SMEM_BYTES (NSTAGE * STAGE_BYTES)

__device__ __forceinline__ void ldsm_x4(uint32_t addr, uint32_t* r) {
    asm volatile("ldmatrix.sync.aligned.m8n8.x4.shared.b16 {%0,%1,%2,%3}, [%4];\n"
                 : "=r"(r[0]), "=r"(r[1]), "=r"(r[2]), "=r"(r[3]) : "r"(addr));
}
__device__ __forceinline__ void ldsm_x4_t(uint32_t addr, uint32_t* r) {
    asm volatile("ldmatrix.sync.aligned.m8n8.x4.trans.shared.b16 {%0,%1,%2,%3}, [%4];\n"
                 : "=r"(r[0]), "=r"(r[1]), "=r"(r[2]), "=r"(r[3]) : "r"(addr));
}
__device__ __forceinline__ void mma_f16(float* c, const uint32_t* a, const uint32_t* b) {
    asm volatile("mma.sync.aligned.m16n8k16.row.col.f32.f16.f16.f32 "
                 "{%0,%1,%2,%3},{%4,%5,%6,%7},{%8,%9},{%0,%1,%2,%3};\n"
                 : "+f"(c[0]), "+f"(c[1]), "+f"(c[2]), "+f"(c[3])
                 : "r"(a[0]), "r"(a[1]), "r"(a[2]), "r"(a[3]), "r"(b[0]), "r"(b[1]));
}
__device__ __forceinline__ void cpa16(uint32_t dst, const void* src, int bytes) {
    asm volatile("cp.async.cg.shared.global [%0], [%1], 16, %2;\n"
                 :: "r"(dst), "l"(src), "r"(bytes));
}
__device__ __forceinline__ void cp_commit() {
    asm volatile("cp.async.commit_group;\n");
}
__device__ __forceinline__ void cp_wait1() {
    asm volatile("cp.async.wait_group 1;\n");
}

__device__ __forceinline__ void gemm_issue_stage(
    uint32_t smem_u32, int stage,
    const __half* __restrict__ A, int lda,
    const __half* __restrict__ B, int ldb,
    int M, int m0, int n0, int kb, int tid)
{
    uint32_t s = smem_u32 + (uint32_t)stage * STAGE_BYTES;
    uint32_t sA = s;
    uint32_t sB = s + ASZ * 2;
    #pragma unroll
    for (int i = 0; i < 2; i++) {
        int chunk = tid + 256 * i;
        int row = chunk >> 2;
        int c16 = chunk & 3;
        int gr = m0 + row;
        int bytes = (gr < M) ? 16 : 0;
        size_t goff = (size_t)gr * lda + kb + c16 * 8;
        uint32_t doff = (uint32_t)(row * ASTR + c16 * 8) * 2;
        cpa16(sA + doff, A + goff, bytes);
    }
    #pragma unroll
    for (int i = 0; i < 2; i++) {
        int chunk = tid + 256 * i;
        int row = chunk >> 4;
        int c16 = chunk & 15;
        size_t goff = (size_t)(kb + row) * ldb + n0 + c16 * 8;
        uint32_t doff = (uint32_t)(row * BSTR + c16 * 8) * 2;
        cpa16(sB + doff, B + goff, 16);
    }
}

__global__ __launch_bounds__(256, 2) void gemm_f16(
    const __half* __restrict__ A, int lda,
    const __half* __restrict__ B, int ldb,
    float* __restrict__ C, __half* __restrict__ Ch,
    int ldc, const float* __restrict__ bias,
    int M, int N, int K, int flags)
{
    extern __shared__ __half smbuf[];
    int tid = threadIdx.x;
    int m0 = blockIdx.y * BM;
    int n0 = blockIdx.x * BN;
    int warp = tid >> 5;
    int lane = tid & 31;
    int wm = (warp >> 2) * 64;
    int wn = (warp & 3) * 32;

    float acc[4][4][4];
    #pragma unroll
    for (int i = 0; i < 4; i++)
        #pragma unroll
        for (int j = 0; j < 4; j++)
            #pragma unroll
            for (int c = 0; c < 4; c++) acc[i][j][c] = 0.f;

    uint32_t smem_u32 = (uint32_t)__cvta_generic_to_shared(smbuf);
    const int nk = K / BKK;

    gemm_issue_stage(smem_u32, 0, A, lda, B, ldb, M, m0, n0, 0, tid);
    cp_commit();
    gemm_issue_stage(smem_u32, 1, A, lda, B, ldb, M, m0, n0, BKK, tid);
    cp_commit();

    int st = 0;
    for (int kt = 0; kt < nk; kt++) {
        cp_wait1();
        __syncthreads();

        int nxt = kt + 2;
        if (nxt < nk) {
            int nst = st + 2;
            if (nst >= NSTAGE) nst -= NSTAGE;
            gemm_issue_stage(smem_u32, nst, A, lda, B, ldb, M, m0, n0, nxt * BKK, tid);
        }
        cp_commit();

        uint32_t s = smem_u32 + (uint32_t)st * STAGE_BYTES;
        uint32_t a_base = s;
        uint32_t b_base = s + ASZ * 2;

        #pragma unroll
        for (int ks = 0; ks < 2; ks++) {
            int kc = ks * 16;
            uint32_t bf[4][2];
            int brow = kc + ((lane >> 3) & 1) * 8 + (lane & 7);
            #pragma unroll
            for (int j = 0; j < 2; j++) {
                int bcol = wn + j * 16 + (lane >> 4) * 8;
                uint32_t off = (uint32_t)((brow * BSTR + bcol) * 2);
                uint32_t th[4];
                ldsm_x4_t(b_base + off, th);
                bf[2 * j][0] = th[0];
                bf[2 * j][1] = th[1];
                bf[2 * j + 1][0] = th[2];
                bf[2 * j + 1][1] = th[3];
            }
            int arow = lane & 15;
            int acol = kc + (lane >> 4) * 8;
            #pragma unroll
            for (int mi = 0; mi < 4; mi++) {
                uint32_t af[4];
                uint32_t off = (uint32_t)(((wm + mi * 16 + arow) * ASTR + acol) * 2);
                ldsm_x4(a_base + off, af);
                #pragma unroll
                for (int ni = 0; ni < 4; ni++) {
                    mma_f16(acc[mi][ni], af, bf[ni]);
                }
            }
        }

        st = (st + 1 == NSTAGE) ? 0 : st + 1;
    }

    // ---- epilogue ----
    #pragma unroll
    for (int mi = 0; mi < 4; mi++) {
        int r0 = m0 + wm + mi * 16 + (lane >> 2);
        #pragma unroll
        for (int ni = 0; ni < 4; ni++) {
            int c0 = n0 + wn + ni * 8 + (lane & 3) * 2;
            #pragma unroll
            for (int half = 0; half < 2; half++) {
                int r = r0 + half * 8;
                if (r >= M) continue;
                #pragma unroll
                for (int e = 0; e < 2; e++) {
                    int c = c0 + e;
                    float val = acc[mi][ni][half * 2 + e];
                    if (flags & FLAG_BIAS) val += bias[c];
                    if (flags & FLAG_GELU) val = gelu_exact(val);
                    if (flags & FLAG_HALF_OUT) {
                        Ch[(size_t)r * ldc + c] = __float2half(val);
                    } else {
                        float* p = &C[(size_t)r * ldc + c];
                        if (flags & FLAG_RES) *p += val; else *p = val;
                    }
                }
            }
        }
    }
}

// ================= fused QKV + attention: block per (n, head) =================
// smem: Hs[208][72] + Ws[3][64][72] + Qs/Ks/Vs[208][72] each, all fp16.
#define AT_ROWS 208
#define AT_STR 72
#define HS_ELEMS (AT_ROWS * AT_STR)          // 14976
#define WS_ELEMS (3 * 64 * AT_STR)           // 13824
#define FUSED_SMEM_BYTES ((HS_ELEMS + WS_ELEMS + 3 * HS_ELEMS) * 2)   // 147456

__global__ __launch_bounds__(256, 1) void qkv_attn_fused(
    const __half* __restrict__ hbuf,
    const float* __restrict__ Wq, const float* __restrict__ Wk, const float* __restrict__ Wv,
    const float* __restrict__ bq, const float* __restrict__ bk, const float* __restrict__ bv,
    float* __restrict__ x)
{
    extern __shared__ __half fsm[];
    __half* Hs = fsm;
    __half* Ws = Hs + HS_ELEMS;
    __half* Qs = Ws + WS_ELEMS;
    __half* Ks = Qs + HS_ELEMS;
    __half* Vs = Ks + HS_ELEMS;

    int nh = blockIdx.x;
    int n = nh / HH, h = nh - n * HH;
    int tid = threadIdx.x;
    int warp = tid >> 5, lane = tid & 31;

    // ---- load h slice (zero-pad t >= SS) ----
    for (int idx = tid; idx < AT_ROWS * 8; idx += 256) {
        int t = idx >> 3;
        int c8 = (idx & 7) * 8;
        uint4 hv = make_uint4(0, 0, 0, 0);
        if (t < SS) hv = *(const uint4*)(hbuf + ((size_t)(n * SS + t)) * DD + h * DH + c8);
        *(uint4*)(Hs + t * AT_STR + c8) = hv;
    }
    // ---- load + convert per-head weights ----
    const float* wsrc[3] = {Wq + h * DH * DH, Wk + h * DH * DH, Wv + h * DH * DH};
    for (int idx = tid; idx < 3 * DH * DH; idx += 256) {
        int mat = idx >> 12;
        int rem = idx & 4095;
        int d = rem >> 6, e = rem & 63;
        Ws[mat * 64 * AT_STR + d * AT_STR + e] = __float2half(wsrc[mat][d * 64 + e]);
    }
    __syncthreads();

    uint32_t h_base = (uint32_t)__cvta_generic_to_shared(Hs);
    uint32_t w_base = (uint32_t)__cvta_generic_to_shared(Ws);
    uint32_t q_base = (uint32_t)__cvta_generic_to_shared(Qs);
    uint32_t k_base = (uint32_t)__cvta_generic_to_shared(Ks);
    uint32_t v_base = (uint32_t)__cvta_generic_to_shared(Vs);

    const float* bsrc0 = bq + h * DH;
    const float* bsrc1 = bk + h * DH;
    const float* bsrc2 = bv + h * DH;
    __half* outs[3] = {Qs, Ks, Vs};

    // ---- QKV compute into smem ----
    #pragma unroll 1
    for (int pass = 0; pass < 2; pass++) {
        int mt = warp + pass * 8;
        if (mt >= 13) break;
        int s0 = mt * 16;

        float acc[3][8][4];
        #pragma unroll
        for (int m = 0; m < 3; m++)
            #pragma unroll
            for (int j = 0; j < 8; j++) {
                acc[m][j][0] = 0.f; acc[m][j][1] = 0.f;
                acc[m][j][2] = 0.f; acc[m][j][3] = 0.f;
            }

        #pragma unroll
        for (int ks = 0; ks < 4; ks++) {
            int kc = ks * 16;
            uint32_t af[4];
            uint32_t aoff = (uint32_t)(((s0 + (lane & 15)) * AT_STR + kc + (lane >> 4) * 8) * 2);
            ldsm_x4(h_base + aoff, af);
            int brow = kc + ((lane >> 3) & 1) * 8 + (lane & 7);
            #pragma unroll
            for (int mat = 0; mat < 3; mat++) {
                #pragma unroll
                for (int j = 0; j < 4; j++) {
                    int bcol = j * 16 + (lane >> 4) * 8;
                    uint32_t th[4];
                    ldsm_x4_t(w_base + (uint32_t)((mat * 64 * AT_STR + brow * AT_STR + bcol) * 2), th);
                    mma_f16(acc[mat][2 * j],     af, th);
                    mma_f16(acc[mat][2 * j + 1], af, th + 2);
                }
            }
        }

        const float* bp[3] = {bsrc0, bsrc1, bsrc2};
        #pragma unroll
        for (int mat = 0; mat < 3; mat++) {
            #pragma unroll
            for (int half = 0; half < 2; half++) {
                int r = s0 + (lane >> 2) + half * 8;   // always < 208
                __half* orow = outs[mat] + r * AT_STR;
                #pragma unroll
                for (int nj = 0; nj < 8; nj++) {
                    int col = nj * 8 + (lane & 3) * 2;
                    __half2 hv = __floats2half2_rn(acc[mat][nj][half * 2]     + bp[mat][col],
                                                   acc[mat][nj][half * 2 + 1] + bp[mat][col + 1]);
                    *(__half2*)&orow[col] = hv;
                }
            }
        }
    }
    __syncthreads();

    // ---- attention ----
    const float scale = 0.125f;
    #pragma unroll 1
    for (int pass = 0; pass < 2; pass++) {
        int mt = warp + pass * 8;
        if (mt >= 13) break;
        int s0 = mt * 16;

        float c[26][4];
        #pragma unroll
        for (int j = 0; j < 26; j++) {
            c[j][0] = 0.f; c[j][1] = 0.f; c[j][2] = 0.f; c[j][3] = 0.f;
        }
        #pragma unroll
        for (int ks = 0; ks < 4; ks++) {
            int kc = ks * 16;
            uint32_t a[4];
            uint32_t aoff = (uint32_t)(((s0 + (lane & 15)) * AT_STR + kc + (lane >> 4) * 8) * 2);
            ldsm_x4(q_base + aoff, a);
            #pragma unroll
            for (int j = 0; j < 13; j++) {
                uint32_t b[4];
                int nrow = j * 16 + (lane >> 4) * 8 + (lane & 7);
                int ncol = kc + ((lane >> 3) & 1) * 8;
                ldsm_x4(k_base + (uint32_t)((nrow * AT_STR + ncol) * 2), b);
                mma_f16(c[2 * j],     a, b);
                mma_f16(c[2 * j + 1], a, b + 2);
            }
        }

        float mx0 = -1e30f, mx1 = -1e30f;
        #pragma unroll
        for (int j = 0; j < 26; j++) {
            int tcol = j * 8 + (lane & 3) * 2;
            #pragma unroll
            for (int e = 0; e < 2; e++) {
                float s0v = c[j][e] * scale;
                float s1v = c[j][2 + e] * scale;
                if (tcol + e >= SS) { s0v = -1e30f; s1v = -1e30f; }
                c[j][e] = s0v;
                c[j][2 + e] = s1v;
                mx0 = fmaxf(mx0, s0v);
                mx1 = fmaxf(mx1, s1v);
            }
        }
        mx0 = fmaxf(mx0, __shfl_xor_sync(0xffffffffu, mx0, 1));
        mx0 = fmaxf(mx0, __shfl_xor_sync(0xffffffffu, mx0, 2));
        mx1 = fmaxf(mx1, __shfl_xor_sync(0xffffffffu, mx1, 1));
        mx1 = fmaxf(mx1, __shfl_xor_sync(0xffffffffu, mx1, 2));

        float sum0 = 0.f, sum1 = 0.f;
        #pragma unroll
        for (int j = 0; j < 26; j++) {
            #pragma unroll
            for (int e = 0; e < 2; e++) {
                float p0 = __expf(c[j][e] - mx0);
                float p1 = __expf(c[j][2 + e] - mx1);
                c[j][e] = p0;
                c[j][2 + e] = p1;
                sum0 += p0;
                sum1 += p1;
            }
        }
        sum0 += __shfl_xor_sync(0xffffffffu, sum0, 1);
        sum0 += __shfl_xor_sync(0xffffffffu, sum0, 2);
        sum1 += __shfl_xor_sync(0xffffffffu, sum1, 1);
        sum1 += __shfl_xor_sync(0xffffffffu, sum1, 2);
        float inv0 = 1.0f / sum0;
        float inv1 = 1.0f / sum1;

        float o[8][4];
        #pragma unroll
        for (int j = 0; j < 8; j++) {
            o[j][0] = 0.f; o[j][1] = 0.f; o[j][2] = 0.f; o[j][3] = 0.f;
        }
        #pragma unroll
        for (int j = 0; j < 13; j++) {
            uint32_t a[4];
            __half2 h0 = __floats2half2_rn(c[2 * j][0] * inv0, c[2 * j][1] * inv0);
            __half2 h1 = __floats2half2_rn(c[2 * j][2] * inv1, c[2 * j][3] * inv1);
            __half2 h2 = __floats2half2_rn(c[2 * j + 1][0] * inv0, c[2 * j + 1][1] * inv0);
            __half2 h3 = __floats2half2_rn(c[2 * j + 1][2] * inv1, c[2 * j + 1][3] * inv1);
            a[0] = *(uint32_t*)&h0;
            a[1] = *(uint32_t*)&h1;
            a[2] = *(uint32_t*)&h2;
            a[3] = *(uint32_t*)&h3;
            int brow = j * 16 + ((lane >> 3) & 1) * 8 + (lane & 7);
            #pragma unroll
            for (int nj = 0; nj < 4; nj++) {
                uint32_t b[4];
                int bcol = nj * 16 + (lane >> 4) * 8;
                ldsm_x4_t(v_base + (uint32_t)((brow * AT_STR + bcol) * 2), b);
                mma_f16(o[2 * nj],     a, b);
                mma_f16(o[2 * nj + 1], a, b + 2);
            }
        }

        int rloc = lane >> 2;
        #pragma unroll
        for (int half = 0; half < 2; half++) {
            int srow = s0 + rloc + half * 8;
            if (srow >= SS) continue;
            float* xr = x + ((size_t)(n * SS + srow)) * DD + h * DH;
            #pragma unroll
            for (int nj = 0; nj < 8; nj++) {
                int col = nj * 8 + (lane & 3) * 2;
                xr[col]     += o[nj][half * 2];
                xr[col + 1] += o[nj][half * 2 + 1];
            }
        }
    }
}

// ---------------- small GEMM (classification head) ----------------
__global__ __launch_bounds__(256) void gemm64(const float* __restrict__ A, long long lda, long long strideA,
                                              const float* __restrict__ B, int ldb, long long strideB,
                                              float* __restrict__ C, int ldc, long long strideC,
                                              const float* __restrict__ bias, long long strideBias,
                                              int M, int N, int K, int flags) {
    int bz = blockIdx.z;
    A += (size_t)bz * strideA;
    B += (size_t)bz * strideB;
    C += (size_t)bz * strideC;
    if (bias) bias += (size_t)bz * strideBias;

    __shared__ float As[16][64];
    __shared__ float Bs[16][68];
    int tid = threadIdx.x;
    int m0 = blockIdx.y * 64, n0 = blockIdx.x * 64;
    int arow = tid >> 2, akcol = (tid & 3) * 4;
    int brow = tid >> 4, bcol = (tid & 15) * 4;
    int tx = tid & 15, ty = tid >> 4;

    float acc[4][4];
    #pragma unroll
    for (int i = 0; i < 4; i++)
        #pragma unroll
        for (int j = 0; j < 4; j++) acc[i][j] = 0.f;

    for (int k0 = 0; k0 < K; k0 += 16) {
        float4 a4 = make_float4(0.f, 0.f, 0.f, 0.f);
        int gm = m0 + arow;
        if (gm < M) a4 = *(const float4*)&A[(size_t)gm * lda + k0 + akcol];
        As[akcol + 0][arow] = a4.x;
        As[akcol + 1][arow] = a4.y;
        As[akcol + 2][arow] = a4.z;
        As[akcol + 3][arow] = a4.w;

        float4 b4;
        int gn = n0 + bcol;
        const float* Brow = &B[(size_t)(k0 + brow) * ldb];
        if (gn + 3 < N) {
            b4 = *(const float4*)&Brow[gn];
        } else {
            b4.x = (gn + 0 < N) ? Brow[gn + 0] : 0.f;
            b4.y = (gn + 1 < N) ? Brow[gn + 1] : 0.f;
            b4.z = (gn + 2 < N) ? Brow[gn + 2] : 0.f;
            b4.w = (gn + 3 < N) ? Brow[gn + 3] : 0.f;
        }
        *(float4*)&Bs[brow][bcol] = b4;
        __syncthreads();

        #pragma unroll
        for (int kk = 0; kk < 16; kk++) {
            float4 a0 = *(float4*)&As[kk][ty * 4];
            float4 b0 = *(float4*)&Bs[kk][tx * 4];
            float ar[4] = {a0.x, a0.y, a0.z, a0.w};
            float br[4] = {b0.x, b0.y, b0.z, b0.w};
            #pragma unroll
            for (int i = 0; i < 4; i++)
                #pragma unroll
                for (int j = 0; j < 4; j++) acc[i][j] += ar[i] * br[j];
        }
        __syncthreads();
    }

    #pragma unroll
    for (int i = 0; i < 4; i++) {
        int r = m0 + ty * 4 + i;
        if (r >= M) continue;
        #pragma unroll
        for (int j = 0; j < 4; j++) {
            int c = n0 + tx * 4 + j;
            if (c >= N) continue;
            float val = acc[i][j];
            if (flags & FLAG_BIAS) val += bias[c];
            if (flags & FLAG_GELU) val = gelu_exact(val);
            float* p = &C[(size_t)r * ldc + c];
            if (flags & FLAG_RES) *p += val; else *p = val;
        }
    }
}

// ---------------- final softmax over 1000 classes ----------------
__global__ __launch_bounds__(256) void softmax_out(const float* __restrict__ logits,
                                                   float* __restrict__ out) {
    int n = blockIdx.x;
    int tid = threadIdx.x;
    const float* l = logits + (size_t)n * OUTC;
    __shared__ float sh[8];
    int lane = tid & 31, wp = tid >> 5;

    float mx = -1e30f;
    for (int c = tid; c < OUTC; c += 256) mx = fmaxf(mx, l[c]);
    #pragma unroll
    for (int o = 16; o; o >>= 1) mx = fmaxf(mx, __shfl_xor_sync(0xffffffffu, mx, o));
    if (lane == 0) sh[wp] = mx;
    __syncthreads();
    float gmx = sh[0];
    #pragma unroll
    for (int i = 1; i < 8; i++) gmx = fmaxf(gmx, sh[i]);
    __syncthreads();

    float sum = 0.f;
    for (int c = tid; c < OUTC; c += 256) sum += __expf(l[c] - gmx);
    #pragma unroll
    for (int o = 16; o; o >>= 1) sum += __shfl_xor_sync(0xffffffffu, sum, o);
    if (lane == 0) sh[wp] = sum;
    __syncthreads();
    float tot = 0.f;
    #pragma unroll
    for (int i = 0; i < 8; i++) tot += sh[i];
    float inv = 1.0f / tot;

    for (int c = tid; c < OUTC; c += 256) out[(size_t)n * OUTC + c] = __expf(l[c] - gmx) * inv;
}

// ---------------- launch ----------------
extern "C" void kernel_launch(void* const* d_in, const int* in_sizes, int n_in,
                              void* d_out, int out_size) {
    const float* images = (const float*)d_in[0];
    const float* Wm     = (const float*)d_in[1];
    const float* bm     = (const float*)d_in[2];
    const float* cls    = (const float*)d_in[3];
    const float* pos    = (const float*)d_in[4];
    const float* ln1w   = (const float*)d_in[5];
    const float* ln1b   = (const float*)d_in[6];
    const float* Wq     = (const float*)d_in[7];
    const float* bq     = (const float*)d_in[8];
    const float* Wk     = (const float*)d_in[9];
    const float* bk     = (const float*)d_in[10];
    const float* Wv     = (const float*)d_in[11];
    const float* bv     = (const float*)d_in[12];
    const float* ln2w   = (const float*)d_in[13];
    const float* ln2b   = (const float*)d_in[14];
    const float* W1     = (const float*)d_in[15];
    const float* b1     = (const float*)d_in[16];
    const float* W2     = (const float*)d_in[17];
    const float* b2     = (const float*)d_in[18];
    const float* Wout   = (const float*)d_in[19];
    const float* bout   = (const float*)d_in[20];
    float* out = (float*)d_out;

    float *p_x, *p_h, *p_logits;
    cudaGetSymbolAddress((void**)&p_x, g_x);
    cudaGetSymbolAddress((void**)&p_h, g_h);
    cudaGetSymbolAddress((void**)&p_logits, g_logits);

    __half *p_patch, *p_hh, *p_u, *p_Wm, *p_W1, *p_W2;
    cudaGetSymbolAddress((void**)&p_patch, g_patch_f16);
    cudaGetSymbolAddress((void**)&p_hh, g_h_f16);
    cudaGetSymbolAddress((void**)&p_u, g_u_f16);
    cudaGetSymbolAddress((void**)&p_Wm, g_Wm_f16);
    cudaGetSymbolAddress((void**)&p_W1, g_W1_f16);
    cudaGetSymbolAddress((void**)&p_W2, g_W2_f16);

    cudaFuncSetAttribute(qkv_attn_fused, cudaFuncAttributeMaxDynamicSharedMemorySize, FUSED_SMEM_BYTES);
    cudaFuncSetAttribute(gemm_f16, cudaFuncAttributeMaxDynamicSharedMemorySize, GEMM_SMEM_BYTES);

    // ---- one-time weight conversions ----
    conv_f16<<<(DD * DD / 4 + 255) / 256, 256>>>(Wm, p_Wm, DD * DD);
    conv_f16<<<(LL * DD * FF / 4 + 255) / 256, 256>>>(W1, p_W1, LL * DD * FF);
    conv_f16<<<(LL * FF * DD / 4 + 255) / 256, 256>>>(W2, p_W2, LL * FF * DD);

    // ---- patch extraction + embed GEMM ----
    extract_patches<<<(PROWS * DD + 255) / 256, 256>>>(images, p_patch);
    gemm_f16<<<dim3(DD / 128, (PROWS + 127) / 128), 256, GEMM_SMEM_BYTES>>>(
        p_patch, DD, p_Wm, DD,
        p_h, nullptr, DD, bm, PROWS, DD, DD, FLAG_BIAS);
    assemble<<<(ROWS * DD + 255) / 256, 256>>>(p_h, cls, pos, p_x);

    for (int l = 0; l < LL; l++) {
        ln_warp<<<ROWS / 8, 256>>>(p_x, ln1w + l * DD, ln1b + l * DD, p_hh);

        qkv_attn_fused<<<NN * HH, 256, FUSED_SMEM_BYTES>>>(
            p_hh,
            Wq + (size_t)l * HH * DH * DH, Wk + (size_t)l * HH * DH * DH, Wv + (size_t)l * HH * DH * DH,
            bq + (size_t)l * DD, bk + (size_t)l * DD, bv + (size_t)l * DD,
            p_x);

        ln_warp<<<ROWS / 8, 256>>>(p_x, ln2w + l * DD, ln2b + l * DD, p_hh);

        gemm_f16<<<dim3(FF / 128, (ROWS + 127) / 128), 256, GEMM_SMEM_BYTES>>>(
            p_hh, DD,
            p_W1 + (size_t)l * DD * FF, FF,
            nullptr, p_u, FF, b1 + (size_t)l * FF,
            ROWS, FF, DD, FLAG_BIAS | FLAG_GELU | FLAG_HALF_OUT);

        gemm_f16<<<dim3(DD / 128, (ROWS + 127) / 128), 256, GEMM_SMEM_BYTES>>>(
            p_u, FF,
            p_W2 + (size_t)l * FF * DD, DD,
            p_x, nullptr, DD, b2 + (size_t)l * DD,
            ROWS, DD, FF, FLAG_BIAS | FLAG_RES);
    }

    // classification head: cls rows have stride SS*DD
    gemm64<<<dim3((OUTC + 63) / 64, 1, 1), 256>>>(
        p_x, (long long)SS * DD, 0,
        Wout, OUTC, 0,
        p_logits, OUTC, 0,
        bout, 0,
        NN, OUTC, DD, FLAG_BIAS);

    softmax_out<<<NN, 256>>>(p_logits, out);
}

// round 12
// speedup vs baseline: 5.3315x; 1.0050x over previous
#include <cuda_runtime.h>
#include <cuda_fp16.h>
#include <math.h>
#include <stdint.h>

// ---------------- problem constants ----------------
#define NN 32
#define CC 3
#define NP 14
#define PS 16
#define DD 768
#define HH 12
#define DH 64
#define SS 197
#define LL 8
#define FF 3072
#define OUTC 1000
#define NPATCH (NP*NP)    // 196
#define ROWS (NN*SS)      // 6304
#define PROWS (NN*NPATCH) // 6272

#define FLAG_BIAS 1
#define FLAG_GELU 2
#define FLAG_RES  4
#define FLAG_HALF_OUT 8

// ---------------- scratch (device globals; no runtime allocation) ----------------
__device__ float g_x[ROWS * DD];
__device__ float g_h[ROWS * DD];
__device__ float g_logits[NN * OUTC];

__device__ __half g_patch_f16[PROWS * DD];
__device__ __half g_h_f16[ROWS * DD];
__device__ __half g_u_f16[ROWS * FF];
__device__ __half g_Wm_f16[DD * DD];
__device__ __half g_W1_f16[LL * DD * FF];
__device__ __half g_W2_f16[LL * FF * DD];

__device__ __forceinline__ float gelu_exact(float x) {
    return 0.5f * x * (1.0f + erff(x * 0.70710678118654752f));
}

// ---------------- fp32 -> fp16 conversion ----------------
__global__ void conv_f16(const float* __restrict__ src, __half* __restrict__ dst, int n) {
    int i = (blockIdx.x * blockDim.x + threadIdx.x) * 4;
    if (i >= n) return;
    float4 v = *(const float4*)&src[i];
    __half2* d = (__half2*)&dst[i];
    d[0] = __floats2half2_rn(v.x, v.y);
    d[1] = __floats2half2_rn(v.z, v.w);
}

// ---------------- patch extraction (writes fp16) ----------------
__global__ void extract_patches(const float* __restrict__ images,
                                __half* __restrict__ P) {
    int idx = blockIdx.x * blockDim.x + threadIdx.x;
    if (idx >= PROWS * DD) return;
    int row = idx / DD;
    int col = idx - row * DD;
    int n = row / NPATCH;
    int p = row - n * NPATCH;
    int py = p / NP, px = p - py * NP;
    int c = col / (PS * PS);
    int r = col - c * PS * PS;
    int i = r / PS, j = r - i * PS;
    int H = NP * PS;
    float v = images[(((size_t)n * CC + c) * H + (py * PS + i)) * H + (px * PS + j)];
    P[idx] = __float2half(v);
}

// ---------------- assemble tokens + cls + pos ----------------
__global__ void assemble(const float* __restrict__ tok, const float* __restrict__ cls,
                         const float* __restrict__ pos, float* __restrict__ x) {
    int idx = blockIdx.x * blockDim.x + threadIdx.x;
    if (idx >= ROWS * DD) return;
    int row = idx / DD;
    int d = idx - row * DD;
    int n = row / SS;
    int s = row - n * SS;
    float v;
    if (s == 0) v = cls[d];
    else        v = tok[((size_t)n * NPATCH + (s - 1)) * DD + d];
    x[idx] = v + pos[(size_t)s * DD + d];
}

// ---------------- warp-per-row layernorm -> fp16 out (no barriers) ----------------
__global__ __launch_bounds__(256) void ln_warp(const float* __restrict__ x,
                                               const float* __restrict__ w,
                                               const float* __restrict__ b,
                                               __half* __restrict__ oh) {
    int warp = threadIdx.x >> 5, lane = threadIdx.x & 31;
    int row = blockIdx.x * 8 + warp;
    const float* xr = x + (size_t)row * DD;

    float4 v[6];
    float s = 0.f;
    #pragma unroll
    for (int i = 0; i < 6; i++) {
        v[i] = *(const float4*)&xr[(lane + 32 * i) * 4];
        s += v[i].x + v[i].y + v[i].z + v[i].w;
    }
    #pragma unroll
    for (int o = 16; o; o >>= 1) s += __shfl_xor_sync(0xffffffffu, s, o);
    float mean = s * (1.0f / DD);

    float sq = 0.f;
    #pragma unroll
    for (int i = 0; i < 6; i++) {
        v[i].x -= mean; v[i].y -= mean; v[i].z -= mean; v[i].w -= mean;
        sq += v[i].x * v[i].x + v[i].y * v[i].y + v[i].z * v[i].z + v[i].w * v[i].w;
    }
    #pragma unroll
    for (int o = 16; o; o >>= 1) sq += __shfl_xor_sync(0xffffffffu, sq, o);
    float rstd = rsqrtf(sq * (1.0f / DD) + 1e-5f);

    __half* orow = oh + (size_t)row * DD;
    #pragma unroll
    for (int i = 0; i < 6; i++) {
        int c = (lane + 32 * i) * 4;
        float4 wv = *(const float4*)&w[c];
        float4 bv = *(const float4*)&b[c];
        float r0 = v[i].x * rstd * wv.x + bv.x;
        float r1 = v[i].y * rstd * wv.y + bv.y;
        float r2 = v[i].z * rstd * wv.z + bv.z;
        float r3 = v[i].w * rstd * wv.w + bv.w;
        __half2 h01 = __floats2half2_rn(r0, r1);
        __half2 h23 = __floats2half2_rn(r2, r3);
        uint2 pk;
        pk.x = *(uint32_t*)&h01;
        pk.y = *(uint32_t*)&h23;
        *(uint2*)&orow[c] = pk;
    }
}

// ================= fp16 tensor-core GEMM (3-stage, frag-pipelined) ==========
#define BM 128
#define BN 128
#define BKK 32
#define ASTR 40
#define BSTR 136
#define ASZ (BM*ASTR)
#define BSZ (BKK*BSTR)
#define STAGE_ELEMS (ASZ + BSZ)
#define STAGE_BYTES (STAGE_ELEMS*2)
#define NSTAGE 3
#define GEMM_SMEM_BYTES (NSTAGE * STAGE_BYTES)

__device__ __forceinline__ void ldsm_x4(uint32_t addr, uint32_t* r) {
    asm volatile("ldmatrix.sync.aligned.m8n8.x4.shared.b16 {%0,%1,%2,%3}, [%4];\n"
                 : "=r"(r[0]), "=r"(r[1]), "=r"(r[2]), "=r"(r[3]) : "r"(addr));
}
__device__ __forceinline__ void ldsm_x4_t(uint32_t addr, uint32_t* r) {
    asm volatile("ldmatrix.sync.aligned.m8n8.x4.trans.shared.b16 {%0,%1,%2,%3}, [%4];\n"
                 : "=r"(r[0]), "=r"(r[1]), "=r"(r[2]), "=r"(r[3]) : "r"(addr));
}
__device__ __forceinline__ void mma_f16(float* c, const uint32_t* a, const uint32_t* b) {
    asm volatile("mma.sync.aligned.m16n8k16.row.col.f32.f16.f16.f32 "
                 "{%0,%1,%2,%3},{%4,%5,%6,%7},{%8,%9},{%0,%1,%2,%3};\n"
                 : "+f"(c[0]), "+f"(c[1]), "+f"(c[2]), "+f"(c[3])
                 : "r"(a[0]), "r"(a[1]), "r"(a[2]), "r"(a[3]), "r"(b[0]), "r"(b[1]));
}
__device__ __forceinline__ void cpa16(uint32_t dst, const void* src, int bytes) {
    asm volatile("cp.async.cg.shared.global [%0], [%1], 16, %2;\n"
                 :: "r"(dst), "l"(src), "r"(bytes));
}
__device__ __forceinline__ void cp_commit() {
    asm volatile("cp.async.commit_group;\n");
}
__device__ __forceinline__ void cp_wait1() {
    asm volatile("cp.async.wait_group 1;\n");
}

__device__ __forceinline__ void gemm_issue_stage(
    uint32_t smem_u32, int stage,
    const __half* __restrict__ A, int lda,
    const __half* __restrict__ B, int ldb,
    int M, int m0, int n0, int kb, int tid)
{
    uint32_t s = smem_u32 + (uint32_t)stage * STAGE_BYTES;
    uint32_t sA = s;
    uint32_t sB = s + ASZ * 2;
    #pragma unroll
    for (int i = 0; i < 2; i++) {
        int chunk = tid + 256 * i;
        int row = chunk >> 2;
        int c16 = chunk & 3;
        int gr = m0 + row;
        int bytes = (gr < M) ? 16 : 0;
        size_t goff = (size_t)gr * lda + kb + c16 * 8;
        uint32_t doff = (uint32_t)(row * ASTR + c16 * 8) * 2;
        cpa16(sA + doff, A + goff, bytes);
    }
    #pragma unroll
    for (int i = 0; i < 2; i++) {
        int chunk = tid + 256 * i;
        int row = chunk >> 4;
        int c16 = chunk & 15;
        size_t goff = (size_t)(kb + row) * ldb + n0 + c16 * 8;
        uint32_t doff = (uint32_t)(row * BSTR + c16 * 8) * 2;
        cpa16(sB + doff, B + goff, 16);
    }
}

__global__ __launch_bounds__(256, 2) void gemm_f16(
    const __half* __restrict__ A, int lda,
    const __half* __restrict__ B, int ldb,
    float* __restrict__ C, __half* __restrict__ Ch,
    int ldc, const float* __restrict__ bias,
    int M, int N, int K, int flags)
{
    extern __shared__ __half smbuf[];
    int tid = threadIdx.x;
    int m0 = blockIdx.y * BM;
    int n0 = blockIdx.x * BN;
    int warp = tid >> 5;
    int lane = tid & 31;
    int wm = (warp >> 2) * 64;
    int wn = (warp & 3) * 32;

    float acc[4][4][4];
    #pragma unroll
    for (int i = 0; i < 4; i++)
        #pragma unroll
        for (int j = 0; j < 4; j++)
            #pragma unroll
            for (int c = 0; c < 4; c++) acc[i][j][c] = 0.f;

    uint32_t smem_u32 = (uint32_t)__cvta_generic_to_shared(smbuf);
    const int nk = K / BKK;

    gemm_issue_stage(smem_u32, 0, A, lda, B, ldb, M, m0, n0, 0, tid);
    cp_commit();
    gemm_issue_stage(smem_u32, 1, A, lda, B, ldb, M, m0, n0, BKK, tid);
    cp_commit();

    int st = 0;
    for (int kt = 0; kt < nk; kt++) {
        cp_wait1();
        __syncthreads();

        int nxt = kt + 2;
        if (nxt < nk) {
            int nst = st + 2;
            if (nst >= NSTAGE) nst -= NSTAGE;
            gemm_issue_stage(smem_u32, nst, A, lda, B, ldb, M, m0, n0, nxt * BKK, tid);
        }
        cp_commit();

        uint32_t s = smem_u32 + (uint32_t)st * STAGE_BYTES;
        uint32_t a_base = s;
        uint32_t b_base = s + ASZ * 2;

        // ---- preload ALL B fragments for both k-steps (latencies overlap) ----
        uint32_t bf[2][4][2];
        #pragma unroll
        for (int ks = 0; ks < 2; ks++) {
            int brow = ks * 16 + ((lane >> 3) & 1) * 8 + (lane & 7);
            #pragma unroll
            for (int j = 0; j < 2; j++) {
                int bcol = wn + j * 16 + (lane >> 4) * 8;
                uint32_t off = (uint32_t)((brow * BSTR + bcol) * 2);
                uint32_t th[4];
                ldsm_x4_t(b_base + off, th);
                bf[ks][2 * j][0] = th[0];
                bf[ks][2 * j][1] = th[1];
                bf[ks][2 * j + 1][0] = th[2];
                bf[ks][2 * j + 1][1] = th[3];
            }
        }

        // ---- A-fragment ping-pong over 8 (ks, mi) iterations ----
        int arow = lane & 15;
        int acolh = (lane >> 4) * 8;
        uint32_t af[2][4];
        ldsm_x4(a_base + (uint32_t)(((wm + arow) * ASTR + acolh) * 2), af[0]);
        #pragma unroll
        for (int it = 0; it < 8; it++) {
            int cur = it & 1;
            if (it < 7) {
                int nit = it + 1;
                int nks = nit >> 2, nmi = nit & 3;
                uint32_t off = (uint32_t)(((wm + nmi * 16 + arow) * ASTR + nks * 16 + acolh) * 2);
                ldsm_x4(a_base + off, af[cur ^ 1]);
            }
            int ks = it >> 2, mi = it & 3;
            #pragma unroll
            for (int ni = 0; ni < 4; ni++) {
                mma_f16(acc[mi][ni], af[cur], bf[ks][ni]);
            }
        }

        st = (st + 1 == NSTAGE) ? 0 : st + 1;
    }

    // ---- epilogue ----
    #pragma unroll
    for (int mi = 0; mi < 4; mi++) {
        int r0 = m0 + wm + mi * 16 + (lane >> 2);
        #pragma unroll
        for (int ni = 0; ni < 4; ni++) {
            int c0 = n0 + wn + ni * 8 + (lane & 3) * 2;
            #pragma unroll
            for (int half = 0; half < 2; half++) {
                int r = r0 + half * 8;
                if (r >= M) continue;
                #pragma unroll
                for (int e = 0; e < 2; e++) {
                    int c = c0 + e;
                    float val = acc[mi][ni][half * 2 + e];
                    if (flags & FLAG_BIAS) val += bias[c];
                    if (flags & FLAG_GELU) val = gelu_exact(val);
                    if (flags & FLAG_HALF_OUT) {
                        Ch[(size_t)r * ldc + c] = __float2half(val);
                    } else {
                        float* p = &C[(size_t)r * ldc + c];
                        if (flags & FLAG_RES) *p += val; else *p = val;
                    }
                }
            }
        }
    }
}

// ================= fused QKV + attention: block per (n, head) =================
#define AT_ROWS 208
#define AT_STR 72
#define HS_ELEMS (AT_ROWS * AT_STR)          // 14976
#define WS_ELEMS (3 * 64 * AT_STR)           // 13824
#define FUSED_SMEM_BYTES ((HS_ELEMS + WS_ELEMS + 3 * HS_ELEMS) * 2)   // 147456

__global__ __launch_bounds__(256, 1) void qkv_attn_fused(
    const __half* __restrict__ hbuf,
    const float* __restrict__ Wq, const float* __restrict__ Wk, const float* __restrict__ Wv,
    const float* __restrict__ bq, const float* __restrict__ bk, const float* __restrict__ bv,
    float* __restrict__ x)
{
    extern __shared__ __half fsm[];
    __half* Hs = fsm;
    __half* Ws = Hs + HS_ELEMS;
    __half* Qs = Ws + WS_ELEMS;
    __half* Ks = Qs + HS_ELEMS;
    __half* Vs = Ks + HS_ELEMS;

    int nh = blockIdx.x;
    int n = nh / HH, h = nh - n * HH;
    int tid = threadIdx.x;
    int warp = tid >> 5, lane = tid & 31;

    for (int idx = tid; idx < AT_ROWS * 8; idx += 256) {
        int t = idx >> 3;
        int c8 = (idx & 7) * 8;
        uint4 hv = make_uint4(0, 0, 0, 0);
        if (t < SS) hv = *(const uint4*)(hbuf + ((size_t)(n * SS + t)) * DD + h * DH + c8);
        *(uint4*)(Hs + t * AT_STR + c8) = hv;
    }
    const float* wsrc[3] = {Wq + h * DH * DH, Wk + h * DH * DH, Wv + h * DH * DH};
    for (int idx = tid; idx < 3 * DH * DH; idx += 256) {
        int mat = idx >> 12;
        int rem = idx & 4095;
        int d = rem >> 6, e = rem & 63;
        Ws[mat * 64 * AT_STR + d * AT_STR + e] = __float2half(wsrc[mat][d * 64 + e]);
    }
    __syncthreads();

    uint32_t h_base = (uint32_t)__cvta_generic_to_shared(Hs);
    uint32_t w_base = (uint32_t)__cvta_generic_to_shared(Ws);
    uint32_t q_base = (uint32_t)__cvta_generic_to_shared(Qs);
    uint32_t k_base = (uint32_t)__cvta_generic_to_shared(Ks);
    uint32_t v_base = (uint32_t)__cvta_generic_to_shared(Vs);

    const float* bsrc0 = bq + h * DH;
    const float* bsrc1 = bk + h * DH;
    const float* bsrc2 = bv + h * DH;
    __half* outs[3] = {Qs, Ks, Vs};

    // ---- QKV compute into smem ----
    #pragma unroll 1
    for (int pass = 0; pass < 2; pass++) {
        int mt = warp + pass * 8;
        if (mt >= 13) break;
        int s0 = mt * 16;

        float acc[3][8][4];
        #pragma unroll
        for (int m = 0; m < 3; m++)
            #pragma unroll
            for (int j = 0; j < 8; j++) {
                acc[m][j][0] = 0.f; acc[m][j][1] = 0.f;
                acc[m][j][2] = 0.f; acc[m][j][3] = 0.f;
            }

        #pragma unroll
        for (int ks = 0; ks < 4; ks++) {
            int kc = ks * 16;
            uint32_t af[4];
            uint32_t aoff = (uint32_t)(((s0 + (lane & 15)) * AT_STR + kc + (lane >> 4) * 8) * 2);
            ldsm_x4(h_base + aoff, af);
            int brow = kc + ((lane >> 3) & 1) * 8 + (lane & 7);
            #pragma unroll
            for (int mat = 0; mat < 3; mat++) {
                #pragma unroll
                for (int j = 0; j < 4; j++) {
                    int bcol = j * 16 + (lane >> 4) * 8;
                    uint32_t th[4];
                    ldsm_x4_t(w_base + (uint32_t)((mat * 64 * AT_STR + brow * AT_STR + bcol) * 2), th);
                    mma_f16(acc[mat][2 * j],     af, th);
                    mma_f16(acc[mat][2 * j + 1], af, th + 2);
                }
            }
        }

        const float* bp[3] = {bsrc0, bsrc1, bsrc2};
        #pragma unroll
        for (int mat = 0; mat < 3; mat++) {
            #pragma unroll
            for (int half = 0; half < 2; half++) {
                int r = s0 + (lane >> 2) + half * 8;
                __half* orow = outs[mat] + r * AT_STR;
                #pragma unroll
                for (int nj = 0; nj < 8; nj++) {
                    int col = nj * 8 + (lane & 3) * 2;
                    __half2 hv = __floats2half2_rn(acc[mat][nj][half * 2]     + bp[mat][col],
                                                   acc[mat][nj][half * 2 + 1] + bp[mat][col + 1]);
                    *(__half2*)&orow[col] = hv;
                }
            }
        }
    }
    __syncthreads();

    // ---- attention ----
    const float scale = 0.125f;
    #pragma unroll 1
    for (int pass = 0; pass < 2; pass++) {
        int mt = warp + pass * 8;
        if (mt >= 13) break;
        int s0 = mt * 16;

        float c[26][4];
        #pragma unroll
        for (int j = 0; j < 26; j++) {
            c[j][0] = 0.f; c[j][1] = 0.f; c[j][2] = 0.f; c[j][3] = 0.f;
        }
        #pragma unroll
        for (int ks = 0; ks < 4; ks++) {
            int kc = ks * 16;
            uint32_t a[4];
            uint32_t aoff = (uint32_t)(((s0 + (lane & 15)) * AT_STR + kc + (lane >> 4) * 8) * 2);
            ldsm_x4(q_base + aoff, a);
            #pragma unroll
            for (int j = 0; j < 13; j++) {
                uint32_t b[4];
                int nrow = j * 16 + (lane >> 4) * 8 + (lane & 7);
                int ncol = kc + ((lane >> 3) & 1) * 8;
                ldsm_x4(k_base + (uint32_t)((nrow * AT_STR + ncol) * 2), b);
                mma_f16(c[2 * j],     a, b);
                mma_f16(c[2 * j + 1], a, b + 2);
            }
        }

        float mx0 = -1e30f, mx1 = -1e30f;
        #pragma unroll
        for (int j = 0; j < 26; j++) {
            int tcol = j * 8 + (lane & 3) * 2;
            #pragma unroll
            for (int e = 0; e < 2; e++) {
                float s0v = c[j][e] * scale;
                float s1v = c[j][2 + e] * scale;
                if (tcol + e >= SS) { s0v = -1e30f; s1v = -1e30f; }
                c[j][e] = s0v;
                c[j][2 + e] = s1v;
                mx0 = fmaxf(mx0, s0v);
                mx1 = fmaxf(mx1, s1v);
            }
        }
        mx0 = fmaxf(mx0, __shfl_xor_sync(0xffffffffu, mx0, 1));
        mx0 = fmaxf(mx0, __shfl_xor_sync(0xffffffffu, mx0, 2));
        mx1 = fmaxf(mx1, __shfl_xor_sync(0xffffffffu, mx1, 1));
        mx1 = fmaxf(mx1, __shfl_xor_sync(0xffffffffu, mx1, 2));

        float sum0 = 0.f, sum1 = 0.f;
        #pragma unroll
        for (int j = 0; j < 26; j++) {
            #pragma unroll
            for (int e = 0; e < 2; e++) {
                float p0 = __expf(c[j][e] - mx0);
                float p1 = __expf(c[j][2 + e] - mx1);
                c[j][e] = p0;
                c[j][2 + e] = p1;
                sum0 += p0;
                sum1 += p1;
            }
        }
        sum0 += __shfl_xor_sync(0xffffffffu, sum0, 1);
        sum0 += __shfl_xor_sync(0xffffffffu, sum0, 2);
        sum1 += __shfl_xor_sync(0xffffffffu, sum1, 1);
        sum1 += __shfl_xor_sync(0xffffffffu, sum1, 2);
        float inv0 = 1.0f / sum0;
        float inv1 = 1.0f / sum1;

        float o[8][4];
        #pragma unroll
        for (int j = 0; j < 8; j++) {
            o[j][0] = 0.f; o[j][1] = 0.f; o[j][2] = 0.f; o[j][3] = 0.f;
        }
        #pragma unroll
        for (int j = 0; j < 13; j++) {
            uint32_t a[4];
            __half2 h0 = __floats2half2_rn(c[2 * j][0] * inv0, c[2 * j][1] * inv0);
            __half2 h1 = __floats2half2_rn(c[2 * j][2] * inv1, c[2 * j][3] * inv1);
            __half2 h2 = __floats2half2_rn(c[2 * j + 1][0] * inv0, c[2 * j + 1][1] * inv0);
            __half2 h3 = __floats2half2_rn(c[2 * j + 1][2] * inv1, c[2 * j + 1][3] * inv1);
            a[0] = *(uint32_t*)&h0;
            a[1] = *(uint32_t*)&h1;
            a[2] = *(uint32_t*)&h2;
            a[3] = *(uint32_t*)&h3;
            int brow = j * 16 + ((lane >> 3) & 1) * 8 + (lane & 7);
            #pragma unroll
            for (int nj = 0; nj < 4; nj++) {
                uint32_t b[4];
                int bcol = nj * 16 + (lane >> 4) * 8;
                ldsm_x4_t(v_base + (uint32_t)((brow * AT_STR + bcol) * 2), b);
                mma_f16(o[2 * nj],     a, b);
                mma_f16(o[2 * nj + 1], a, b + 2);
            }
        }

        int rloc = lane >> 2;
        #pragma unroll
        for (int half = 0; half < 2; half++) {
            int srow = s0 + rloc + half * 8;
            if (srow >= SS) continue;
            float* xr = x + ((size_t)(n * SS + srow)) * DD + h * DH;
            #pragma unroll
            for (int nj = 0; nj < 8; nj++) {
                int col = nj * 8 + (lane & 3) * 2;
                xr[col]     += o[nj][half * 2];
                xr[col + 1] += o[nj][half * 2 + 1];
            }
        }
    }
}

// ---------------- small GEMM (classification head) ----------------
__global__ __launch_bounds__(256) void gemm64(const float* __restrict__ A, long long lda, long long strideA,
                                              const float* __restrict__ B, int ldb, long long strideB,
                                              float* __restrict__ C, int ldc, long long strideC,
                                              const float* __restrict__ bias, long long strideBias,
                                              int M, int N, int K, int flags) {
    int bz = blockIdx.z;
    A += (size_t)bz * strideA;
    B += (size_t)bz * strideB;
    C += (size_t)bz * strideC;
    if (bias) bias += (size_t)bz * strideBias;

    __shared__ float As[16][64];
    __shared__ float Bs[16][68];
    int tid = threadIdx.x;
    int m0 = blockIdx.y * 64, n0 = blockIdx.x * 64;
    int arow = tid >> 2, akcol = (tid & 3) * 4;
    int brow = tid >> 4, bcol = (tid & 15) * 4;
    int tx = tid & 15, ty = tid >> 4;

    float acc[4][4];
    #pragma unroll
    for (int i = 0; i < 4; i++)
        #pragma unroll
        for (int j = 0; j < 4; j++) acc[i][j] = 0.f;

    for (int k0 = 0; k0 < K; k0 += 16) {
        float4 a4 = make_float4(0.f, 0.f, 0.f, 0.f);
        int gm = m0 + arow;
        if (gm < M) a4 = *(const float4*)&A[(size_t)gm * lda + k0 + akcol];
        As[akcol + 0][arow] = a4.x;
        As[akcol + 1][arow] = a4.y;
        As[akcol + 2][arow] = a4.z;
        As[akcol + 3][arow] = a4.w;

        float4 b4;
        int gn = n0 + bcol;
        const float* Brow = &B[(size_t)(k0 + brow) * ldb];
        if (gn + 3 < N) {
            b4 = *(const float4*)&Brow[gn];
        } else {
            b4.x = (gn + 0 < N) ? Brow[gn + 0] : 0.f;
            b4.y = (gn + 1 < N) ? Brow[gn + 1] : 0.f;
            b4.z = (gn + 2 < N) ? Brow[gn + 2] : 0.f;
            b4.w = (gn + 3 < N) ? Brow[gn + 3] : 0.f;
        }
        *(float4*)&Bs[brow][bcol] = b4;
        __syncthreads();

        #pragma unroll
        for (int kk = 0; kk < 16; kk++) {
            float4 a0 = *(float4*)&As[kk][ty * 4];
            float4 b0 = *(float4*)&Bs[kk][tx * 4];
            float ar[4] = {a0.x, a0.y, a0.z, a0.w};
            float br[4] = {b0.x, b0.y, b0.z, b0.w};
            #pragma unroll
            for (int i = 0; i < 4; i++)
                #pragma unroll
                for (int j = 0; j < 4; j++) acc[i][j] += ar[i] * br[j];
        }
        __syncthreads();
    }

    #pragma unroll
    for (int i = 0; i < 4; i++) {
        int r = m0 + ty * 4 + i;
        if (r >= M) continue;
        #pragma unroll
        for (int j = 0; j < 4; j++) {
            int c = n0 + tx * 4 + j;
            if (c >= N) continue;
            float val = acc[i][j];
            if (flags & FLAG_BIAS) val += bias[c];
            if (flags & FLAG_GELU) val = gelu_exact(val);
            float* p = &C[(size_t)r * ldc + c];
            if (flags & FLAG_RES) *p += val; else *p = val;
        }
    }
}

// ---------------- final softmax over 1000 classes ----------------
__global__ __launch_bounds__(256) void softmax_out(const float* __restrict__ logits,
                                                   float* __restrict__ out) {
    int n = blockIdx.x;
    int tid = threadIdx.x;
    const float* l = logits + (size_t)n * OUTC;
    __shared__ float sh[8];
    int lane = tid & 31, wp = tid >> 5;

    float mx = -1e30f;
    for (int c = tid; c < OUTC; c += 256) mx = fmaxf(mx, l[c]);
    #pragma unroll
    for (int o = 16; o; o >>= 1) mx = fmaxf(mx, __shfl_xor_sync(0xffffffffu, mx, o));
    if (lane == 0) sh[wp] = mx;
    __syncthreads();
    float gmx = sh[0];
    #pragma unroll
    for (int i = 1; i < 8; i++) gmx = fmaxf(gmx, sh[i]);
    __syncthreads();

    float sum = 0.f;
    for (int c = tid; c < OUTC; c += 256) sum += __expf(l[c] - gmx);
    #pragma unroll
    for (int o = 16; o; o >>= 1) sum += __shfl_xor_sync(0xffffffffu, sum, o);
    if (lane == 0) sh[wp] = sum;
    __syncthreads();
    float tot = 0.f;
    #pragma unroll
    for (int i = 0; i < 8; i++) tot += sh[i];
    float inv = 1.0f / tot;

    for (int c = tid; c < OUTC; c += 256) out[(size_t)n * OUTC + c] = __expf(l[c] - gmx) * inv;
}

// ---------------- launch ----------------
extern "C" void kernel_launch(void* const* d_in, const int* in_sizes, int n_in,
                              void* d_out, int out_size) {
    const float* images = (const float*)d_in[0];
    const float* Wm     = (const float*)d_in[1];
    const float* bm     = (const float*)d_in[2];
    const float* cls    = (const float*)d_in[3];
    const float* pos    = (const float*)d_in[4];
    const float* ln1w   = (const float*)d_in[5];
    const float* ln1b   = (const float*)d_in[6];
    const float* Wq     = (const float*)d_in[7];
    const float* bq     = (const float*)d_in[8];
    const float* Wk     = (const float*)d_in[9];
    const float* bk     = (const float*)d_in[10];
    const float* Wv     = (const float*)d_in[11];
    const float* bv     = (const float*)d_in[12];
    const float* ln2w   = (const float*)d_in[13];
    const float* ln2b   = (const float*)d_in[14];
    const float* W1     = (const float*)d_in[15];
    const float* b1     = (const float*)d_in[16];
    const float* W2     = (const float*)d_in[17];
    const float* b2     = (const float*)d_in[18];
    const float* Wout   = (const float*)d_in[19];
    const float* bout   = (const float*)d_in[20];
    float* out = (float*)d_out;

    float *p_x, *p_h, *p_logits;
    cudaGetSymbolAddress((void**)&p_x, g_x);
    cudaGetSymbolAddress((void**)&p_h, g_h);
    cudaGetSymbolAddress((void**)&p_logits, g_logits);

    __half *p_patch, *p_hh, *p_u, *p_Wm, *p_W1, *p_W2;
    cudaGetSymbolAddress((void**)&p_patch, g_patch_f16);
    cudaGetSymbolAddress((void**)&p_hh, g_h_f16);
    cudaGetSymbolAddress((void**)&p_u, g_u_f16);
    cudaGetSymbolAddress((void**)&p_Wm, g_Wm_f16);
    cudaGetSymbolAddress((void**)&p_W1, g_W1_f16);
    cudaGetSymbolAddress((void**)&p_W2, g_W2_f16);

    cudaFuncSetAttribute(qkv_attn_fused, cudaFuncAttributeMaxDynamicSharedMemorySize, FUSED_SMEM_BYTES);
    cudaFuncSetAttribute(gemm_f16, cudaFuncAttributeMaxDynamicSharedMemorySize, GEMM_SMEM_BYTES);

    // ---- one-time weight conversions ----
    conv_f16<<<(DD * DD / 4 + 255) / 256, 256>>>(Wm, p_Wm, DD * DD);
    conv_f16<<<(LL * DD * FF / 4 + 255) / 256, 256>>>(W1, p_W1, LL * DD * FF);
    conv_f16<<<(LL * FF * DD / 4 + 255) / 256, 256>>>(W2, p_W2, LL * FF * DD);

    // ---- patch extraction + embed GEMM ----
    extract_patches<<<(PROWS * DD + 255) / 256, 256>>>(images, p_patch);
    gemm_f16<<<dim3(DD / 128, (PROWS + 127) / 128), 256, GEMM_SMEM_BYTES>>>(
        p_patch, DD, p_Wm, DD,
        p_h, nullptr, DD, bm, PROWS, DD, DD, FLAG_BIAS);
    assemble<<<(ROWS * DD + 255) / 256, 256>>>(p_h, cls, pos, p_x);

    for (int l = 0; l < LL; l++) {
        ln_warp<<<ROWS / 8, 256>>>(p_x, ln1w + l * DD, ln1b + l * DD, p_hh);

        qkv_attn_fused<<<NN * HH, 256, FUSED_SMEM_BYTES>>>(
            p_hh,
            Wq + (size_t)l * HH * DH * DH, Wk + (size_t)l * HH * DH * DH, Wv + (size_t)l * HH * DH * DH,
            bq + (size_t)l * DD, bk + (size_t)l * DD, bv + (size_t)l * DD,
            p_x);

        ln_warp<<<ROWS / 8, 256>>>(p_x, ln2w + l * DD, ln2b + l * DD, p_hh);

        gemm_f16<<<dim3(FF / 128, (ROWS + 127) / 128), 256, GEMM_SMEM_BYTES>>>(
            p_hh, DD,
            p_W1 + (size_t)l * DD * FF, FF,
            nullptr, p_u, FF, b1 + (size_t)l * FF,
            ROWS, FF, DD, FLAG_BIAS | FLAG_GELU | FLAG_HALF_OUT);

        gemm_f16<<<dim3(DD / 128, (ROWS + 127) / 128), 256, GEMM_SMEM_BYTES>>>(
            p_u, FF,
            p_W2 + (size_t)l * FF * DD, DD,
            p_x, nullptr, DD, b2 + (size_t)l * DD,
            ROWS, DD, FF, FLAG_BIAS | FLAG_RES);
    }

    // classification head: cls rows have stride SS*DD
    gemm64<<<dim3((OUTC + 63) / 64, 1, 1), 256>>>(
        p_x, (long long)SS * DD, 0,
        Wout, OUTC, 0,
        p_logits, OUTC, 0,
        bout, 0,
        NN, OUTC, DD, FLAG_BIAS);

    softmax_out<<<NN, 256>>>(p_logits, out);
}

// round 13
// speedup vs baseline: 5.7679x; 1.0819x over previous
#include <cuda_runtime.h>
#include <cuda_fp16.h>
#include <math.h>
#include <stdint.h>

// ---------------- problem constants ----------------
#define NN 32
#define CC 3
#define NP 14
#define PS 16
#define DD 768
#define HH 12
#define DH 64
#define SS 197
#define LL 8
#define FF 3072
#define OUTC 1000
#define NPATCH (NP*NP)    // 196
#define ROWS (NN*SS)      // 6304
#define PROWS (NN*NPATCH) // 6272

#define FLAG_BIAS 1
#define FLAG_GELU 2
#define FLAG_RES  4
#define FLAG_HALF_OUT 8

// ---------------- scratch (device globals; no runtime allocation) ----------------
__device__ float g_x[ROWS * DD];
__device__ float g_h[ROWS * DD];
__device__ float g_lpart[4 * NN * OUTC];

__device__ __half g_patch_f16[PROWS * DD];
__device__ __half g_h_f16[ROWS * DD];
__device__ __half g_u_f16[ROWS * FF];
__device__ __half g_Wm_f16[DD * DD];
__device__ __half g_W1_f16[LL * DD * FF];
__device__ __half g_W2_f16[LL * FF * DD];

__device__ __forceinline__ float gelu_exact(float x) {
    return 0.5f * x * (1.0f + erff(x * 0.70710678118654752f));
}

// ---------------- fp32 -> fp16 conversion ----------------
__global__ void conv_f16(const float* __restrict__ src, __half* __restrict__ dst, int n) {
    int i = (blockIdx.x * blockDim.x + threadIdx.x) * 4;
    if (i >= n) return;
    float4 v = *(const float4*)&src[i];
    __half2* d = (__half2*)&dst[i];
    d[0] = __floats2half2_rn(v.x, v.y);
    d[1] = __floats2half2_rn(v.z, v.w);
}

// ---------------- patch extraction (writes fp16) ----------------
__global__ void extract_patches(const float* __restrict__ images,
                                __half* __restrict__ P) {
    int idx = blockIdx.x * blockDim.x + threadIdx.x;
    if (idx >= PROWS * DD) return;
    int row = idx / DD;
    int col = idx - row * DD;
    int n = row / NPATCH;
    int p = row - n * NPATCH;
    int py = p / NP, px = p - py * NP;
    int c = col / (PS * PS);
    int r = col - c * PS * PS;
    int i = r / PS, j = r - i * PS;
    int H = NP * PS;
    float v = images[(((size_t)n * CC + c) * H + (py * PS + i)) * H + (px * PS + j)];
    P[idx] = __float2half(v);
}

// ---------------- assemble tokens + cls + pos ----------------
__global__ void assemble(const float* __restrict__ tok, const float* __restrict__ cls,
                         const float* __restrict__ pos, float* __restrict__ x) {
    int idx = blockIdx.x * blockDim.x + threadIdx.x;
    if (idx >= ROWS * DD) return;
    int row = idx / DD;
    int d = idx - row * DD;
    int n = row / SS;
    int s = row - n * SS;
    float v;
    if (s == 0) v = cls[d];
    else        v = tok[((size_t)n * NPATCH + (s - 1)) * DD + d];
    x[idx] = v + pos[(size_t)s * DD + d];
}

// ---------------- warp-per-row layernorm -> fp16 out (no barriers) ----------------
__global__ __launch_bounds__(256) void ln_warp(const float* __restrict__ x,
                                               const float* __restrict__ w,
                                               const float* __restrict__ b,
                                               __half* __restrict__ oh) {
    int warp = threadIdx.x >> 5, lane = threadIdx.x & 31;
    int row = blockIdx.x * 8 + warp;
    const float* xr = x + (size_t)row * DD;

    float4 v[6];
    float s = 0.f;
    #pragma unroll
    for (int i = 0; i < 6; i++) {
        v[i] = *(const float4*)&xr[(lane + 32 * i) * 4];
        s += v[i].x + v[i].y + v[i].z + v[i].w;
    }
    #pragma unroll
    for (int o = 16; o; o >>= 1) s += __shfl_xor_sync(0xffffffffu, s, o);
    float mean = s * (1.0f / DD);

    float sq = 0.f;
    #pragma unroll
    for (int i = 0; i < 6; i++) {
        v[i].x -= mean; v[i].y -= mean; v[i].z -= mean; v[i].w -= mean;
        sq += v[i].x * v[i].x + v[i].y * v[i].y + v[i].z * v[i].z + v[i].w * v[i].w;
    }
    #pragma unroll
    for (int o = 16; o; o >>= 1) sq += __shfl_xor_sync(0xffffffffu, sq, o);
    float rstd = rsqrtf(sq * (1.0f / DD) + 1e-5f);

    __half* orow = oh + (size_t)row * DD;
    #pragma unroll
    for (int i = 0; i < 6; i++) {
        int c = (lane + 32 * i) * 4;
        float4 wv = *(const float4*)&w[c];
        float4 bv = *(const float4*)&b[c];
        float r0 = v[i].x * rstd * wv.x + bv.x;
        float r1 = v[i].y * rstd * wv.y + bv.y;
        float r2 = v[i].z * rstd * wv.z + bv.z;
        float r3 = v[i].w * rstd * wv.w + bv.w;
        __half2 h01 = __floats2half2_rn(r0, r1);
        __half2 h23 = __floats2half2_rn(r2, r3);
        uint2 pk;
        pk.x = *(uint32_t*)&h01;
        pk.y = *(uint32_t*)&h23;
        *(uint2*)&orow[c] = pk;
    }
}

// ================= fp16 tensor-core GEMM (3-stage pipeline) ==========
#define BM 128
#define BN 128
#define BKK 32
#define ASTR 40
#define BSTR 136
#define ASZ (BM*ASTR)
#define BSZ (BKK*BSTR)
#define STAGE_ELEMS (ASZ + BSZ)
#define STAGE_BYTES (STAGE_ELEMS*2)
#define NSTAGE 3
#define GEMM_SMEM_BYTES (NSTAGE * STAGE_BYTES)

__device__ __forceinline__ void ldsm_x4(uint32_t addr, uint32_t* r) {
    asm volatile("ldmatrix.sync.aligned.m8n8.x4.shared.b16 {%0,%1,%2,%3}, [%4];\n"
                 : "=r"(r[0]), "=r"(r[1]), "=r"(r[2]), "=r"(r[3]) : "r"(addr));
}
__device__ __forceinline__ void ldsm_x4_t(uint32_t addr, uint32_t* r) {
    asm volatile("ldmatrix.sync.aligned.m8n8.x4.trans.shared.b16 {%0,%1,%2,%3}, [%4];\n"
                 : "=r"(r[0]), "=r"(r[1]), "=r"(r[2]), "=r"(r[3]) : "r"(addr));
}
__device__ __forceinline__ void mma_f16(float* c, const uint32_t* a, const uint32_t* b) {
    asm volatile("mma.sync.aligned.m16n8k16.row.col.f32.f16.f16.f32 "
                 "{%0,%1,%2,%3},{%4,%5,%6,%7},{%8,%9},{%0,%1,%2,%3};\n"
                 : "+f"(c[0]), "+f"(c[1]), "+f"(c[2]), "+f"(c[3])
                 : "r"(a[0]), "r"(a[1]), "r"(a[2]), "r"(a[3]), "r"(b[0]), "r"(b[1]));
}
__device__ __forceinline__ void cpa16(uint32_t dst, const void* src, int bytes) {
    asm volatile("cp.async.cg.shared.global [%0], [%1], 16, %2;\n"
                 :: "r"(dst), "l"(src), "r"(bytes));
}
__device__ __forceinline__ void cp_commit() {
    asm volatile("cp.async.commit_group;\n");
}
__device__ __forceinline__ void cp_wait1() {
    asm volatile("cp.async.wait_group 1;\n");
}

__device__ __forceinline__ void gemm_issue_stage(
    uint32_t smem_u32, int stage,
    const __half* __restrict__ A, int lda,
    const __half* __restrict__ B, int ldb,
    int M, int m0, int n0, int kb, int tid)
{
    uint32_t s = smem_u32 + (uint32_t)stage * STAGE_BYTES;
    uint32_t sA = s;
    uint32_t sB = s + ASZ * 2;
    #pragma unroll
    for (int i = 0; i < 2; i++) {
        int chunk = tid + 256 * i;
        int row = chunk >> 2;
        int c16 = chunk & 3;
        int gr = m0 + row;
        int bytes = (gr < M) ? 16 : 0;
        size_t goff = (size_t)gr * lda + kb + c16 * 8;
        uint32_t doff = (uint32_t)(row * ASTR + c16 * 8) * 2;
        cpa16(sA + doff, A + goff, bytes);
    }
    #pragma unroll
    for (int i = 0; i < 2; i++) {
        int chunk = tid + 256 * i;
        int row = chunk >> 4;
        int c16 = chunk & 15;
        size_t goff = (size_t)(kb + row) * ldb + n0 + c16 * 8;
        uint32_t doff = (uint32_t)(row * BSTR + c16 * 8) * 2;
        cpa16(sB + doff, B + goff, 16);
    }
}

__global__ __launch_bounds__(256, 2) void gemm_f16(
    const __half* __restrict__ A, int lda,
    const __half* __restrict__ B, int ldb,
    float* __restrict__ C, __half* __restrict__ Ch,
    int ldc, const float* __restrict__ bias,
    int M, int N, int K, int flags)
{
    extern __shared__ __half smbuf[];
    int tid = threadIdx.x;
    int m0 = blockIdx.y * BM;
    int n0 = blockIdx.x * BN;
    int warp = tid >> 5;
    int lane = tid & 31;
    int wm = (warp >> 2) * 64;
    int wn = (warp & 3) * 32;

    float acc[4][4][4];
    #pragma unroll
    for (int i = 0; i < 4; i++)
        #pragma unroll
        for (int j = 0; j < 4; j++)
            #pragma unroll
            for (int c = 0; c < 4; c++) acc[i][j][c] = 0.f;

    uint32_t smem_u32 = (uint32_t)__cvta_generic_to_shared(smbuf);
    const int nk = K / BKK;

    gemm_issue_stage(smem_u32, 0, A, lda, B, ldb, M, m0, n0, 0, tid);
    cp_commit();
    gemm_issue_stage(smem_u32, 1, A, lda, B, ldb, M, m0, n0, BKK, tid);
    cp_commit();

    int st = 0;
    for (int kt = 0; kt < nk; kt++) {
        cp_wait1();
        __syncthreads();

        int nxt = kt + 2;
        if (nxt < nk) {
            int nst = st + 2;
            if (nst >= NSTAGE) nst -= NSTAGE;
            gemm_issue_stage(smem_u32, nst, A, lda, B, ldb, M, m0, n0, nxt * BKK, tid);
        }
        cp_commit();

        uint32_t s = smem_u32 + (uint32_t)st * STAGE_BYTES;
        uint32_t a_base = s;
        uint32_t b_base = s + ASZ * 2;

        #pragma unroll
        for (int ks = 0; ks < 2; ks++) {
            int kc = ks * 16;
            uint32_t bf[4][2];
            int brow = kc + ((lane >> 3) & 1) * 8 + (lane & 7);
            #pragma unroll
            for (int j = 0; j < 2; j++) {
                int bcol = wn + j * 16 + (lane >> 4) * 8;
                uint32_t off = (uint32_t)((brow * BSTR + bcol) * 2);
                uint32_t th[4];
                ldsm_x4_t(b_base + off, th);
                bf[2 * j][0] = th[0];
                bf[2 * j][1] = th[1];
                bf[2 * j + 1][0] = th[2];
                bf[2 * j + 1][1] = th[3];
            }
            int arow = lane & 15;
            int acol = kc + (lane >> 4) * 8;
            #pragma unroll
            for (int mi = 0; mi < 4; mi++) {
                uint32_t af[4];
                uint32_t off = (uint32_t)(((wm + mi * 16 + arow) * ASTR + acol) * 2);
                ldsm_x4(a_base + off, af);
                #pragma unroll
                for (int ni = 0; ni < 4; ni++) {
                    mma_f16(acc[mi][ni], af, bf[ni]);
                }
            }
        }

        st = (st + 1 == NSTAGE) ? 0 : st + 1;
    }

    // ---- epilogue ----
    #pragma unroll
    for (int mi = 0; mi < 4; mi++) {
        int r0 = m0 + wm + mi * 16 + (lane >> 2);
        #pragma unroll
        for (int ni = 0; ni < 4; ni++) {
            int c0 = n0 + wn + ni * 8 + (lane & 3) * 2;
            #pragma unroll
            for (int half = 0; half < 2; half++) {
                int r = r0 + half * 8;
                if (r >= M) continue;
                #pragma unroll
                for (int e = 0; e < 2; e++) {
                    int c = c0 + e;
                    float val = acc[mi][ni][half * 2 + e];
                    if (flags & FLAG_BIAS) val += bias[c];
                    if (flags & FLAG_GELU) val = gelu_exact(val);
                    if (flags & FLAG_HALF_OUT) {
                        Ch[(size_t)r * ldc + c] = __float2half(val);
                    } else {
                        float* p = &C[(size_t)r * ldc + c];
                        if (flags & FLAG_RES) *p += val; else *p = val;
                    }
                }
            }
        }
    }
}

// ================= fused QKV + attention: block per (n, head), 13 warps ==========
// smem: Hs[208][72] + Ws[3][64][72] + Ks[208][72] + Vs[208][72]; Q lives in registers.
#define AT_ROWS 208
#define AT_STR 72
#define HS_ELEMS (AT_ROWS * AT_STR)          // 14976
#define WS_ELEMS (3 * 64 * AT_STR)           // 13824
#define FUSED_SMEM_BYTES ((2 * HS_ELEMS + WS_ELEMS + HS_ELEMS) * 2)   // 117504
#define FW_THREADS 416

__global__ __launch_bounds__(FW_THREADS, 1) void qkv_attn_fused(
    const __half* __restrict__ hbuf,
    const float* __restrict__ Wq, const float* __restrict__ Wk, const float* __restrict__ Wv,
    const float* __restrict__ bq, const float* __restrict__ bk, const float* __restrict__ bv,
    float* __restrict__ x)
{
    extern __shared__ __half fsm[];
    __half* Hs = fsm;
    __half* Ws = Hs + HS_ELEMS;
    __half* Ks = Ws + WS_ELEMS;
    __half* Vs = Ks + HS_ELEMS;

    int nh = blockIdx.x;
    int n = nh / HH, h = nh - n * HH;
    int tid = threadIdx.x;
    int warp = tid >> 5, lane = tid & 31;   // warp 0..12

    // ---- load h slice (zero-pad t >= SS): 1664 chunks / 416 threads = 4 each ----
    #pragma unroll
    for (int i = 0; i < 4; i++) {
        int idx = tid + i * FW_THREADS;
        int t = idx >> 3;
        int c8 = (idx & 7) * 8;
        uint4 hv = make_uint4(0, 0, 0, 0);
        if (t < SS) hv = *(const uint4*)(hbuf + ((size_t)(n * SS + t)) * DD + h * DH + c8);
        *(uint4*)(Hs + t * AT_STR + c8) = hv;
    }
    // ---- load + convert per-head weights ----
    const float* wsrc[3] = {Wq + h * DH * DH, Wk + h * DH * DH, Wv + h * DH * DH};
    for (int idx = tid; idx < 3 * DH * DH; idx += FW_THREADS) {
        int mat = idx >> 12;
        int rem = idx & 4095;
        int d = rem >> 6, e = rem & 63;
        Ws[mat * 64 * AT_STR + d * AT_STR + e] = __float2half(wsrc[mat][d * 64 + e]);
    }
    __syncthreads();

    uint32_t h_base = (uint32_t)__cvta_generic_to_shared(Hs);
    uint32_t w_base = (uint32_t)__cvta_generic_to_shared(Ws);
    uint32_t k_base = (uint32_t)__cvta_generic_to_shared(Ks);
    uint32_t v_base = (uint32_t)__cvta_generic_to_shared(Vs);

    int s0 = warp * 16;   // this warp's token tile (13 tiles cover all 208 rows)

    // ---- QKV MMAs ----
    float acc[3][8][4];
    #pragma unroll
    for (int m = 0; m < 3; m++)
        #pragma unroll
        for (int j = 0; j < 8; j++) {
            acc[m][j][0] = 0.f; acc[m][j][1] = 0.f;
            acc[m][j][2] = 0.f; acc[m][j][3] = 0.f;
        }

    #pragma unroll
    for (int ks = 0; ks < 4; ks++) {
        int kc = ks * 16;
        uint32_t af[4];
        uint32_t aoff = (uint32_t)(((s0 + (lane & 15)) * AT_STR + kc + (lane >> 4) * 8) * 2);
        ldsm_x4(h_base + aoff, af);
        int brow = kc + ((lane >> 3) & 1) * 8 + (lane & 7);
        #pragma unroll
        for (int mat = 0; mat < 3; mat++) {
            #pragma unroll
            for (int j = 0; j < 4; j++) {
                int bcol = j * 16 + (lane >> 4) * 8;
                uint32_t th[4];
                ldsm_x4_t(w_base + (uint32_t)((mat * 64 * AT_STR + brow * AT_STR + bcol) * 2), th);
                mma_f16(acc[mat][2 * j],     af, th);
                mma_f16(acc[mat][2 * j + 1], af, th + 2);
            }
        }
    }

    // ---- Q: bias + pack c-frag directly into A-frags (no smem) ----
    const float* bq_h = bq + h * DH;
    uint32_t qa[4][4];
    #pragma unroll
    for (int ks = 0; ks < 4; ks++) {
        int colA = 16 * ks + (lane & 3) * 2;
        int colB = colA + 8;
        float b0 = bq_h[colA], b1 = bq_h[colA + 1];
        float b2 = bq_h[colB], b3 = bq_h[colB + 1];
        __half2 t0 = __floats2half2_rn(acc[0][2 * ks][0] + b0, acc[0][2 * ks][1] + b1);
        __half2 t1 = __floats2half2_rn(acc[0][2 * ks][2] + b0, acc[0][2 * ks][3] + b1);
        __half2 t2 = __floats2half2_rn(acc[0][2 * ks + 1][0] + b2, acc[0][2 * ks + 1][1] + b3);
        __half2 t3 = __floats2half2_rn(acc[0][2 * ks + 1][2] + b2, acc[0][2 * ks + 1][3] + b3);
        qa[ks][0] = *(uint32_t*)&t0;
        qa[ks][1] = *(uint32_t*)&t1;
        qa[ks][2] = *(uint32_t*)&t2;
        qa[ks][3] = *(uint32_t*)&t3;
    }

    // ---- write K, V (+bias) to smem ----
    {
        const float* bk_h = bk + h * DH;
        const float* bv_h = bv + h * DH;
        #pragma unroll
        for (int half = 0; half < 2; half++) {
            int r = s0 + (lane >> 2) + half * 8;
            __half* krow = Ks + r * AT_STR;
            __half* vrow = Vs + r * AT_STR;
            #pragma unroll
            for (int nj = 0; nj < 8; nj++) {
                int col = nj * 8 + (lane & 3) * 2;
                __half2 kv = __floats2half2_rn(acc[1][nj][half * 2]     + bk_h[col],
                                               acc[1][nj][half * 2 + 1] + bk_h[col + 1]);
                __half2 vv = __floats2half2_rn(acc[2][nj][half * 2]     + bv_h[col],
                                               acc[2][nj][half * 2 + 1] + bv_h[col + 1]);
                *(__half2*)&krow[col] = kv;
                *(__half2*)&vrow[col] = vv;
            }
        }
    }
    __syncthreads();

    // ---- scores ----
    const float scale = 0.125f;
    float c[26][4];
    #pragma unroll
    for (int j = 0; j < 26; j++) {
        c[j][0] = 0.f; c[j][1] = 0.f; c[j][2] = 0.f; c[j][3] = 0.f;
    }
    #pragma unroll
    for (int ks = 0; ks < 4; ks++) {
        int ncol = ks * 16 + ((lane >> 3) & 1) * 8;
        #pragma unroll
        for (int j = 0; j < 13; j++) {
            uint32_t b[4];
            int nrow = j * 16 + (lane >> 4) * 8 + (lane & 7);
            ldsm_x4(k_base + (uint32_t)((nrow * AT_STR + ncol) * 2), b);
            mma_f16(c[2 * j],     qa[ks], b);
            mma_f16(c[2 * j + 1], qa[ks], b + 2);
        }
    }

    // ---- scale + mask + softmax ----
    float mx0 = -1e30f, mx1 = -1e30f;
    #pragma unroll
    for (int j = 0; j < 26; j++) {
        int tcol = j * 8 + (lane & 3) * 2;
        #pragma unroll
        for (int e = 0; e < 2; e++) {
            float s0v = c[j][e] * scale;
            float s1v = c[j][2 + e] * scale;
            if (tcol + e >= SS) { s0v = -1e30f; s1v = -1e30f; }
            c[j][e] = s0v;
            c[j][2 + e] = s1v;
            mx0 = fmaxf(mx0, s0v);
            mx1 = fmaxf(mx1, s1v);
        }
    }
    mx0 = fmaxf(mx0, __shfl_xor_sync(0xffffffffu, mx0, 1));
    mx0 = fmaxf(mx0, __shfl_xor_sync(0xffffffffu, mx0, 2));
    mx1 = fmaxf(mx1, __shfl_xor_sync(0xffffffffu, mx1, 1));
    mx1 = fmaxf(mx1, __shfl_xor_sync(0xffffffffu, mx1, 2));

    float sum0 = 0.f, sum1 = 0.f;
    #pragma unroll
    for (int j = 0; j < 26; j++) {
        #pragma unroll
        for (int e = 0; e < 2; e++) {
            float p0 = __expf(c[j][e] - mx0);
            float p1 = __expf(c[j][2 + e] - mx1);
            c[j][e] = p0;
            c[j][2 + e] = p1;
            sum0 += p0;
            sum1 += p1;
        }
    }
    sum0 += __shfl_xor_sync(0xffffffffu, sum0, 1);
    sum0 += __shfl_xor_sync(0xffffffffu, sum0, 2);
    sum1 += __shfl_xor_sync(0xffffffffu, sum1, 1);
    sum1 += __shfl_xor_sync(0xffffffffu, sum1, 2);
    float inv0 = 1.0f / sum0;
    float inv1 = 1.0f / sum1;

    // ---- PV ----
    float o[8][4];
    #pragma unroll
    for (int j = 0; j < 8; j++) {
        o[j][0] = 0.f; o[j][1] = 0.f; o[j][2] = 0.f; o[j][3] = 0.f;
    }
    #pragma unroll
    for (int j = 0; j < 13; j++) {
        uint32_t a[4];
        __half2 h0 = __floats2half2_rn(c[2 * j][0] * inv0, c[2 * j][1] * inv0);
        __half2 h1 = __floats2half2_rn(c[2 * j][2] * inv1, c[2 * j][3] * inv1);
        __half2 h2 = __floats2half2_rn(c[2 * j + 1][0] * inv0, c[2 * j + 1][1] * inv0);
        __half2 h3 = __floats2half2_rn(c[2 * j + 1][2] * inv1, c[2 * j + 1][3] * inv1);
        a[0] = *(uint32_t*)&h0;
        a[1] = *(uint32_t*)&h1;
        a[2] = *(uint32_t*)&h2;
        a[3] = *(uint32_t*)&h3;
        int brow = j * 16 + ((lane >> 3) & 1) * 8 + (lane & 7);
        #pragma unroll
        for (int nj = 0; nj < 4; nj++) {
            uint32_t b[4];
            int bcol = nj * 16 + (lane >> 4) * 8;
            ldsm_x4_t(v_base + (uint32_t)((brow * AT_STR + bcol) * 2), b);
            mma_f16(o[2 * nj],     a, b);
            mma_f16(o[2 * nj + 1], a, b + 2);
        }
    }

    // ---- write with residual add ----
    int rloc = lane >> 2;
    #pragma unroll
    for (int half = 0; half < 2; half++) {
        int srow = s0 + rloc + half * 8;
        if (srow >= SS) continue;
        float* xr = x + ((size_t)(n * SS + srow)) * DD + h * DH;
        #pragma unroll
        for (int nj = 0; nj < 8; nj++) {
            int col = nj * 8 + (lane & 3) * 2;
            xr[col]     += o[nj][half * 2];
            xr[col + 1] += o[nj][half * 2 + 1];
        }
    }
}

// ---------------- split-K classification head: grid (16 n-tiles, 4 k-chunks) -------
__global__ __launch_bounds__(256) void head_gemm(const float* __restrict__ x,
                                                 const float* __restrict__ Wout,
                                                 float* __restrict__ part) {
    __shared__ float As[16][34];
    __shared__ float Bs[16][68];
    int tid = threadIdx.x;
    int n0 = blockIdx.x * 64;
    int kz = blockIdx.y;
    int tx = tid & 15, ty = tid >> 4;

    float acc[2][4];
    acc[0][0] = 0.f; acc[0][1] = 0.f; acc[0][2] = 0.f; acc[0][3] = 0.f;
    acc[1][0] = 0.f; acc[1][1] = 0.f; acc[1][2] = 0.f; acc[1][3] = 0.f;

    for (int k0 = kz * 192; k0 < kz * 192 + 192; k0 += 16) {
        if (tid < 128) {
            int arow = tid >> 2;
            int akcol = (tid & 3) * 4;
            float4 a4 = *(const float4*)&x[(size_t)arow * (SS * DD) + k0 + akcol];
            As[akcol + 0][arow] = a4.x;
            As[akcol + 1][arow] = a4.y;
            As[akcol + 2][arow] = a4.z;
            As[akcol + 3][arow] = a4.w;
        }
        {
            int brow = tid >> 4;
            int bcol = (tid & 15) * 4;
            int gn = n0 + bcol;
            const float* Brow = &Wout[(size_t)(k0 + brow) * OUTC];
            float4 b4;
            b4.x = (gn + 0 < OUTC) ? Brow[gn + 0] : 0.f;
            b4.y = (gn + 1 < OUTC) ? Brow[gn + 1] : 0.f;
            b4.z = (gn + 2 < OUTC) ? Brow[gn + 2] : 0.f;
            b4.w = (gn + 3 < OUTC) ? Brow[gn + 3] : 0.f;
            *(float4*)&Bs[brow][bcol] = b4;
        }
        __syncthreads();

        #pragma unroll
        for (int kk = 0; kk < 16; kk++) {
            float a0 = As[kk][ty * 2];
            float a1 = As[kk][ty * 2 + 1];
            float4 b4 = *(float4*)&Bs[kk][tx * 4];
            acc[0][0] += a0 * b4.x; acc[0][1] += a0 * b4.y;
            acc[0][2] += a0 * b4.z; acc[0][3] += a0 * b4.w;
            acc[1][0] += a1 * b4.x; acc[1][1] += a1 * b4.y;
            acc[1][2] += a1 * b4.z; acc[1][3] += a1 * b4.w;
        }
        __syncthreads();
    }

    float* pbase = part + (size_t)kz * NN * OUTC;
    #pragma unroll
    for (int i = 0; i < 2; i++) {
        int r = ty * 2 + i;
        #pragma unroll
        for (int j = 0; j < 4; j++) {
            int cidx = n0 + tx * 4 + j;
            if (cidx < OUTC) pbase[(size_t)r * OUTC + cidx] = acc[i][j];
        }
    }
}

// ---------------- final softmax (sums 4 K-partials + bias) ----------------
__global__ __launch_bounds__(256) void softmax_out(const float* __restrict__ part,
                                                   const float* __restrict__ bout,
                                                   float* __restrict__ out) {
    __shared__ float sl[OUTC];
    __shared__ float sh[8];
    int n = blockIdx.x;
    int tid = threadIdx.x;
    int lane = tid & 31, wp = tid >> 5;

    for (int cidx = tid; cidx < OUTC; cidx += 256) {
        size_t o = (size_t)n * OUTC + cidx;
        sl[cidx] = bout[cidx] + part[o] + part[NN * OUTC + o] +
                   part[2 * NN * OUTC + o] + part[3 * NN * OUTC + o];
    }
    __syncthreads();

    float mx = -1e30f;
    for (int cidx = tid; cidx < OUTC; cidx += 256) mx = fmaxf(mx, sl[cidx]);
    #pragma unroll
    for (int o = 16; o; o >>= 1) mx = fmaxf(mx, __shfl_xor_sync(0xffffffffu, mx, o));
    if (lane == 0) sh[wp] = mx;
    __syncthreads();
    float gmx = sh[0];
    #pragma unroll
    for (int i = 1; i < 8; i++) gmx = fmaxf(gmx, sh[i]);
    __syncthreads();

    float sum = 0.f;
    for (int cidx = tid; cidx < OUTC; cidx += 256) sum += __expf(sl[cidx] - gmx);
    #pragma unroll
    for (int o = 16; o; o >>= 1) sum += __shfl_xor_sync(0xffffffffu, sum, o);
    if (lane == 0) sh[wp] = sum;
    __syncthreads();
    float tot = 0.f;
    #pragma unroll
    for (int i = 0; i < 8; i++) tot += sh[i];
    float inv = 1.0f / tot;

    for (int cidx = tid; cidx < OUTC; cidx += 256)
        out[(size_t)n * OUTC + cidx] = __expf(sl[cidx] - gmx) * inv;
}

// ---------------- launch ----------------
extern "C" void kernel_launch(void* const* d_in, const int* in_sizes, int n_in,
                              void* d_out, int out_size) {
    const float* images = (const float*)d_in[0];
    const float* Wm     = (const float*)d_in[1];
    const float* bm     = (const float*)d_in[2];
    const float* cls    = (const float*)d_in[3];
    const float* pos    = (const float*)d_in[4];
    const float* ln1w   = (const float*)d_in[5];
    const float* ln1b   = (const float*)d_in[6];
    const float* Wq     = (const float*)d_in[7];
    const float* bq     = (const float*)d_in[8];
    const float* Wk     = (const float*)d_in[9];
    const float* bk     = (const float*)d_in[10];
    const float* Wv     = (const float*)d_in[11];
    const float* bv     = (const float*)d_in[12];
    const float* ln2w   = (const float*)d_in[13];
    const float* ln2b   = (const float*)d_in[14];
    const float* W1     = (const float*)d_in[15];
    const float* b1     = (const float*)d_in[16];
    const float* W2     = (const float*)d_in[17];
    const float* b2     = (const float*)d_in[18];
    const float* Wout   = (const float*)d_in[19];
    const float* bout   = (const float*)d_in[20];
    float* out = (float*)d_out;

    float *p_x, *p_h, *p_lpart;
    cudaGetSymbolAddress((void**)&p_x, g_x);
    cudaGetSymbolAddress((void**)&p_h, g_h);
    cudaGetSymbolAddress((void**)&p_lpart, g_lpart);

    __half *p_patch, *p_hh, *p_u, *p_Wm, *p_W1, *p_W2;
    cudaGetSymbolAddress((void**)&p_patch, g_patch_f16);
    cudaGetSymbolAddress((void**)&p_hh, g_h_f16);
    cudaGetSymbolAddress((void**)&p_u, g_u_f16);
    cudaGetSymbolAddress((void**)&p_Wm, g_Wm_f16);
    cudaGetSymbolAddress((void**)&p_W1, g_W1_f16);
    cudaGetSymbolAddress((void**)&p_W2, g_W2_f16);

    cudaFuncSetAttribute(qkv_attn_fused, cudaFuncAttributeMaxDynamicSharedMemorySize, FUSED_SMEM_BYTES);
    cudaFuncSetAttribute(gemm_f16, cudaFuncAttributeMaxDynamicSharedMemorySize, GEMM_SMEM_BYTES);

    // ---- one-time weight conversions ----
    conv_f16<<<(DD * DD / 4 + 255) / 256, 256>>>(Wm, p_Wm, DD * DD);
    conv_f16<<<(LL * DD * FF / 4 + 255) / 256, 256>>>(W1, p_W1, LL * DD * FF);
    conv_f16<<<(LL * FF * DD / 4 + 255) / 256, 256>>>(W2, p_W2, LL * FF * DD);

    // ---- patch extraction + embed GEMM ----
    extract_patches<<<(PROWS * DD + 255) / 256, 256>>>(images, p_patch);
    gemm_f16<<<dim3(DD / 128, (PROWS + 127) / 128), 256, GEMM_SMEM_BYTES>>>(
        p_patch, DD, p_Wm, DD,
        p_h, nullptr, DD, bm, PROWS, DD, DD, FLAG_BIAS);
    assemble<<<(ROWS * DD + 255) / 256, 256>>>(p_h, cls, pos, p_x);

    for (int l = 0; l < LL; l++) {
        ln_warp<<<ROWS / 8, 256>>>(p_x, ln1w + l * DD, ln1b + l * DD, p_hh);

        qkv_attn_fused<<<NN * HH, FW_THREADS, FUSED_SMEM_BYTES>>>(
            p_hh,
            Wq + (size_t)l * HH * DH * DH, Wk + (size_t)l * HH * DH * DH, Wv + (size_t)l * HH * DH * DH,
            bq + (size_t)l * DD, bk + (size_t)l * DD, bv + (size_t)l * DD,
            p_x);

        ln_warp<<<ROWS / 8, 256>>>(p_x, ln2w + l * DD, ln2b + l * DD, p_hh);

        gemm_f16<<<dim3(FF / 128, (ROWS + 127) / 128), 256, GEMM_SMEM_BYTES>>>(
            p_hh, DD,
            p_W1 + (size_t)l * DD * FF, FF,
            nullptr, p_u, FF, b1 + (size_t)l * FF,
            ROWS, FF, DD, FLAG_BIAS | FLAG_GELU | FLAG_HALF_OUT);

        gemm_f16<<<dim3(DD / 128, (ROWS + 127) / 128), 256, GEMM_SMEM_BYTES>>>(
            p_u, FF,
            p_W2 + (size_t)l * FF * DD, DD,
            p_x, nullptr, DD, b2 + (size_t)l * DD,
            ROWS, DD, FF, FLAG_BIAS | FLAG_RES);
    }

    // classification head: split-K partials (deterministic), bias+reduce in softmax
    head_gemm<<<dim3(16, 4), 256>>>(p_x, Wout, p_lpart);
    softmax_out<<<NN, 256>>>(p_lpart, bout, out);
}